// round 12
// baseline (speedup 1.0000x reference)
#include <cuda_runtime.h>
#include <cuda_bf16.h>
#include <cstdint>
#include <cstddef>

#define HH 600
#define WW 600
#define HWX (HH*WW)
#define C 64
#define E 256
#define NL 7
#define CROPV 50
#define NOUT 500
#define NTRI ((NOUT*(NOUT+1))/2)   // 125250
#define MAXBIN 100

__device__ __forceinline__ uint32_t smem_to_u32(const void* p) {
    uint32_t a;
    asm("{ .reg .u64 t; cvta.to.shared.u64 t, %1; cvt.u32.u64 %0, t; }" : "=r"(a) : "l"(p));
    return a;
}
__device__ __forceinline__ float bf2f(uint32_t u) {
    return __bfloat162float(__ushort_as_bfloat16((unsigned short)u));
}
__device__ __forceinline__ unsigned short f2bfu(float v) {
    return __bfloat16_as_ushort(__float2bfloat16_rn(v));
}

#define LDSM_X4(r0, r1, r2, r3, a) \
    asm volatile("ldmatrix.sync.aligned.m8n8.x4.shared.b16 {%0,%1,%2,%3}, [%4];" \
        : "=r"(r0), "=r"(r1), "=r"(r2), "=r"(r3) : "r"(a))
#define LDSM_X4_T(r0, r1, r2, r3, a) \
    asm volatile("ldmatrix.sync.aligned.m8n8.x4.trans.shared.b16 {%0,%1,%2,%3}, [%4];" \
        : "=r"(r0), "=r"(r1), "=r"(r2), "=r"(r3) : "r"(a))

__device__ __forceinline__ void mma16816(float* d, const uint32_t* a, uint32_t b0, uint32_t b1) {
    asm volatile("mma.sync.aligned.m16n8k16.row.col.f32.bf16.bf16.f32 "
        "{%0,%1,%2,%3}, {%4,%5,%6,%7}, {%8,%9}, {%0,%1,%2,%3};"
        : "+f"(d[0]), "+f"(d[1]), "+f"(d[2]), "+f"(d[3])
        : "r"(a[0]), "r"(a[1]), "r"(a[2]), "r"(a[3]), "r"(b0), "r"(b1));
}

__device__ __forceinline__ void cp16(uint32_t dst, const void* src, bool ok) {
    asm volatile("cp.async.cg.shared.global [%0], [%1], 16, %2;"
        :: "r"(dst), "l"(src), "r"(ok ? 16 : 0) : "memory");
}
#define CP_COMMIT() asm volatile("cp.async.commit_group;" ::: "memory")
#define CP_WAIT0()  asm volatile("cp.async.wait_group 0;" ::: "memory")

// ---------------- device buffers ----------------
__device__ __nv_bfloat16 g_Ahi[(size_t)HWX * C];
__device__ __nv_bfloat16 g_Alo[(size_t)HWX * C];
__device__ __nv_bfloat16 g_Bhi[(size_t)HWX * C];
__device__ __nv_bfloat16 g_Blo[(size_t)HWX * C];
__device__ __nv_bfloat16 g_whi[NL * 49 * C * C];   // [l][tap][ci][co]
__device__ __nv_bfloat16 g_wlo[NL * 49 * C * C];
__device__ __nv_bfloat16 g_xhi[HH * E];
__device__ __nv_bfloat16 g_xlo[HH * E];
__device__ __nv_bfloat16 g_wxhi[(size_t)HH * E * C];
__device__ __nv_bfloat16 g_wxlo[(size_t)HH * E * C];
__device__ float g_bf[NL * C];
__device__ float g_u[HH * C];
__device__ float g_dproj[(MAXBIN + 1) * C];
__device__ float g_weff[C + 1];

// ---------------- prep kernels ----------------
__global__ void prep_u(const float* __restrict__ x, const float* __restrict__ w_in) {
    int i = blockIdx.x, c = threadIdx.x;
    const float* xr = x + i * E;
    const float* wr = w_in + c * E;
    float s = 0.f;
    #pragma unroll 8
    for (int e = 0; e < E; e++) s += wr[e] * xr[e];
    g_u[i * C + c] = s;
}

__global__ void prep_dproj(const float* __restrict__ dist, const float* __restrict__ w_in,
                           const float* __restrict__ b_in) {
    int p = blockIdx.x, c = threadIdx.x;
    const float* dr = dist + p * E;
    const float* wr = w_in + c * E;
    float s = b_in[c];
    #pragma unroll 8
    for (int e = 0; e < E; e++) s += wr[e] * dr[e];
    g_dproj[p * C + c] = s;
}

__global__ void prep_x(const float* __restrict__ x) {
    int i = blockIdx.x, e = threadIdx.x;
    float v = x[i * E + e];
    unsigned short h = f2bfu(v);
    g_xhi[i * E + e] = __ushort_as_bfloat16(h);
    g_xlo[i * E + e] = __float2bfloat16_rn(v - bf2f(h));
}

__global__ void prep_wx(const float* __restrict__ x, const float* __restrict__ w_in) {
    int i = blockIdx.x, e = threadIdx.x;
    float xie = x[i * E + e];
    size_t base = ((size_t)i * E + e) * C;
    #pragma unroll
    for (int c0 = 0; c0 < C; c0 += 2) {
        float v0 = w_in[c0 * E + e] * xie;
        float v1 = w_in[(c0 + 1) * E + e] * xie;
        unsigned short h0 = f2bfu(v0), h1 = f2bfu(v1);
        unsigned short l0 = f2bfu(v0 - bf2f(h0)), l1 = f2bfu(v1 - bf2f(h1));
        *(uint32_t*)(g_wxhi + base + c0) = (uint32_t)h0 | ((uint32_t)h1 << 16);
        *(uint32_t*)(g_wxlo + base + c0) = (uint32_t)l0 | ((uint32_t)l1 << 16);
    }
}

__global__ void prep_fold(const float* __restrict__ w_dil, const float* __restrict__ gamma,
                          const float* __restrict__ var) {
    int blk = blockIdx.x;
    int l = blk / 49, tap = blk % 49;
    int tid = threadIdx.x;
    __nv_bfloat16* dh = g_whi + blk * 4096;
    __nv_bfloat16* dl = g_wlo + blk * 4096;
    const float* wsrc = w_dil + l * C * C * 49;
    #pragma unroll
    for (int k = 0; k < 16; k++) {
        int idx = tid * 16 + k;           // ci*64 + co
        int ci = idx >> 6, co = idx & 63;
        float s = gamma[l * C + co] * rsqrtf(var[l * C + co] + 1e-5f);
        float v = wsrc[(co * C + ci) * 49 + tap] * s;
        unsigned short h = f2bfu(v);
        dh[idx] = __ushort_as_bfloat16(h);
        dl[idx] = __float2bfloat16_rn(v - bf2f(h));
    }
}

__global__ void prep_bias(const float* __restrict__ b_dil, const float* __restrict__ gamma,
                          const float* __restrict__ beta, const float* __restrict__ mean,
                          const float* __restrict__ var) {
    int l = blockIdx.x, c = threadIdx.x;
    float s = gamma[l * C + c] * rsqrtf(var[l * C + c] + 1e-5f);
    g_bf[l * C + c] = (b_dil[l * C + c] - mean[l * C + c]) * s + beta[l * C + c];
}

__global__ void prep_weff(const float* __restrict__ w_out, const float* __restrict__ b_out,
                          const float* __restrict__ w_head, const float* __restrict__ b_head) {
    int ci = threadIdx.x;
    float s = 0.f;
    for (int co = 0; co < C; co++) s += w_head[co] * w_out[co * C + ci];
    g_weff[ci] = s;
    if (ci == 0) {
        float b = b_head[0];
        for (int co = 0; co < C; co++) b += w_head[co] * b_out[co];
        g_weff[C] = b;
    }
}

// ---------------- pair via mma.sync ----------------
#define OFF_PAH(b) ((b) * 49152)
#define OFF_PAL(b) ((b) * 49152 + 16384)
#define OFF_PBH(b) ((b) * 49152 + 32768)
#define OFF_PBL(b) ((b) * 49152 + 40960)
#define SMEM_PAIR 98304

__global__ __launch_bounds__(256, 2) void pair_mma() {
    extern __shared__ char smem[];
    const uint32_t sb = smem_to_u32(smem);
    const int tid = threadIdx.x;
    const int wid = tid >> 5, lane = tid & 31;
    const int i = blockIdx.y;
    const int j0 = blockIdx.x * 128;

    int aRow[4], aCc[4]; uint32_t aOff[4];
    #pragma unroll
    for (int k = 0; k < 4; k++) {
        int chunk = tid + k * 256;
        aRow[k] = chunk >> 3;
        aCc[k] = chunk & 7;
        aOff[k] = (uint32_t)(aRow[k] * 128 + ((aCc[k] ^ (aRow[k] & 7)) << 4));
    }
    int bRow[2], bCc[2]; uint32_t bOff[2];
    #pragma unroll
    for (int k = 0; k < 2; k++) {
        int chunk = tid + k * 256;
        bRow[k] = chunk >> 3;
        bCc[k] = chunk & 7;
        bOff[k] = (uint32_t)(bRow[k] * 128 + ((bCc[k] ^ (bRow[k] & 7)) << 4));
    }

    const int row0 = wid * 16;
    const int quad = lane >> 3;
    const int rA = row0 + (lane & 7) + ((quad & 1) << 3);
    const int aChunkAdd = quad >> 1;
    const int rBbase = (lane & 7) + (((lane >> 3) & 1) << 3);
    const int bChunkAdd = lane >> 4;

    float acc[8][4] = {};

    {
        #pragma unroll
        for (int k = 0; k < 4; k++) {
            int j = j0 + aRow[k];
            bool ok = j < WW;
            size_t g = ok ? ((size_t)j * E + aCc[k] * 8) : 0;
            cp16(sb + OFF_PAH(0) + aOff[k], g_xhi + g, ok);
            cp16(sb + OFF_PAL(0) + aOff[k], g_xlo + g, ok);
        }
        size_t wb = ((size_t)i * E) * C;
        #pragma unroll
        for (int k = 0; k < 2; k++) {
            size_t g = wb + (size_t)bRow[k] * C + bCc[k] * 8;
            cp16(sb + OFF_PBH(0) + bOff[k], g_wxhi + g, true);
            cp16(sb + OFF_PBL(0) + bOff[k], g_wxlo + g, true);
        }
        CP_COMMIT();
        CP_WAIT0();
        __syncthreads();
    }

    #pragma unroll 1
    for (int ch = 0; ch < 4; ch++) {
        int buf = ch & 1;
        if (ch < 3) {
            int e0 = (ch + 1) * 64;
            int nb = buf ^ 1;
            #pragma unroll
            for (int k = 0; k < 4; k++) {
                int j = j0 + aRow[k];
                bool ok = j < WW;
                size_t g = ok ? ((size_t)j * E + e0 + aCc[k] * 8) : 0;
                cp16(sb + OFF_PAH(nb) + aOff[k], g_xhi + g, ok);
                cp16(sb + OFF_PAL(nb) + aOff[k], g_xlo + g, ok);
            }
            size_t wb = ((size_t)i * E + e0) * C;
            #pragma unroll
            for (int k = 0; k < 2; k++) {
                size_t g = wb + (size_t)bRow[k] * C + bCc[k] * 8;
                cp16(sb + OFF_PBH(nb) + bOff[k], g_wxhi + g, true);
                cp16(sb + OFF_PBL(nb) + bOff[k], g_wxlo + g, true);
            }
            CP_COMMIT();
        }

        const uint32_t pah = sb + OFF_PAH(buf);
        const uint32_t pal = sb + OFF_PAL(buf);
        const uint32_t pbh = sb + OFF_PBH(buf);
        const uint32_t pbl = sb + OFF_PBL(buf);
        #pragma unroll
        for (int ks = 0; ks < 4; ks++) {
            uint32_t ah[4], al[4];
            {
                int chunk = 2 * ks + aChunkAdd;
                uint32_t ao = (uint32_t)(rA * 128 + ((chunk ^ (rA & 7)) << 4));
                LDSM_X4(ah[0], ah[1], ah[2], ah[3], pah + ao);
                LDSM_X4(al[0], al[1], al[2], al[3], pal + ao);
            }
            int rB = rBbase + 16 * ks;
            #pragma unroll
            for (int p = 0; p < 4; p++) {
                int chunkB = 2 * p + bChunkAdd;
                uint32_t bo = (uint32_t)(rB * 128 + ((chunkB ^ (rB & 7)) << 4));
                uint32_t b0, b1, b2, b3;
                LDSM_X4_T(b0, b1, b2, b3, pbh + bo);
                mma16816(acc[2 * p],     ah, b0, b1);
                mma16816(acc[2 * p + 1], ah, b2, b3);
                mma16816(acc[2 * p],     al, b0, b1);
                mma16816(acc[2 * p + 1], al, b2, b3);
                LDSM_X4_T(b0, b1, b2, b3, pbl + bo);
                mma16816(acc[2 * p],     ah, b0, b1);
                mma16816(acc[2 * p + 1], ah, b2, b3);
            }
        }
        if (ch < 3) {
            CP_WAIT0();
            __syncthreads();
        }
    }

    int rtop = row0 + (lane >> 2);
    int cpair = (lane & 3) * 2;
    #pragma unroll
    for (int half = 0; half < 2; half++) {
        int j = j0 + rtop + half * 8;
        if (j < WW) {
            int pos = (i > j) ? (i - j) : (j - i);
            if (pos > MAXBIN) pos = MAXBIN;
            size_t prow = ((size_t)i * WW + j) * C;
            #pragma unroll
            for (int nt = 0; nt < 8; nt++) {
                int col = nt * 8 + cpair;
                float v0 = acc[nt][half * 2]     + 0.5f * (g_u[i * C + col]     + g_u[j * C + col])     + g_dproj[pos * C + col];
                float v1 = acc[nt][half * 2 + 1] + 0.5f * (g_u[i * C + col + 1] + g_u[j * C + col + 1]) + g_dproj[pos * C + col + 1];
                unsigned short h0 = f2bfu(v0), h1 = f2bfu(v1);
                unsigned short l0 = f2bfu(v0 - bf2f(h0)), l1 = f2bfu(v1 - bf2f(h1));
                *(uint32_t*)(g_Ahi + prow + col) = (uint32_t)h0 | ((uint32_t)h1 << 16);
                *(uint32_t*)(g_Alo + prow + col) = (uint32_t)l0 | ((uint32_t)l1 << 16);
            }
        }
    }
}

// ---------------- dilated conv (small dil): y-pair strip, DB W ----------------
#define OFF_BIAS 0
#define OFF_WB(b)  (256 + (b) * 16384)
#define OFF_S2     (256 + 32768)

template<int DIL>
__global__ __launch_bounds__(256, 2) void conv_strip2(int l) {
    constexpr int NR = ((128 + 6 * DIL) + 31) & ~31;

    extern __shared__ char smem[];
    const uint32_t sb = smem_to_u32(smem);
    const int tid = threadIdx.x;
    const int wid = tid >> 5, lane = tid & 31;
    const int y0 = blockIdx.y * 2;
    const int x0 = blockIdx.x * 128;

    const __nv_bfloat16* __restrict__ shi = (l & 1) ? g_Bhi : g_Ahi;
    const __nv_bfloat16* __restrict__ slo = (l & 1) ? g_Blo : g_Alo;
    __nv_bfloat16* __restrict__ dhi = (l & 1) ? g_Ahi : g_Bhi;
    __nv_bfloat16* __restrict__ dlo = (l & 1) ? g_Alo : g_Blo;
    const __nv_bfloat16* __restrict__ wh = g_whi + l * 49 * 4096;
    const __nv_bfloat16* __restrict__ wl = g_wlo + l * 49 * 4096;

    if (tid < C) ((float*)(smem + OFF_BIAS))[tid] = g_bf[l * C + tid];

    int wCi[2]; uint32_t wSo[2], wGo[2];
    #pragma unroll
    for (int k = 0; k < 2; k++) {
        int chunk = tid + k * 256;
        wCi[k] = chunk >> 3;
        int cc = chunk & 7;
        wGo[k] = (uint32_t)(wCi[k] * 64 + cc * 8);
        wSo[k] = (uint32_t)(wCi[k] * 128 + ((cc ^ (wCi[k] & 7)) << 4));
    }

    const int row0 = wid * 16;
    const int quad = lane >> 3;
    const int rA = row0 + (lane & 7) + ((quad & 1) << 3);
    const int aChunkAdd = quad >> 1;
    const int rBbase = (lane & 7) + (((lane >> 3) & 1) << 3);
    const int bChunkAdd = lane >> 4;

    float acc[2][8][4] = {};

    #pragma unroll 1
    for (int ky = 0; ky < 7; ky++) {
        #pragma unroll
        for (int s = 0; s < 2; s++) {
            int yy = y0 + s + (ky - 3) * DIL;
            bool yok = (yy >= 0) && (yy < HH);
            size_t rowbase = (size_t)yy * WW;
            uint32_t sbase = sb + OFF_S2 + s * (NR * 256);
            #pragma unroll 1
            for (int chunk = tid; chunk < NR * 8; chunk += 256) {
                int r = chunk >> 3;
                int cc = chunk & 7;
                int xg = x0 - 3 * DIL + r;
                bool ok = yok && (xg >= 0) && (xg < WW);
                size_t g = ok ? ((rowbase + xg) * C + cc * 8) : 0;
                uint32_t so = (uint32_t)(r * 128 + ((cc ^ (r & 7)) << 4));
                cp16(sbase + so, shi + g, ok);
                cp16(sbase + NR * 128 + so, slo + g, ok);
            }
        }
        {
            const __nv_bfloat16* wph = wh + (ky * 7) * 4096;
            const __nv_bfloat16* wpl = wl + (ky * 7) * 4096;
            #pragma unroll
            for (int k = 0; k < 2; k++) {
                cp16(sb + OFF_WB(0) + wSo[k],        wph + wGo[k], true);
                cp16(sb + OFF_WB(0) + 8192 + wSo[k], wpl + wGo[k], true);
            }
        }
        CP_COMMIT();
        CP_WAIT0();
        __syncthreads();

        #pragma unroll 1
        for (int kx = 0; kx < 7; kx++) {
            int buf = kx & 1;
            if (kx < 6) {
                const __nv_bfloat16* wph = wh + (ky * 7 + kx + 1) * 4096;
                const __nv_bfloat16* wpl = wl + (ky * 7 + kx + 1) * 4096;
                int nb = (kx + 1) & 1;
                #pragma unroll
                for (int k = 0; k < 2; k++) {
                    cp16(sb + OFF_WB(nb) + wSo[k],        wph + wGo[k], true);
                    cp16(sb + OFF_WB(nb) + 8192 + wSo[k], wpl + wGo[k], true);
                }
                CP_COMMIT();
            }
            const uint32_t wbh = sb + OFF_WB(buf);
            const uint32_t wbl = wbh + 8192;
            const int rowL = kx * DIL + rA;
            const uint32_t aoBase = (uint32_t)(rowL * 128);
            const int rpar = rowL & 7;
            const uint32_t s0h = sb + OFF_S2;
            const uint32_t s0l = s0h + NR * 128;
            const uint32_t s1h = s0h + NR * 256;
            const uint32_t s1l = s1h + NR * 128;

            #pragma unroll
            for (int ks = 0; ks < 4; ks++) {
                uint32_t ah0[4], al0[4], ah1[4], al1[4];
                {
                    int chunk = 2 * ks + aChunkAdd;
                    uint32_t ao = aoBase + ((uint32_t)(chunk ^ rpar) << 4);
                    LDSM_X4(ah0[0], ah0[1], ah0[2], ah0[3], s0h + ao);
                    LDSM_X4(al0[0], al0[1], al0[2], al0[3], s0l + ao);
                    LDSM_X4(ah1[0], ah1[1], ah1[2], ah1[3], s1h + ao);
                    LDSM_X4(al1[0], al1[1], al1[2], al1[3], s1l + ao);
                }
                int rB = rBbase + 16 * ks;
                #pragma unroll
                for (int p = 0; p < 4; p++) {
                    int chunkB = 2 * p + bChunkAdd;
                    uint32_t bo = (uint32_t)(rB * 128 + ((chunkB ^ (rB & 7)) << 4));
                    uint32_t b0, b1, b2, b3;
                    LDSM_X4_T(b0, b1, b2, b3, wbh + bo);
                    mma16816(acc[0][2 * p],     ah0, b0, b1);
                    mma16816(acc[0][2 * p + 1], ah0, b2, b3);
                    mma16816(acc[1][2 * p],     ah1, b0, b1);
                    mma16816(acc[1][2 * p + 1], ah1, b2, b3);
                    mma16816(acc[0][2 * p],     al0, b0, b1);
                    mma16816(acc[0][2 * p + 1], al0, b2, b3);
                    mma16816(acc[1][2 * p],     al1, b0, b1);
                    mma16816(acc[1][2 * p + 1], al1, b2, b3);
                    LDSM_X4_T(b0, b1, b2, b3, wbl + bo);
                    mma16816(acc[0][2 * p],     ah0, b0, b1);
                    mma16816(acc[0][2 * p + 1], ah0, b2, b3);
                    mma16816(acc[1][2 * p],     ah1, b0, b1);
                    mma16816(acc[1][2 * p + 1], ah1, b2, b3);
                }
            }
            if (kx < 6) {
                CP_WAIT0();
                __syncthreads();
            }
        }
        __syncthreads();
    }

    const float* sbias = (const float*)(smem + OFF_BIAS);
    int rtop = row0 + (lane >> 2);
    int cpair = (lane & 3) * 2;
    #pragma unroll
    for (int s = 0; s < 2; s++) {
        int y = y0 + s;
        #pragma unroll
        for (int half = 0; half < 2; half++) {
            int xg = x0 + rtop + half * 8;
            if (xg < WW) {
                size_t prow = ((size_t)y * WW + xg) * C;
                #pragma unroll
                for (int nt = 0; nt < 8; nt++) {
                    int col = nt * 8 + cpair;
                    size_t p = prow + col;
                    uint32_t rh = *(const uint32_t*)(shi + p);
                    uint32_t rl = *(const uint32_t*)(slo + p);
                    float v0 = acc[s][nt][half * 2]     + sbias[col]     + bf2f(rh & 0xffffu) + bf2f(rl & 0xffffu);
                    float v1 = acc[s][nt][half * 2 + 1] + sbias[col + 1] + bf2f(rh >> 16)     + bf2f(rl >> 16);
                    v0 = fmaxf(v0, 0.f); v1 = fmaxf(v1, 0.f);
                    unsigned short h0 = f2bfu(v0), h1 = f2bfu(v1);
                    unsigned short l0 = f2bfu(v0 - bf2f(h0)), l1 = f2bfu(v1 - bf2f(h1));
                    *(uint32_t*)(dhi + p) = (uint32_t)h0 | ((uint32_t)h1 << 16);
                    *(uint32_t*)(dlo + p) = (uint32_t)l0 | ((uint32_t)l1 << 16);
                }
            }
        }
    }
}

// ---------------- dilated conv (mid/large dil): single-row strip, 32x32 warp tiles ----------------
#define OFF_STRIP  (256 + 32768)

template<int DIL>
__global__ __launch_bounds__(256, 2) void conv_strip_sq(int l) {
    constexpr int NR = ((128 + 6 * DIL) + 31) & ~31;
    constexpr int OFF_SH = OFF_STRIP;
    constexpr int OFF_SL = OFF_STRIP + NR * 128;

    extern __shared__ char smem[];
    const uint32_t sb = smem_to_u32(smem);
    const int tid = threadIdx.x;
    const int wid = tid >> 5, lane = tid & 31;
    const int y = blockIdx.y;
    const int x0 = blockIdx.x * 128;

    const __nv_bfloat16* __restrict__ shi = (l & 1) ? g_Bhi : g_Ahi;
    const __nv_bfloat16* __restrict__ slo = (l & 1) ? g_Blo : g_Alo;
    __nv_bfloat16* __restrict__ dhi = (l & 1) ? g_Ahi : g_Bhi;
    __nv_bfloat16* __restrict__ dlo = (l & 1) ? g_Alo : g_Blo;
    const __nv_bfloat16* __restrict__ wh = g_whi + l * 49 * 4096;
    const __nv_bfloat16* __restrict__ wl = g_wlo + l * 49 * 4096;

    if (tid < C) ((float*)(smem + OFF_BIAS))[tid] = g_bf[l * C + tid];

    int wCi[2]; uint32_t wSo[2], wGo[2];
    #pragma unroll
    for (int k = 0; k < 2; k++) {
        int chunk = tid + k * 256;
        wCi[k] = chunk >> 3;
        int cc = chunk & 7;
        wGo[k] = (uint32_t)(wCi[k] * 64 + cc * 8);
        wSo[k] = (uint32_t)(wCi[k] * 128 + ((cc ^ (wCi[k] & 7)) << 4));
    }

    // 32x32 warp tiles: 4 row-blocks x 2 col-blocks
    const int wrow = wid & 3, wcol = wid >> 2;
    const int quad = lane >> 3;
    const int rAoff = (lane & 7) + ((quad & 1) << 3);
    const int aChunkAdd = quad >> 1;
    const int rBbase = (lane & 7) + (((lane >> 3) & 1) << 3);
    const int bChunkAdd = lane >> 4;

    float acc[2][4][4] = {};

    #pragma unroll 1
    for (int ky = 0; ky < 7; ky++) {
        int yy = y + (ky - 3) * DIL;
        bool yok = (yy >= 0) && (yy < HH);
        size_t rowbase = (size_t)yy * WW;

        #pragma unroll 1
        for (int chunk = tid; chunk < NR * 8; chunk += 256) {
            int r = chunk >> 3;
            int cc = chunk & 7;
            int xg = x0 - 3 * DIL + r;
            bool ok = yok && (xg >= 0) && (xg < WW);
            size_t g = ok ? ((rowbase + xg) * C + cc * 8) : 0;
            uint32_t so = (uint32_t)(r * 128 + ((cc ^ (r & 7)) << 4));
            cp16(sb + OFF_SH + so, shi + g, ok);
            cp16(sb + OFF_SL + so, slo + g, ok);
        }
        {
            const __nv_bfloat16* wph = wh + (ky * 7) * 4096;
            const __nv_bfloat16* wpl = wl + (ky * 7) * 4096;
            #pragma unroll
            for (int k = 0; k < 2; k++) {
                cp16(sb + OFF_WB(0) + wSo[k],        wph + wGo[k], true);
                cp16(sb + OFF_WB(0) + 8192 + wSo[k], wpl + wGo[k], true);
            }
        }
        CP_COMMIT();
        CP_WAIT0();
        __syncthreads();

        #pragma unroll 1
        for (int kx = 0; kx < 7; kx++) {
            int buf = kx & 1;
            if (kx < 6) {
                const __nv_bfloat16* wph = wh + (ky * 7 + kx + 1) * 4096;
                const __nv_bfloat16* wpl = wl + (ky * 7 + kx + 1) * 4096;
                int nb = (kx + 1) & 1;
                #pragma unroll
                for (int k = 0; k < 2; k++) {
                    cp16(sb + OFF_WB(nb) + wSo[k],        wph + wGo[k], true);
                    cp16(sb + OFF_WB(nb) + 8192 + wSo[k], wpl + wGo[k], true);
                }
                CP_COMMIT();
            }
            const uint32_t wbh = sb + OFF_WB(buf);
            const uint32_t wbl = wbh + 8192;
            const int rbase = kx * DIL + wrow * 32 + rAoff;

            #pragma unroll
            for (int ks = 0; ks < 4; ks++) {
                uint32_t ah[2][4], al[2][4];
                #pragma unroll
                for (int mf = 0; mf < 2; mf++) {
                    int rowL = rbase + mf * 16;
                    int chunk = 2 * ks + aChunkAdd;
                    uint32_t ao = (uint32_t)(rowL * 128 + ((chunk ^ (rowL & 7)) << 4));
                    LDSM_X4(ah[mf][0], ah[mf][1], ah[mf][2], ah[mf][3], sb + OFF_SH + ao);
                    LDSM_X4(al[mf][0], al[mf][1], al[mf][2], al[mf][3], sb + OFF_SL + ao);
                }
                int rB = rBbase + 16 * ks;
                #pragma unroll
                for (int p = 0; p < 2; p++) {
                    int chunkB = 2 * (wcol * 2 + p) + bChunkAdd;
                    uint32_t bo = (uint32_t)(rB * 128 + ((chunkB ^ (rB & 7)) << 4));
                    uint32_t b0, b1, b2, b3;
                    LDSM_X4_T(b0, b1, b2, b3, wbh + bo);
                    mma16816(acc[0][2 * p],     ah[0], b0, b1);
                    mma16816(acc[0][2 * p + 1], ah[0], b2, b3);
                    mma16816(acc[1][2 * p],     ah[1], b0, b1);
                    mma16816(acc[1][2 * p + 1], ah[1], b2, b3);
                    mma16816(acc[0][2 * p],     al[0], b0, b1);
                    mma16816(acc[0][2 * p + 1], al[0], b2, b3);
                    mma16816(acc[1][2 * p],     al[1], b0, b1);
                    mma16816(acc[1][2 * p + 1], al[1], b2, b3);
                    LDSM_X4_T(b0, b1, b2, b3, wbl + bo);
                    mma16816(acc[0][2 * p],     ah[0], b0, b1);
                    mma16816(acc[0][2 * p + 1], ah[0], b2, b3);
                    mma16816(acc[1][2 * p],     ah[1], b0, b1);
                    mma16816(acc[1][2 * p + 1], ah[1], b2, b3);
                }
            }
            if (kx < 6) {
                CP_WAIT0();
                __syncthreads();
            }
        }
        __syncthreads();
    }

    const float* sbias = (const float*)(smem + OFF_BIAS);
    int rtop = wrow * 32 + (lane >> 2);
    int cbase = wcol * 32 + (lane & 3) * 2;
    #pragma unroll
    for (int mf = 0; mf < 2; mf++) {
        #pragma unroll
        for (int half = 0; half < 2; half++) {
            int xg = x0 + rtop + mf * 16 + half * 8;
            if (xg < WW) {
                size_t prow = ((size_t)y * WW + xg) * C;
                #pragma unroll
                for (int nt = 0; nt < 4; nt++) {
                    int col = cbase + nt * 8;
                    size_t p = prow + col;
                    uint32_t rh = *(const uint32_t*)(shi + p);
                    uint32_t rl = *(const uint32_t*)(slo + p);
                    float v0 = acc[mf][nt][half * 2]     + sbias[col]     + bf2f(rh & 0xffffu) + bf2f(rl & 0xffffu);
                    float v1 = acc[mf][nt][half * 2 + 1] + sbias[col + 1] + bf2f(rh >> 16)     + bf2f(rl >> 16);
                    v0 = fmaxf(v0, 0.f); v1 = fmaxf(v1, 0.f);
                    unsigned short h0 = f2bfu(v0), h1 = f2bfu(v1);
                    unsigned short l0 = f2bfu(v0 - bf2f(h0)), l1 = f2bfu(v1 - bf2f(h1));
                    *(uint32_t*)(dhi + p) = (uint32_t)h0 | ((uint32_t)h1 << 16);
                    *(uint32_t*)(dlo + p) = (uint32_t)l0 | ((uint32_t)l1 << 16);
                }
            }
        }
    }
}

// ---------------- dilated conv (dil 64): per-tap DB A+W, 32x32 warp tiles ----------------
#define OT_BUF(b)  (256 + (b) * 49152)
#define SMEM_TAP   98560

template<int DIL>
__global__ __launch_bounds__(256, 2) void conv_tap_sq(int l) {
    extern __shared__ char smem[];
    const uint32_t sb = smem_to_u32(smem);
    const int tid = threadIdx.x;
    const int wid = tid >> 5, lane = tid & 31;
    const int y = blockIdx.y;
    const int x0 = blockIdx.x * 128;

    const __nv_bfloat16* __restrict__ shi = (l & 1) ? g_Bhi : g_Ahi;
    const __nv_bfloat16* __restrict__ slo = (l & 1) ? g_Blo : g_Alo;
    __nv_bfloat16* __restrict__ dhi = (l & 1) ? g_Ahi : g_Bhi;
    __nv_bfloat16* __restrict__ dlo = (l & 1) ? g_Alo : g_Blo;
    const __nv_bfloat16* __restrict__ wh = g_whi + l * 49 * 4096;
    const __nv_bfloat16* __restrict__ wl = g_wlo + l * 49 * 4096;

    if (tid < C) ((float*)(smem))[tid] = g_bf[l * C + tid];

    int aRow[4], aCc[4]; uint32_t aOff[4];
    #pragma unroll
    for (int k = 0; k < 4; k++) {
        int chunk = tid + k * 256;
        aRow[k] = chunk >> 3;
        aCc[k] = chunk & 7;
        aOff[k] = (uint32_t)(aRow[k] * 128 + ((aCc[k] ^ (aRow[k] & 7)) << 4));
    }
    int wCi[2]; uint32_t wSo[2], wGo[2];
    #pragma unroll
    for (int k = 0; k < 2; k++) {
        int chunk = tid + k * 256;
        wCi[k] = chunk >> 3;
        int cc = chunk & 7;
        wGo[k] = (uint32_t)(wCi[k] * 64 + cc * 8);
        wSo[k] = (uint32_t)(wCi[k] * 128 + ((cc ^ (wCi[k] & 7)) << 4));
    }

    const int wrow = wid & 3, wcol = wid >> 2;
    const int quad = lane >> 3;
    const int rAoff = (lane & 7) + ((quad & 1) << 3);
    const int aChunkAdd = quad >> 1;
    const int rBbase = (lane & 7) + (((lane >> 3) & 1) << 3);
    const int bChunkAdd = lane >> 4;
    const int rbase = wrow * 32 + rAoff;

    #define STAGE_TAP(TAP, BUF) do { \
        int _t = (TAP); \
        int _ky = _t / 7, _kx = _t - _ky * 7; \
        int _yy = y + (_ky - 3) * DIL; \
        bool _yok = (_yy >= 0) && (_yy < HH); \
        size_t _rb = (size_t)_yy * WW; \
        int _xs = x0 + (_kx - 3) * DIL; \
        uint32_t _ba = sb + OT_BUF(BUF); \
        _Pragma("unroll") \
        for (int _k = 0; _k < 4; _k++) { \
            int _xg = _xs + aRow[_k]; \
            bool _ok = _yok && (_xg >= 0) && (_xg < WW); \
            size_t _g = _ok ? ((_rb + _xg) * C + aCc[_k] * 8) : 0; \
            cp16(_ba + aOff[_k],         shi + _g, _ok); \
            cp16(_ba + 16384 + aOff[_k], slo + _g, _ok); \
        } \
        const __nv_bfloat16* _wph = wh + _t * 4096; \
        const __nv_bfloat16* _wpl = wl + _t * 4096; \
        _Pragma("unroll") \
        for (int _k = 0; _k < 2; _k++) { \
            cp16(_ba + 32768 + wSo[_k], _wph + wGo[_k], true); \
            cp16(_ba + 40960 + wSo[_k], _wpl + wGo[_k], true); \
        } \
    } while (0)

    float acc[2][4][4] = {};

    STAGE_TAP(0, 0);
    CP_COMMIT();
    CP_WAIT0();
    __syncthreads();

    #pragma unroll 1
    for (int tap = 0; tap < 49; ++tap) {
        int buf = tap & 1;
        if (tap < 48) {
            STAGE_TAP(tap + 1, buf ^ 1);
            CP_COMMIT();
        }
        const uint32_t pah = sb + OT_BUF(buf);
        const uint32_t pal = pah + 16384;
        const uint32_t wbh = pah + 32768;
        const uint32_t wbl = pah + 40960;

        #pragma unroll
        for (int ks = 0; ks < 4; ks++) {
            uint32_t ah[2][4], al[2][4];
            #pragma unroll
            for (int mf = 0; mf < 2; mf++) {
                int rowL = rbase + mf * 16;
                int chunk = 2 * ks + aChunkAdd;
                uint32_t ao = (uint32_t)(rowL * 128 + ((chunk ^ (rowL & 7)) << 4));
                LDSM_X4(ah[mf][0], ah[mf][1], ah[mf][2], ah[mf][3], pah + ao);
                LDSM_X4(al[mf][0], al[mf][1], al[mf][2], al[mf][3], pal + ao);
            }
            int rB = rBbase + 16 * ks;
            #pragma unroll
            for (int p = 0; p < 2; p++) {
                int chunkB = 2 * (wcol * 2 + p) + bChunkAdd;
                uint32_t bo = (uint32_t)(rB * 128 + ((chunkB ^ (rB & 7)) << 4));
                uint32_t b0, b1, b2, b3;
                LDSM_X4_T(b0, b1, b2, b3, wbh + bo);
                mma16816(acc[0][2 * p],     ah[0], b0, b1);
                mma16816(acc[0][2 * p + 1], ah[0], b2, b3);
                mma16816(acc[1][2 * p],     ah[1], b0, b1);
                mma16816(acc[1][2 * p + 1], ah[1], b2, b3);
                mma16816(acc[0][2 * p],     al[0], b0, b1);
                mma16816(acc[0][2 * p + 1], al[0], b2, b3);
                mma16816(acc[1][2 * p],     al[1], b0, b1);
                mma16816(acc[1][2 * p + 1], al[1], b2, b3);
                LDSM_X4_T(b0, b1, b2, b3, wbl + bo);
                mma16816(acc[0][2 * p],     ah[0], b0, b1);
                mma16816(acc[0][2 * p + 1], ah[0], b2, b3);
                mma16816(acc[1][2 * p],     ah[1], b0, b1);
                mma16816(acc[1][2 * p + 1], ah[1], b2, b3);
            }
        }
        if (tap < 48) {
            CP_WAIT0();
            __syncthreads();
        }
    }
    #undef STAGE_TAP

    const float* sbias = (const float*)(smem);
    int rtop = wrow * 32 + (lane >> 2);
    int cbase = wcol * 32 + (lane & 3) * 2;
    #pragma unroll
    for (int mf = 0; mf < 2; mf++) {
        #pragma unroll
        for (int half = 0; half < 2; half++) {
            int xg = x0 + rtop + mf * 16 + half * 8;
            if (xg < WW) {
                size_t prow = ((size_t)y * WW + xg) * C;
                #pragma unroll
                for (int nt = 0; nt < 4; nt++) {
                    int col = cbase + nt * 8;
                    size_t p = prow + col;
                    uint32_t rh = *(const uint32_t*)(shi + p);
                    uint32_t rl = *(const uint32_t*)(slo + p);
                    float v0 = acc[mf][nt][half * 2]     + sbias[col]     + bf2f(rh & 0xffffu) + bf2f(rl & 0xffffu);
                    float v1 = acc[mf][nt][half * 2 + 1] + sbias[col + 1] + bf2f(rh >> 16)     + bf2f(rl >> 16);
                    v0 = fmaxf(v0, 0.f); v1 = fmaxf(v1, 0.f);
                    unsigned short h0 = f2bfu(v0), h1 = f2bfu(v1);
                    unsigned short l0 = f2bfu(v0 - bf2f(h0)), l1 = f2bfu(v1 - bf2f(h1));
                    *(uint32_t*)(dhi + p) = (uint32_t)h0 | ((uint32_t)h1 << 16);
                    *(uint32_t*)(dlo + p) = (uint32_t)l0 | ((uint32_t)l1 << 16);
                }
            }
        }
    }
}

// ---------------- head ----------------
__device__ __forceinline__ int tri_offs(int r) { return r * NOUT - (r * (r - 1)) / 2; }

__global__ void head_k(float* __restrict__ out) {
    int k = blockIdx.x * blockDim.x + threadIdx.x;
    if (k >= NTRI) return;
    float disc = (2.f * NOUT + 1.f) * (2.f * NOUT + 1.f) - 8.f * (float)k;
    int r = (int)(((2.f * NOUT + 1.f) - sqrtf(disc)) * 0.5f);
    if (r < 0) r = 0;
    if (r > NOUT - 1) r = NOUT - 1;
    while (r > 0 && tri_offs(r) > k) r--;
    while (r < NOUT - 1 && tri_offs(r + 1) <= k) r++;
    int c = r + (k - tri_offs(r));
    int yy = CROPV + r, xx = CROPV + c;
    size_t p = ((size_t)yy * WW + xx) * C;

    float s = g_weff[C];
    const uint4* rh = (const uint4*)(g_Bhi + p);
    const uint4* rl = (const uint4*)(g_Blo + p);
    #pragma unroll
    for (int q = 0; q < 8; q++) {
        uint4 vh = rh[q], vl = rl[q];
        uint32_t vhw[4] = {vh.x, vh.y, vh.z, vh.w};
        uint32_t vlw[4] = {vl.x, vl.y, vl.z, vl.w};
        #pragma unroll
        for (int e = 0; e < 4; e++) {
            int ci = q * 8 + e * 2;
            float h0 = bf2f(vhw[e] & 0xffffu) + bf2f(vlw[e] & 0xffffu);
            float h1 = bf2f(vhw[e] >> 16) + bf2f(vlw[e] >> 16);
            s = fmaf(h0, __ldg(&g_weff[ci]), s);
            s = fmaf(h1, __ldg(&g_weff[ci + 1]), s);
        }
    }
    out[k] = s;
}

// ------------------------------------------------------------------
template<int DIL>
static void launch_conv2(int l) {
    constexpr int NR = ((128 + 6 * DIL) + 31) & ~31;
    constexpr int SMEM = 256 + 32768 + 2 * NR * 256;
    static bool done = false;
    if (!done) {
        cudaFuncSetAttribute(conv_strip2<DIL>, cudaFuncAttributeMaxDynamicSharedMemorySize, SMEM);
        done = true;
    }
    conv_strip2<DIL><<<dim3((WW + 127) / 128, HH / 2), 256, SMEM>>>(l);
}

template<int DIL>
static void launch_conv_sq(int l) {
    constexpr int NR = ((128 + 6 * DIL) + 31) & ~31;
    constexpr int SMEM = 256 + 32768 + NR * 256;
    static bool done = false;
    if (!done) {
        cudaFuncSetAttribute(conv_strip_sq<DIL>, cudaFuncAttributeMaxDynamicSharedMemorySize, SMEM);
        done = true;
    }
    conv_strip_sq<DIL><<<dim3((WW + 127) / 128, HH), 256, SMEM>>>(l);
}

template<int DIL>
static void launch_tap_sq(int l) {
    static bool done = false;
    if (!done) {
        cudaFuncSetAttribute(conv_tap_sq<DIL>, cudaFuncAttributeMaxDynamicSharedMemorySize, SMEM_TAP);
        done = true;
    }
    conv_tap_sq<DIL><<<dim3((WW + 127) / 128, HH), 256, SMEM_TAP>>>(l);
}

extern "C" void kernel_launch(void* const* d_in, const int* in_sizes, int n_in,
                              void* d_out, int out_size) {
    const float* x      = (const float*)d_in[0];
    const float* dist   = (const float*)d_in[1];
    const float* w_in   = (const float*)d_in[2];
    const float* b_in   = (const float*)d_in[3];
    const float* w_dil  = (const float*)d_in[4];
    const float* b_dil  = (const float*)d_in[5];
    const float* gamma  = (const float*)d_in[6];
    const float* beta   = (const float*)d_in[7];
    const float* mean   = (const float*)d_in[8];
    const float* var    = (const float*)d_in[9];
    const float* w_out  = (const float*)d_in[10];
    const float* b_out  = (const float*)d_in[11];
    const float* w_head = (const float*)d_in[12];
    const float* b_head = (const float*)d_in[13];
    float* out = (float*)d_out;

    cudaFuncSetAttribute(pair_mma, cudaFuncAttributeMaxDynamicSharedMemorySize, SMEM_PAIR);

    prep_u<<<HH, C>>>(x, w_in);
    prep_dproj<<<MAXBIN + 1, C>>>(dist, w_in, b_in);
    prep_x<<<HH, E>>>(x);
    prep_wx<<<HH, E>>>(x, w_in);
    prep_fold<<<NL * 49, 256>>>(w_dil, gamma, var);
    prep_bias<<<NL, C>>>(b_dil, gamma, beta, mean, var);
    prep_weff<<<1, C>>>(w_out, b_out, w_head, b_head);

    pair_mma<<<dim3((WW + 127) / 128, HH), 256, SMEM_PAIR>>>();

    launch_conv2<1>(0);
    launch_conv2<2>(1);
    launch_conv2<4>(2);
    launch_conv_sq<8>(3);
    launch_conv_sq<16>(4);
    launch_conv_sq<32>(5);
    launch_tap_sq<64>(6);

    head_k<<<(NTRI + 255) / 256, 256>>>(out);
}

// round 13
// speedup vs baseline: 1.0259x; 1.0259x over previous
#include <cuda_runtime.h>
#include <cuda_bf16.h>
#include <cstdint>
#include <cstddef>

#define HH 600
#define WW 600
#define HWX (HH*WW)
#define C 64
#define E 256
#define NL 7
#define CROPV 50
#define NOUT 500
#define NTRI ((NOUT*(NOUT+1))/2)   // 125250
#define MAXBIN 100

__device__ __forceinline__ uint32_t smem_to_u32(const void* p) {
    uint32_t a;
    asm("{ .reg .u64 t; cvta.to.shared.u64 t, %1; cvt.u32.u64 %0, t; }" : "=r"(a) : "l"(p));
    return a;
}
__device__ __forceinline__ float bf2f(uint32_t u) {
    return __bfloat162float(__ushort_as_bfloat16((unsigned short)u));
}
__device__ __forceinline__ unsigned short f2bfu(float v) {
    return __bfloat16_as_ushort(__float2bfloat16_rn(v));
}

#define LDSM_X4(r0, r1, r2, r3, a) \
    asm volatile("ldmatrix.sync.aligned.m8n8.x4.shared.b16 {%0,%1,%2,%3}, [%4];" \
        : "=r"(r0), "=r"(r1), "=r"(r2), "=r"(r3) : "r"(a))
#define LDSM_X4_T(r0, r1, r2, r3, a) \
    asm volatile("ldmatrix.sync.aligned.m8n8.x4.trans.shared.b16 {%0,%1,%2,%3}, [%4];" \
        : "=r"(r0), "=r"(r1), "=r"(r2), "=r"(r3) : "r"(a))

__device__ __forceinline__ void mma16816(float* d, const uint32_t* a, uint32_t b0, uint32_t b1) {
    asm volatile("mma.sync.aligned.m16n8k16.row.col.f32.bf16.bf16.f32 "
        "{%0,%1,%2,%3}, {%4,%5,%6,%7}, {%8,%9}, {%0,%1,%2,%3};"
        : "+f"(d[0]), "+f"(d[1]), "+f"(d[2]), "+f"(d[3])
        : "r"(a[0]), "r"(a[1]), "r"(a[2]), "r"(a[3]), "r"(b0), "r"(b1));
}

__device__ __forceinline__ void cp16(uint32_t dst, const void* src, bool ok) {
    asm volatile("cp.async.cg.shared.global [%0], [%1], 16, %2;"
        :: "r"(dst), "l"(src), "r"(ok ? 16 : 0) : "memory");
}
#define CP_COMMIT() asm volatile("cp.async.commit_group;" ::: "memory")
#define CP_WAIT0()  asm volatile("cp.async.wait_group 0;" ::: "memory")

// ---------------- device buffers ----------------
__device__ __nv_bfloat16 g_Ahi[(size_t)HWX * C];
__device__ __nv_bfloat16 g_Alo[(size_t)HWX * C];
__device__ __nv_bfloat16 g_Bhi[(size_t)HWX * C];
__device__ __nv_bfloat16 g_Blo[(size_t)HWX * C];
__device__ __nv_bfloat16 g_whi[NL * 49 * C * C];   // [l][tap][ci][co]
__device__ __nv_bfloat16 g_wlo[NL * 49 * C * C];
__device__ __nv_bfloat16 g_xhi[HH * E];
__device__ __nv_bfloat16 g_xlo[HH * E];
__device__ __nv_bfloat16 g_wxhi[(size_t)HH * E * C];
__device__ __nv_bfloat16 g_wxlo[(size_t)HH * E * C];
__device__ float g_bf[NL * C];
__device__ float g_u[HH * C];
__device__ float g_dproj[(MAXBIN + 1) * C];
__device__ float g_weff[C + 1];

// ---------------- prep kernels ----------------
__global__ void prep_u(const float* __restrict__ x, const float* __restrict__ w_in) {
    int i = blockIdx.x, c = threadIdx.x;
    const float* xr = x + i * E;
    const float* wr = w_in + c * E;
    float s = 0.f;
    #pragma unroll 8
    for (int e = 0; e < E; e++) s += wr[e] * xr[e];
    g_u[i * C + c] = s;
}

__global__ void prep_dproj(const float* __restrict__ dist, const float* __restrict__ w_in,
                           const float* __restrict__ b_in) {
    int p = blockIdx.x, c = threadIdx.x;
    const float* dr = dist + p * E;
    const float* wr = w_in + c * E;
    float s = b_in[c];
    #pragma unroll 8
    for (int e = 0; e < E; e++) s += wr[e] * dr[e];
    g_dproj[p * C + c] = s;
}

__global__ void prep_x(const float* __restrict__ x) {
    int i = blockIdx.x, e = threadIdx.x;
    float v = x[i * E + e];
    unsigned short h = f2bfu(v);
    g_xhi[i * E + e] = __ushort_as_bfloat16(h);
    g_xlo[i * E + e] = __float2bfloat16_rn(v - bf2f(h));
}

__global__ void prep_wx(const float* __restrict__ x, const float* __restrict__ w_in) {
    int i = blockIdx.x, e = threadIdx.x;
    float xie = x[i * E + e];
    size_t base = ((size_t)i * E + e) * C;
    #pragma unroll
    for (int c0 = 0; c0 < C; c0 += 2) {
        float v0 = w_in[c0 * E + e] * xie;
        float v1 = w_in[(c0 + 1) * E + e] * xie;
        unsigned short h0 = f2bfu(v0), h1 = f2bfu(v1);
        unsigned short l0 = f2bfu(v0 - bf2f(h0)), l1 = f2bfu(v1 - bf2f(h1));
        *(uint32_t*)(g_wxhi + base + c0) = (uint32_t)h0 | ((uint32_t)h1 << 16);
        *(uint32_t*)(g_wxlo + base + c0) = (uint32_t)l0 | ((uint32_t)l1 << 16);
    }
}

__global__ void prep_fold(const float* __restrict__ w_dil, const float* __restrict__ gamma,
                          const float* __restrict__ var) {
    int blk = blockIdx.x;
    int l = blk / 49, tap = blk % 49;
    int tid = threadIdx.x;
    __nv_bfloat16* dh = g_whi + blk * 4096;
    __nv_bfloat16* dl = g_wlo + blk * 4096;
    const float* wsrc = w_dil + l * C * C * 49;
    #pragma unroll
    for (int k = 0; k < 16; k++) {
        int idx = tid * 16 + k;           // ci*64 + co
        int ci = idx >> 6, co = idx & 63;
        float s = gamma[l * C + co] * rsqrtf(var[l * C + co] + 1e-5f);
        float v = wsrc[(co * C + ci) * 49 + tap] * s;
        unsigned short h = f2bfu(v);
        dh[idx] = __ushort_as_bfloat16(h);
        dl[idx] = __float2bfloat16_rn(v - bf2f(h));
    }
}

__global__ void prep_bias(const float* __restrict__ b_dil, const float* __restrict__ gamma,
                          const float* __restrict__ beta, const float* __restrict__ mean,
                          const float* __restrict__ var) {
    int l = blockIdx.x, c = threadIdx.x;
    float s = gamma[l * C + c] * rsqrtf(var[l * C + c] + 1e-5f);
    g_bf[l * C + c] = (b_dil[l * C + c] - mean[l * C + c]) * s + beta[l * C + c];
}

__global__ void prep_weff(const float* __restrict__ w_out, const float* __restrict__ b_out,
                          const float* __restrict__ w_head, const float* __restrict__ b_head) {
    int ci = threadIdx.x;
    float s = 0.f;
    for (int co = 0; co < C; co++) s += w_head[co] * w_out[co * C + ci];
    g_weff[ci] = s;
    if (ci == 0) {
        float b = b_head[0];
        for (int co = 0; co < C; co++) b += w_head[co] * b_out[co];
        g_weff[C] = b;
    }
}

// ---------------- pair via mma.sync ----------------
#define OFF_PAH(b) ((b) * 49152)
#define OFF_PAL(b) ((b) * 49152 + 16384)
#define OFF_PBH(b) ((b) * 49152 + 32768)
#define OFF_PBL(b) ((b) * 49152 + 40960)
#define SMEM_PAIR 98304

__global__ __launch_bounds__(256, 2) void pair_mma() {
    extern __shared__ char smem[];
    const uint32_t sb = smem_to_u32(smem);
    const int tid = threadIdx.x;
    const int wid = tid >> 5, lane = tid & 31;
    const int i = blockIdx.y;
    const int j0 = blockIdx.x * 128;

    int aRow[4], aCc[4]; uint32_t aOff[4];
    #pragma unroll
    for (int k = 0; k < 4; k++) {
        int chunk = tid + k * 256;
        aRow[k] = chunk >> 3;
        aCc[k] = chunk & 7;
        aOff[k] = (uint32_t)(aRow[k] * 128 + ((aCc[k] ^ (aRow[k] & 7)) << 4));
    }
    int bRow[2], bCc[2]; uint32_t bOff[2];
    #pragma unroll
    for (int k = 0; k < 2; k++) {
        int chunk = tid + k * 256;
        bRow[k] = chunk >> 3;
        bCc[k] = chunk & 7;
        bOff[k] = (uint32_t)(bRow[k] * 128 + ((bCc[k] ^ (bRow[k] & 7)) << 4));
    }

    const int row0 = wid * 16;
    const int quad = lane >> 3;
    const int rA = row0 + (lane & 7) + ((quad & 1) << 3);
    const int aChunkAdd = quad >> 1;
    const int rBbase = (lane & 7) + (((lane >> 3) & 1) << 3);
    const int bChunkAdd = lane >> 4;

    float acc[8][4] = {};

    {
        #pragma unroll
        for (int k = 0; k < 4; k++) {
            int j = j0 + aRow[k];
            bool ok = j < WW;
            size_t g = ok ? ((size_t)j * E + aCc[k] * 8) : 0;
            cp16(sb + OFF_PAH(0) + aOff[k], g_xhi + g, ok);
            cp16(sb + OFF_PAL(0) + aOff[k], g_xlo + g, ok);
        }
        size_t wb = ((size_t)i * E) * C;
        #pragma unroll
        for (int k = 0; k < 2; k++) {
            size_t g = wb + (size_t)bRow[k] * C + bCc[k] * 8;
            cp16(sb + OFF_PBH(0) + bOff[k], g_wxhi + g, true);
            cp16(sb + OFF_PBL(0) + bOff[k], g_wxlo + g, true);
        }
        CP_COMMIT();
        CP_WAIT0();
        __syncthreads();
    }

    #pragma unroll 1
    for (int ch = 0; ch < 4; ch++) {
        int buf = ch & 1;
        if (ch < 3) {
            int e0 = (ch + 1) * 64;
            int nb = buf ^ 1;
            #pragma unroll
            for (int k = 0; k < 4; k++) {
                int j = j0 + aRow[k];
                bool ok = j < WW;
                size_t g = ok ? ((size_t)j * E + e0 + aCc[k] * 8) : 0;
                cp16(sb + OFF_PAH(nb) + aOff[k], g_xhi + g, ok);
                cp16(sb + OFF_PAL(nb) + aOff[k], g_xlo + g, ok);
            }
            size_t wb = ((size_t)i * E + e0) * C;
            #pragma unroll
            for (int k = 0; k < 2; k++) {
                size_t g = wb + (size_t)bRow[k] * C + bCc[k] * 8;
                cp16(sb + OFF_PBH(nb) + bOff[k], g_wxhi + g, true);
                cp16(sb + OFF_PBL(nb) + bOff[k], g_wxlo + g, true);
            }
            CP_COMMIT();
        }

        const uint32_t pah = sb + OFF_PAH(buf);
        const uint32_t pal = sb + OFF_PAL(buf);
        const uint32_t pbh = sb + OFF_PBH(buf);
        const uint32_t pbl = sb + OFF_PBL(buf);
        #pragma unroll
        for (int ks = 0; ks < 4; ks++) {
            uint32_t ah[4], al[4];
            {
                int chunk = 2 * ks + aChunkAdd;
                uint32_t ao = (uint32_t)(rA * 128 + ((chunk ^ (rA & 7)) << 4));
                LDSM_X4(ah[0], ah[1], ah[2], ah[3], pah + ao);
                LDSM_X4(al[0], al[1], al[2], al[3], pal + ao);
            }
            int rB = rBbase + 16 * ks;
            #pragma unroll
            for (int p = 0; p < 4; p++) {
                int chunkB = 2 * p + bChunkAdd;
                uint32_t bo = (uint32_t)(rB * 128 + ((chunkB ^ (rB & 7)) << 4));
                uint32_t b0, b1, b2, b3;
                LDSM_X4_T(b0, b1, b2, b3, pbh + bo);
                mma16816(acc[2 * p],     ah, b0, b1);
                mma16816(acc[2 * p + 1], ah, b2, b3);
                mma16816(acc[2 * p],     al, b0, b1);
                mma16816(acc[2 * p + 1], al, b2, b3);
                LDSM_X4_T(b0, b1, b2, b3, pbl + bo);
                mma16816(acc[2 * p],     ah, b0, b1);
                mma16816(acc[2 * p + 1], ah, b2, b3);
            }
        }
        if (ch < 3) {
            CP_WAIT0();
            __syncthreads();
        }
    }

    int rtop = row0 + (lane >> 2);
    int cpair = (lane & 3) * 2;
    #pragma unroll
    for (int half = 0; half < 2; half++) {
        int j = j0 + rtop + half * 8;
        if (j < WW) {
            int pos = (i > j) ? (i - j) : (j - i);
            if (pos > MAXBIN) pos = MAXBIN;
            size_t prow = ((size_t)i * WW + j) * C;
            #pragma unroll
            for (int nt = 0; nt < 8; nt++) {
                int col = nt * 8 + cpair;
                float v0 = acc[nt][half * 2]     + 0.5f * (g_u[i * C + col]     + g_u[j * C + col])     + g_dproj[pos * C + col];
                float v1 = acc[nt][half * 2 + 1] + 0.5f * (g_u[i * C + col + 1] + g_u[j * C + col + 1]) + g_dproj[pos * C + col + 1];
                unsigned short h0 = f2bfu(v0), h1 = f2bfu(v1);
                unsigned short l0 = f2bfu(v0 - bf2f(h0)), l1 = f2bfu(v1 - bf2f(h1));
                *(uint32_t*)(g_Ahi + prow + col) = (uint32_t)h0 | ((uint32_t)h1 << 16);
                *(uint32_t*)(g_Alo + prow + col) = (uint32_t)l0 | ((uint32_t)l1 << 16);
            }
        }
    }
}

// ---------------- dilated conv (small dil): y-pair strip, DB W ----------------
#define OFF_BIAS 0
#define OFF_WB(b)  (256 + (b) * 16384)
#define OFF_S2     (256 + 32768)

template<int DIL>
__global__ __launch_bounds__(256, 2) void conv_strip2(int l) {
    constexpr int NR = ((128 + 6 * DIL) + 31) & ~31;

    extern __shared__ char smem[];
    const uint32_t sb = smem_to_u32(smem);
    const int tid = threadIdx.x;
    const int wid = tid >> 5, lane = tid & 31;
    const int y0 = blockIdx.y * 2;
    const int x0 = blockIdx.x * 128;

    const __nv_bfloat16* __restrict__ shi = (l & 1) ? g_Bhi : g_Ahi;
    const __nv_bfloat16* __restrict__ slo = (l & 1) ? g_Blo : g_Alo;
    __nv_bfloat16* __restrict__ dhi = (l & 1) ? g_Ahi : g_Bhi;
    __nv_bfloat16* __restrict__ dlo = (l & 1) ? g_Alo : g_Blo;
    const __nv_bfloat16* __restrict__ wh = g_whi + l * 49 * 4096;
    const __nv_bfloat16* __restrict__ wl = g_wlo + l * 49 * 4096;

    if (tid < C) ((float*)(smem + OFF_BIAS))[tid] = g_bf[l * C + tid];

    int wCi[2]; uint32_t wSo[2], wGo[2];
    #pragma unroll
    for (int k = 0; k < 2; k++) {
        int chunk = tid + k * 256;
        wCi[k] = chunk >> 3;
        int cc = chunk & 7;
        wGo[k] = (uint32_t)(wCi[k] * 64 + cc * 8);
        wSo[k] = (uint32_t)(wCi[k] * 128 + ((cc ^ (wCi[k] & 7)) << 4));
    }

    const int row0 = wid * 16;
    const int quad = lane >> 3;
    const int rA = row0 + (lane & 7) + ((quad & 1) << 3);
    const int aChunkAdd = quad >> 1;
    const int rBbase = (lane & 7) + (((lane >> 3) & 1) << 3);
    const int bChunkAdd = lane >> 4;

    float acc[2][8][4] = {};

    #pragma unroll 1
    for (int ky = 0; ky < 7; ky++) {
        #pragma unroll
        for (int s = 0; s < 2; s++) {
            int yy = y0 + s + (ky - 3) * DIL;
            bool yok = (yy >= 0) && (yy < HH);
            size_t rowbase = (size_t)yy * WW;
            uint32_t sbase = sb + OFF_S2 + s * (NR * 256);
            #pragma unroll 1
            for (int chunk = tid; chunk < NR * 8; chunk += 256) {
                int r = chunk >> 3;
                int cc = chunk & 7;
                int xg = x0 - 3 * DIL + r;
                bool ok = yok && (xg >= 0) && (xg < WW);
                size_t g = ok ? ((rowbase + xg) * C + cc * 8) : 0;
                uint32_t so = (uint32_t)(r * 128 + ((cc ^ (r & 7)) << 4));
                cp16(sbase + so, shi + g, ok);
                cp16(sbase + NR * 128 + so, slo + g, ok);
            }
        }
        {
            const __nv_bfloat16* wph = wh + (ky * 7) * 4096;
            const __nv_bfloat16* wpl = wl + (ky * 7) * 4096;
            #pragma unroll
            for (int k = 0; k < 2; k++) {
                cp16(sb + OFF_WB(0) + wSo[k],        wph + wGo[k], true);
                cp16(sb + OFF_WB(0) + 8192 + wSo[k], wpl + wGo[k], true);
            }
        }
        CP_COMMIT();
        CP_WAIT0();
        __syncthreads();

        #pragma unroll 1
        for (int kx = 0; kx < 7; kx++) {
            int buf = kx & 1;
            if (kx < 6) {
                const __nv_bfloat16* wph = wh + (ky * 7 + kx + 1) * 4096;
                const __nv_bfloat16* wpl = wl + (ky * 7 + kx + 1) * 4096;
                int nb = (kx + 1) & 1;
                #pragma unroll
                for (int k = 0; k < 2; k++) {
                    cp16(sb + OFF_WB(nb) + wSo[k],        wph + wGo[k], true);
                    cp16(sb + OFF_WB(nb) + 8192 + wSo[k], wpl + wGo[k], true);
                }
                CP_COMMIT();
            }
            const uint32_t wbh = sb + OFF_WB(buf);
            const uint32_t wbl = wbh + 8192;
            const int rowL = kx * DIL + rA;
            const uint32_t aoBase = (uint32_t)(rowL * 128);
            const int rpar = rowL & 7;
            const uint32_t s0h = sb + OFF_S2;
            const uint32_t s0l = s0h + NR * 128;
            const uint32_t s1h = s0h + NR * 256;
            const uint32_t s1l = s1h + NR * 128;

            #pragma unroll
            for (int ks = 0; ks < 4; ks++) {
                uint32_t ah0[4], al0[4], ah1[4], al1[4];
                {
                    int chunk = 2 * ks + aChunkAdd;
                    uint32_t ao = aoBase + ((uint32_t)(chunk ^ rpar) << 4);
                    LDSM_X4(ah0[0], ah0[1], ah0[2], ah0[3], s0h + ao);
                    LDSM_X4(al0[0], al0[1], al0[2], al0[3], s0l + ao);
                    LDSM_X4(ah1[0], ah1[1], ah1[2], ah1[3], s1h + ao);
                    LDSM_X4(al1[0], al1[1], al1[2], al1[3], s1l + ao);
                }
                int rB = rBbase + 16 * ks;
                #pragma unroll
                for (int p = 0; p < 4; p++) {
                    int chunkB = 2 * p + bChunkAdd;
                    uint32_t bo = (uint32_t)(rB * 128 + ((chunkB ^ (rB & 7)) << 4));
                    uint32_t b0, b1, b2, b3;
                    LDSM_X4_T(b0, b1, b2, b3, wbh + bo);
                    mma16816(acc[0][2 * p],     ah0, b0, b1);
                    mma16816(acc[0][2 * p + 1], ah0, b2, b3);
                    mma16816(acc[1][2 * p],     ah1, b0, b1);
                    mma16816(acc[1][2 * p + 1], ah1, b2, b3);
                    mma16816(acc[0][2 * p],     al0, b0, b1);
                    mma16816(acc[0][2 * p + 1], al0, b2, b3);
                    mma16816(acc[1][2 * p],     al1, b0, b1);
                    mma16816(acc[1][2 * p + 1], al1, b2, b3);
                    LDSM_X4_T(b0, b1, b2, b3, wbl + bo);
                    mma16816(acc[0][2 * p],     ah0, b0, b1);
                    mma16816(acc[0][2 * p + 1], ah0, b2, b3);
                    mma16816(acc[1][2 * p],     ah1, b0, b1);
                    mma16816(acc[1][2 * p + 1], ah1, b2, b3);
                }
            }
            if (kx < 6) {
                CP_WAIT0();
                __syncthreads();
            }
        }
        __syncthreads();
    }

    const float* sbias = (const float*)(smem + OFF_BIAS);
    int rtop = row0 + (lane >> 2);
    int cpair = (lane & 3) * 2;
    #pragma unroll
    for (int s = 0; s < 2; s++) {
        int y = y0 + s;
        #pragma unroll
        for (int half = 0; half < 2; half++) {
            int xg = x0 + rtop + half * 8;
            if (xg < WW) {
                size_t prow = ((size_t)y * WW + xg) * C;
                #pragma unroll
                for (int nt = 0; nt < 8; nt++) {
                    int col = nt * 8 + cpair;
                    size_t p = prow + col;
                    uint32_t rh = *(const uint32_t*)(shi + p);
                    uint32_t rl = *(const uint32_t*)(slo + p);
                    float v0 = acc[s][nt][half * 2]     + sbias[col]     + bf2f(rh & 0xffffu) + bf2f(rl & 0xffffu);
                    float v1 = acc[s][nt][half * 2 + 1] + sbias[col + 1] + bf2f(rh >> 16)     + bf2f(rl >> 16);
                    v0 = fmaxf(v0, 0.f); v1 = fmaxf(v1, 0.f);
                    unsigned short h0 = f2bfu(v0), h1 = f2bfu(v1);
                    unsigned short l0 = f2bfu(v0 - bf2f(h0)), l1 = f2bfu(v1 - bf2f(h1));
                    *(uint32_t*)(dhi + p) = (uint32_t)h0 | ((uint32_t)h1 << 16);
                    *(uint32_t*)(dlo + p) = (uint32_t)l0 | ((uint32_t)l1 << 16);
                }
            }
        }
    }
}

// ---------------- dilated conv (mid dil incl. 32): single-row strip, DB W ----------------
#define OFF_STRIP  (256 + 32768)

template<int DIL>
__global__ __launch_bounds__(256, 2) void conv_strip(int l) {
    constexpr int NR = ((128 + 6 * DIL) + 31) & ~31;
    constexpr int OFF_SH = OFF_STRIP;
    constexpr int OFF_SL = OFF_STRIP + NR * 128;

    extern __shared__ char smem[];
    const uint32_t sb = smem_to_u32(smem);
    const int tid = threadIdx.x;
    const int wid = tid >> 5, lane = tid & 31;
    const int y = blockIdx.y;
    const int x0 = blockIdx.x * 128;

    const __nv_bfloat16* __restrict__ shi = (l & 1) ? g_Bhi : g_Ahi;
    const __nv_bfloat16* __restrict__ slo = (l & 1) ? g_Blo : g_Alo;
    __nv_bfloat16* __restrict__ dhi = (l & 1) ? g_Ahi : g_Bhi;
    __nv_bfloat16* __restrict__ dlo = (l & 1) ? g_Alo : g_Blo;
    const __nv_bfloat16* __restrict__ wh = g_whi + l * 49 * 4096;
    const __nv_bfloat16* __restrict__ wl = g_wlo + l * 49 * 4096;

    if (tid < C) ((float*)(smem + OFF_BIAS))[tid] = g_bf[l * C + tid];

    int wCi[2]; uint32_t wSo[2], wGo[2];
    #pragma unroll
    for (int k = 0; k < 2; k++) {
        int chunk = tid + k * 256;
        wCi[k] = chunk >> 3;
        int cc = chunk & 7;
        wGo[k] = (uint32_t)(wCi[k] * 64 + cc * 8);
        wSo[k] = (uint32_t)(wCi[k] * 128 + ((cc ^ (wCi[k] & 7)) << 4));
    }

    const int row0 = wid * 16;
    const int quad = lane >> 3;
    const int rA = row0 + (lane & 7) + ((quad & 1) << 3);
    const int aChunkAdd = quad >> 1;
    const int rBbase = (lane & 7) + (((lane >> 3) & 1) << 3);
    const int bChunkAdd = lane >> 4;

    float acc[8][4] = {};

    #pragma unroll 1
    for (int ky = 0; ky < 7; ky++) {
        int yy = y + (ky - 3) * DIL;
        bool yok = (yy >= 0) && (yy < HH);
        size_t rowbase = (size_t)yy * WW;

        #pragma unroll 1
        for (int chunk = tid; chunk < NR * 8; chunk += 256) {
            int r = chunk >> 3;
            int cc = chunk & 7;
            int xg = x0 - 3 * DIL + r;
            bool ok = yok && (xg >= 0) && (xg < WW);
            size_t g = ok ? ((rowbase + xg) * C + cc * 8) : 0;
            uint32_t so = (uint32_t)(r * 128 + ((cc ^ (r & 7)) << 4));
            cp16(sb + OFF_SH + so, shi + g, ok);
            cp16(sb + OFF_SL + so, slo + g, ok);
        }
        {
            const __nv_bfloat16* wph = wh + (ky * 7) * 4096;
            const __nv_bfloat16* wpl = wl + (ky * 7) * 4096;
            #pragma unroll
            for (int k = 0; k < 2; k++) {
                cp16(sb + OFF_WB(0) + wSo[k],        wph + wGo[k], true);
                cp16(sb + OFF_WB(0) + 8192 + wSo[k], wpl + wGo[k], true);
            }
        }
        CP_COMMIT();
        CP_WAIT0();
        __syncthreads();

        #pragma unroll 1
        for (int kx = 0; kx < 7; kx++) {
            int buf = kx & 1;
            if (kx < 6) {
                const __nv_bfloat16* wph = wh + (ky * 7 + kx + 1) * 4096;
                const __nv_bfloat16* wpl = wl + (ky * 7 + kx + 1) * 4096;
                int nb = (kx + 1) & 1;
                #pragma unroll
                for (int k = 0; k < 2; k++) {
                    cp16(sb + OFF_WB(nb) + wSo[k],        wph + wGo[k], true);
                    cp16(sb + OFF_WB(nb) + 8192 + wSo[k], wpl + wGo[k], true);
                }
                CP_COMMIT();
            }
            const uint32_t wbh = sb + OFF_WB(buf);
            const uint32_t wbl = wbh + 8192;
            const int rowL = kx * DIL + rA;
            const uint32_t aoBase = (uint32_t)(rowL * 128);
            const int rpar = rowL & 7;

            #pragma unroll
            for (int ks = 0; ks < 4; ks++) {
                uint32_t ah[4], al[4];
                {
                    int chunk = 2 * ks + aChunkAdd;
                    uint32_t ao = aoBase + ((uint32_t)(chunk ^ rpar) << 4);
                    LDSM_X4(ah[0], ah[1], ah[2], ah[3], sb + OFF_SH + ao);
                    LDSM_X4(al[0], al[1], al[2], al[3], sb + OFF_SL + ao);
                }
                int rB = rBbase + 16 * ks;
                #pragma unroll
                for (int p = 0; p < 4; p++) {
                    int chunkB = 2 * p + bChunkAdd;
                    uint32_t bo = (uint32_t)(rB * 128 + ((chunkB ^ (rB & 7)) << 4));
                    uint32_t b0, b1, b2, b3;
                    LDSM_X4_T(b0, b1, b2, b3, wbh + bo);
                    mma16816(acc[2 * p],     ah, b0, b1);
                    mma16816(acc[2 * p + 1], ah, b2, b3);
                    mma16816(acc[2 * p],     al, b0, b1);
                    mma16816(acc[2 * p + 1], al, b2, b3);
                    LDSM_X4_T(b0, b1, b2, b3, wbl + bo);
                    mma16816(acc[2 * p],     ah, b0, b1);
                    mma16816(acc[2 * p + 1], ah, b2, b3);
                }
            }
            if (kx < 6) {
                CP_WAIT0();
                __syncthreads();
            }
        }
        __syncthreads();
    }

    const float* sbias = (const float*)(smem + OFF_BIAS);
    int rtop = row0 + (lane >> 2);
    int cpair = (lane & 3) * 2;
    #pragma unroll
    for (int half = 0; half < 2; half++) {
        int xg = x0 + rtop + half * 8;
        if (xg < WW) {
            size_t prow = ((size_t)y * WW + xg) * C;
            #pragma unroll
            for (int nt = 0; nt < 8; nt++) {
                int col = nt * 8 + cpair;
                size_t p = prow + col;
                uint32_t rh = *(const uint32_t*)(shi + p);
                uint32_t rl = *(const uint32_t*)(slo + p);
                float v0 = acc[nt][half * 2]     + sbias[col]     + bf2f(rh & 0xffffu) + bf2f(rl & 0xffffu);
                float v1 = acc[nt][half * 2 + 1] + sbias[col + 1] + bf2f(rh >> 16)     + bf2f(rl >> 16);
                v0 = fmaxf(v0, 0.f); v1 = fmaxf(v1, 0.f);
                unsigned short h0 = f2bfu(v0), h1 = f2bfu(v1);
                unsigned short l0 = f2bfu(v0 - bf2f(h0)), l1 = f2bfu(v1 - bf2f(h1));
                *(uint32_t*)(dhi + p) = (uint32_t)h0 | ((uint32_t)h1 << 16);
                *(uint32_t*)(dlo + p) = (uint32_t)l0 | ((uint32_t)l1 << 16);
            }
        }
    }
}

// ---------------- dilated conv (dil 64): per-tap double-buffered A+W ----------------
#define OT_BUF(b)  (256 + (b) * 49152)
#define SMEM_TAP   98560

template<int DIL>
__global__ __launch_bounds__(256, 2) void conv_tap(int l) {
    extern __shared__ char smem[];
    const uint32_t sb = smem_to_u32(smem);
    const int tid = threadIdx.x;
    const int wid = tid >> 5, lane = tid & 31;
    const int y = blockIdx.y;
    const int x0 = blockIdx.x * 128;

    const __nv_bfloat16* __restrict__ shi = (l & 1) ? g_Bhi : g_Ahi;
    const __nv_bfloat16* __restrict__ slo = (l & 1) ? g_Blo : g_Alo;
    __nv_bfloat16* __restrict__ dhi = (l & 1) ? g_Ahi : g_Bhi;
    __nv_bfloat16* __restrict__ dlo = (l & 1) ? g_Alo : g_Blo;
    const __nv_bfloat16* __restrict__ wh = g_whi + l * 49 * 4096;
    const __nv_bfloat16* __restrict__ wl = g_wlo + l * 49 * 4096;

    if (tid < C) ((float*)(smem))[tid] = g_bf[l * C + tid];

    int aRow[4], aCc[4]; uint32_t aOff[4];
    #pragma unroll
    for (int k = 0; k < 4; k++) {
        int chunk = tid + k * 256;
        aRow[k] = chunk >> 3;
        aCc[k] = chunk & 7;
        aOff[k] = (uint32_t)(aRow[k] * 128 + ((aCc[k] ^ (aRow[k] & 7)) << 4));
    }
    int wCi[2]; uint32_t wSo[2], wGo[2];
    #pragma unroll
    for (int k = 0; k < 2; k++) {
        int chunk = tid + k * 256;
        wCi[k] = chunk >> 3;
        int cc = chunk & 7;
        wGo[k] = (uint32_t)(wCi[k] * 64 + cc * 8);
        wSo[k] = (uint32_t)(wCi[k] * 128 + ((cc ^ (wCi[k] & 7)) << 4));
    }

    const int row0 = wid * 16;
    const int quad = lane >> 3;
    const int rA = row0 + (lane & 7) + ((quad & 1) << 3);
    const int aChunkAdd = quad >> 1;
    const int rBbase = (lane & 7) + (((lane >> 3) & 1) << 3);
    const int bChunkAdd = lane >> 4;
    const int rpar = rA & 7;
    const uint32_t aoBase = (uint32_t)(rA * 128);

    #define STAGE_TAP(TAP, BUF) do { \
        int _t = (TAP); \
        int _ky = _t / 7, _kx = _t - _ky * 7; \
        int _yy = y + (_ky - 3) * DIL; \
        bool _yok = (_yy >= 0) && (_yy < HH); \
        size_t _rb = (size_t)_yy * WW; \
        int _xs = x0 + (_kx - 3) * DIL; \
        uint32_t _ba = sb + OT_BUF(BUF); \
        _Pragma("unroll") \
        for (int _k = 0; _k < 4; _k++) { \
            int _xg = _xs + aRow[_k]; \
            bool _ok = _yok && (_xg >= 0) && (_xg < WW); \
            size_t _g = _ok ? ((_rb + _xg) * C + aCc[_k] * 8) : 0; \
            cp16(_ba + aOff[_k],         shi + _g, _ok); \
            cp16(_ba + 16384 + aOff[_k], slo + _g, _ok); \
        } \
        const __nv_bfloat16* _wph = wh + _t * 4096; \
        const __nv_bfloat16* _wpl = wl + _t * 4096; \
        _Pragma("unroll") \
        for (int _k = 0; _k < 2; _k++) { \
            cp16(_ba + 32768 + wSo[_k], _wph + wGo[_k], true); \
            cp16(_ba + 40960 + wSo[_k], _wpl + wGo[_k], true); \
        } \
    } while (0)

    float acc[8][4] = {};

    STAGE_TAP(0, 0);
    CP_COMMIT();
    CP_WAIT0();
    __syncthreads();

    #pragma unroll 1
    for (int tap = 0; tap < 49; ++tap) {
        int buf = tap & 1;
        if (tap < 48) {
            STAGE_TAP(tap + 1, buf ^ 1);
            CP_COMMIT();
        }
        const uint32_t pah = sb + OT_BUF(buf);
        const uint32_t pal = pah + 16384;
        const uint32_t wbh = pah + 32768;
        const uint32_t wbl = pah + 40960;

        #pragma unroll
        for (int ks = 0; ks < 4; ks++) {
            uint32_t ah[4], al[4];
            {
                int chunk = 2 * ks + aChunkAdd;
                uint32_t ao = aoBase + ((uint32_t)(chunk ^ rpar) << 4);
                LDSM_X4(ah[0], ah[1], ah[2], ah[3], pah + ao);
                LDSM_X4(al[0], al[1], al[2], al[3], pal + ao);
            }
            int rB = rBbase + 16 * ks;
            #pragma unroll
            for (int p = 0; p < 4; p++) {
                int chunkB = 2 * p + bChunkAdd;
                uint32_t bo = (uint32_t)(rB * 128 + ((chunkB ^ (rB & 7)) << 4));
                uint32_t b0, b1, b2, b3;
                LDSM_X4_T(b0, b1, b2, b3, wbh + bo);
                mma16816(acc[2 * p],     ah, b0, b1);
                mma16816(acc[2 * p + 1], ah, b2, b3);
                mma16816(acc[2 * p],     al, b0, b1);
                mma16816(acc[2 * p + 1], al, b2, b3);
                LDSM_X4_T(b0, b1, b2, b3, wbl + bo);
                mma16816(acc[2 * p],     ah, b0, b1);
                mma16816(acc[2 * p + 1], ah, b2, b3);
            }
        }
        if (tap < 48) {
            CP_WAIT0();
            __syncthreads();
        }
    }
    #undef STAGE_TAP

    const float* sbias = (const float*)(smem);
    int rtop = row0 + (lane >> 2);
    int cpair = (lane & 3) * 2;
    #pragma unroll
    for (int half = 0; half < 2; half++) {
        int xg = x0 + rtop + half * 8;
        if (xg < WW) {
            size_t prow = ((size_t)y * WW + xg) * C;
            #pragma unroll
            for (int nt = 0; nt < 8; nt++) {
                int col = nt * 8 + cpair;
                size_t p = prow + col;
                uint32_t rh = *(const uint32_t*)(shi + p);
                uint32_t rl = *(const uint32_t*)(slo + p);
                float v0 = acc[nt][half * 2]     + sbias[col]     + bf2f(rh & 0xffffu) + bf2f(rl & 0xffffu);
                float v1 = acc[nt][half * 2 + 1] + sbias[col + 1] + bf2f(rh >> 16)     + bf2f(rl >> 16);
                v0 = fmaxf(v0, 0.f); v1 = fmaxf(v1, 0.f);
                unsigned short h0 = f2bfu(v0), h1 = f2bfu(v1);
                unsigned short l0 = f2bfu(v0 - bf2f(h0)), l1 = f2bfu(v1 - bf2f(h1));
                *(uint32_t*)(dhi + p) = (uint32_t)h0 | ((uint32_t)h1 << 16);
                *(uint32_t*)(dlo + p) = (uint32_t)l0 | ((uint32_t)l1 << 16);
            }
        }
    }
}

// ---------------- head ----------------
__device__ __forceinline__ int tri_offs(int r) { return r * NOUT - (r * (r - 1)) / 2; }

__global__ void head_k(float* __restrict__ out) {
    int k = blockIdx.x * blockDim.x + threadIdx.x;
    if (k >= NTRI) return;
    float disc = (2.f * NOUT + 1.f) * (2.f * NOUT + 1.f) - 8.f * (float)k;
    int r = (int)(((2.f * NOUT + 1.f) - sqrtf(disc)) * 0.5f);
    if (r < 0) r = 0;
    if (r > NOUT - 1) r = NOUT - 1;
    while (r > 0 && tri_offs(r) > k) r--;
    while (r < NOUT - 1 && tri_offs(r + 1) <= k) r++;
    int c = r + (k - tri_offs(r));
    int yy = CROPV + r, xx = CROPV + c;
    size_t p = ((size_t)yy * WW + xx) * C;

    float s = g_weff[C];
    const uint4* rh = (const uint4*)(g_Bhi + p);
    const uint4* rl = (const uint4*)(g_Blo + p);
    #pragma unroll
    for (int q = 0; q < 8; q++) {
        uint4 vh = rh[q], vl = rl[q];
        uint32_t vhw[4] = {vh.x, vh.y, vh.z, vh.w};
        uint32_t vlw[4] = {vl.x, vl.y, vl.z, vl.w};
        #pragma unroll
        for (int e = 0; e < 4; e++) {
            int ci = q * 8 + e * 2;
            float h0 = bf2f(vhw[e] & 0xffffu) + bf2f(vlw[e] & 0xffffu);
            float h1 = bf2f(vhw[e] >> 16) + bf2f(vlw[e] >> 16);
            s = fmaf(h0, __ldg(&g_weff[ci]), s);
            s = fmaf(h1, __ldg(&g_weff[ci + 1]), s);
        }
    }
    out[k] = s;
}

// ------------------------------------------------------------------
template<int DIL>
static void launch_conv2(int l) {
    constexpr int NR = ((128 + 6 * DIL) + 31) & ~31;
    constexpr int SMEM = 256 + 32768 + 2 * NR * 256;
    static bool done = false;
    if (!done) {
        cudaFuncSetAttribute(conv_strip2<DIL>, cudaFuncAttributeMaxDynamicSharedMemorySize, SMEM);
        done = true;
    }
    conv_strip2<DIL><<<dim3((WW + 127) / 128, HH / 2), 256, SMEM>>>(l);
}

template<int DIL>
static void launch_conv(int l) {
    constexpr int NR = ((128 + 6 * DIL) + 31) & ~31;
    constexpr int SMEM = 256 + 32768 + NR * 256;
    static bool done = false;
    if (!done) {
        cudaFuncSetAttribute(conv_strip<DIL>, cudaFuncAttributeMaxDynamicSharedMemorySize, SMEM);
        done = true;
    }
    conv_strip<DIL><<<dim3((WW + 127) / 128, HH), 256, SMEM>>>(l);
}

template<int DIL>
static void launch_tap(int l) {
    static bool done = false;
    if (!done) {
        cudaFuncSetAttribute(conv_tap<DIL>, cudaFuncAttributeMaxDynamicSharedMemorySize, SMEM_TAP);
        done = true;
    }
    conv_tap<DIL><<<dim3((WW + 127) / 128, HH), 256, SMEM_TAP>>>(l);
}

extern "C" void kernel_launch(void* const* d_in, const int* in_sizes, int n_in,
                              void* d_out, int out_size) {
    const float* x      = (const float*)d_in[0];
    const float* dist   = (const float*)d_in[1];
    const float* w_in   = (const float*)d_in[2];
    const float* b_in   = (const float*)d_in[3];
    const float* w_dil  = (const float*)d_in[4];
    const float* b_dil  = (const float*)d_in[5];
    const float* gamma  = (const float*)d_in[6];
    const float* beta   = (const float*)d_in[7];
    const float* mean   = (const float*)d_in[8];
    const float* var    = (const float*)d_in[9];
    const float* w_out  = (const float*)d_in[10];
    const float* b_out  = (const float*)d_in[11];
    const float* w_head = (const float*)d_in[12];
    const float* b_head = (const float*)d_in[13];
    float* out = (float*)d_out;

    cudaFuncSetAttribute(pair_mma, cudaFuncAttributeMaxDynamicSharedMemorySize, SMEM_PAIR);

    prep_u<<<HH, C>>>(x, w_in);
    prep_dproj<<<MAXBIN + 1, C>>>(dist, w_in, b_in);
    prep_x<<<HH, E>>>(x);
    prep_wx<<<HH, E>>>(x, w_in);
    prep_fold<<<NL * 49, 256>>>(w_dil, gamma, var);
    prep_bias<<<NL, C>>>(b_dil, gamma, beta, mean, var);
    prep_weff<<<1, C>>>(w_out, b_out, w_head, b_head);

    pair_mma<<<dim3((WW + 127) / 128, HH), 256, SMEM_PAIR>>>();

    launch_conv2<1>(0);
    launch_conv2<2>(1);
    launch_conv2<4>(2);
    launch_conv<8>(3);
    launch_conv<16>(4);
    launch_conv<32>(5);
    launch_tap<64>(6);

    head_k<<<(NTRI + 255) / 256, 256>>>(out);
}

// round 14
// speedup vs baseline: 1.0332x; 1.0071x over previous
#include <cuda_runtime.h>
#include <cuda_bf16.h>
#include <cstdint>
#include <cstddef>

#define HH 600
#define WW 600
#define HWX (HH*WW)
#define C 64
#define E 256
#define NL 7
#define CROPV 50
#define NOUT 500
#define NTRI ((NOUT*(NOUT+1))/2)   // 125250
#define MAXBIN 100

__device__ __forceinline__ uint32_t smem_to_u32(const void* p) {
    uint32_t a;
    asm("{ .reg .u64 t; cvta.to.shared.u64 t, %1; cvt.u32.u64 %0, t; }" : "=r"(a) : "l"(p));
    return a;
}
__device__ __forceinline__ float bf2f(uint32_t u) {
    return __bfloat162float(__ushort_as_bfloat16((unsigned short)u));
}
__device__ __forceinline__ unsigned short f2bfu(float v) {
    return __bfloat16_as_ushort(__float2bfloat16_rn(v));
}

#define LDSM_X4(r0, r1, r2, r3, a) \
    asm volatile("ldmatrix.sync.aligned.m8n8.x4.shared.b16 {%0,%1,%2,%3}, [%4];" \
        : "=r"(r0), "=r"(r1), "=r"(r2), "=r"(r3) : "r"(a))
#define LDSM_X4_T(r0, r1, r2, r3, a) \
    asm volatile("ldmatrix.sync.aligned.m8n8.x4.trans.shared.b16 {%0,%1,%2,%3}, [%4];" \
        : "=r"(r0), "=r"(r1), "=r"(r2), "=r"(r3) : "r"(a))

__device__ __forceinline__ void mma16816(float* d, const uint32_t* a, uint32_t b0, uint32_t b1) {
    asm volatile("mma.sync.aligned.m16n8k16.row.col.f32.bf16.bf16.f32 "
        "{%0,%1,%2,%3}, {%4,%5,%6,%7}, {%8,%9}, {%0,%1,%2,%3};"
        : "+f"(d[0]), "+f"(d[1]), "+f"(d[2]), "+f"(d[3])
        : "r"(a[0]), "r"(a[1]), "r"(a[2]), "r"(a[3]), "r"(b0), "r"(b1));
}

__device__ __forceinline__ void cp16(uint32_t dst, const void* src, bool ok) {
    asm volatile("cp.async.cg.shared.global [%0], [%1], 16, %2;"
        :: "r"(dst), "l"(src), "r"(ok ? 16 : 0) : "memory");
}
#define CP_COMMIT() asm volatile("cp.async.commit_group;" ::: "memory")
#define CP_WAIT0()  asm volatile("cp.async.wait_group 0;" ::: "memory")

// ---------------- device buffers ----------------
__device__ __nv_bfloat16 g_Ahi[(size_t)HWX * C];
__device__ __nv_bfloat16 g_Alo[(size_t)HWX * C];
__device__ __nv_bfloat16 g_Bhi[(size_t)HWX * C];
__device__ __nv_bfloat16 g_Blo[(size_t)HWX * C];
__device__ __nv_bfloat16 g_whi[NL * 49 * C * C];   // [l][tap][ci][co]
__device__ __nv_bfloat16 g_wlo[NL * 49 * C * C];
__device__ __nv_bfloat16 g_xhi[HH * E];
__device__ __nv_bfloat16 g_xlo[HH * E];
__device__ __nv_bfloat16 g_wxhi[(size_t)HH * E * C];
__device__ __nv_bfloat16 g_wxlo[(size_t)HH * E * C];
__device__ float g_bf[NL * C];
__device__ float g_u[HH * C];
__device__ float g_dproj[(MAXBIN + 1) * C];
__device__ float g_weff[C + 1];

// ---------------- prep kernels ----------------
__global__ void prep_u(const float* __restrict__ x, const float* __restrict__ w_in) {
    int i = blockIdx.x, c = threadIdx.x;
    const float* xr = x + i * E;
    const float* wr = w_in + c * E;
    float s = 0.f;
    #pragma unroll 8
    for (int e = 0; e < E; e++) s += wr[e] * xr[e];
    g_u[i * C + c] = s;
}

__global__ void prep_dproj(const float* __restrict__ dist, const float* __restrict__ w_in,
                           const float* __restrict__ b_in) {
    int p = blockIdx.x, c = threadIdx.x;
    const float* dr = dist + p * E;
    const float* wr = w_in + c * E;
    float s = b_in[c];
    #pragma unroll 8
    for (int e = 0; e < E; e++) s += wr[e] * dr[e];
    g_dproj[p * C + c] = s;
}

// coalesced wx prep (fuses x hi/lo split): thread -> (e group, 8 consecutive c)
__global__ void prep_wx(const float* __restrict__ x, const float* __restrict__ w_in) {
    int i = blockIdx.x;
    int tid = threadIdx.x;
    int eg = tid >> 3;          // 0..31
    int c0 = (tid & 7) * 8;     // 0,8,..,56
    #pragma unroll
    for (int ee = 0; ee < 8; ee++) {
        int e = eg + ee * 32;
        float xie = x[i * E + e];
        if ((tid & 7) == 0) {
            unsigned short h = f2bfu(xie);
            g_xhi[i * E + e] = __ushort_as_bfloat16(h);
            g_xlo[i * E + e] = __float2bfloat16_rn(xie - bf2f(h));
        }
        size_t base = ((size_t)i * E + e) * C + c0;
        uint32_t hw[4], lw[4];
        #pragma unroll
        for (int k = 0; k < 4; k++) {
            float v0 = w_in[(c0 + 2 * k) * E + e] * xie;
            float v1 = w_in[(c0 + 2 * k + 1) * E + e] * xie;
            unsigned short h0 = f2bfu(v0), h1 = f2bfu(v1);
            unsigned short l0 = f2bfu(v0 - bf2f(h0)), l1 = f2bfu(v1 - bf2f(h1));
            hw[k] = (uint32_t)h0 | ((uint32_t)h1 << 16);
            lw[k] = (uint32_t)l0 | ((uint32_t)l1 << 16);
        }
        *(uint4*)(g_wxhi + base) = make_uint4(hw[0], hw[1], hw[2], hw[3]);
        *(uint4*)(g_wxlo + base) = make_uint4(lw[0], lw[1], lw[2], lw[3]);
    }
}

__global__ void prep_fold(const float* __restrict__ w_dil, const float* __restrict__ gamma,
                          const float* __restrict__ var) {
    int blk = blockIdx.x;
    int l = blk / 49, tap = blk % 49;
    int tid = threadIdx.x;
    __nv_bfloat16* dh = g_whi + blk * 4096;
    __nv_bfloat16* dl = g_wlo + blk * 4096;
    const float* wsrc = w_dil + l * C * C * 49;
    #pragma unroll
    for (int k = 0; k < 16; k++) {
        int idx = tid * 16 + k;           // ci*64 + co
        int ci = idx >> 6, co = idx & 63;
        float s = gamma[l * C + co] * rsqrtf(var[l * C + co] + 1e-5f);
        float v = wsrc[(co * C + ci) * 49 + tap] * s;
        unsigned short h = f2bfu(v);
        dh[idx] = __ushort_as_bfloat16(h);
        dl[idx] = __float2bfloat16_rn(v - bf2f(h));
    }
}

__global__ void prep_bias(const float* __restrict__ b_dil, const float* __restrict__ gamma,
                          const float* __restrict__ beta, const float* __restrict__ mean,
                          const float* __restrict__ var) {
    int l = blockIdx.x, c = threadIdx.x;
    float s = gamma[l * C + c] * rsqrtf(var[l * C + c] + 1e-5f);
    g_bf[l * C + c] = (b_dil[l * C + c] - mean[l * C + c]) * s + beta[l * C + c];
}

__global__ void prep_weff(const float* __restrict__ w_out, const float* __restrict__ b_out,
                          const float* __restrict__ w_head, const float* __restrict__ b_head) {
    int ci = threadIdx.x;
    float s = 0.f;
    for (int co = 0; co < C; co++) s += w_head[co] * w_out[co * C + ci];
    g_weff[ci] = s;
    if (ci == 0) {
        float b = b_head[0];
        for (int co = 0; co < C; co++) b += w_head[co] * b_out[co];
        g_weff[C] = b;
    }
}

// ---------------- pair via mma.sync ----------------
#define OFF_PAH(b) ((b) * 49152)
#define OFF_PAL(b) ((b) * 49152 + 16384)
#define OFF_PBH(b) ((b) * 49152 + 32768)
#define OFF_PBL(b) ((b) * 49152 + 40960)
#define SMEM_PAIR 98304

__global__ __launch_bounds__(256, 2) void pair_mma() {
    extern __shared__ char smem[];
    const uint32_t sb = smem_to_u32(smem);
    const int tid = threadIdx.x;
    const int wid = tid >> 5, lane = tid & 31;
    const int i = blockIdx.y;
    const int j0 = blockIdx.x * 128;

    int aRow[4], aCc[4]; uint32_t aOff[4];
    #pragma unroll
    for (int k = 0; k < 4; k++) {
        int chunk = tid + k * 256;
        aRow[k] = chunk >> 3;
        aCc[k] = chunk & 7;
        aOff[k] = (uint32_t)(aRow[k] * 128 + ((aCc[k] ^ (aRow[k] & 7)) << 4));
    }
    int bRow[2], bCc[2]; uint32_t bOff[2];
    #pragma unroll
    for (int k = 0; k < 2; k++) {
        int chunk = tid + k * 256;
        bRow[k] = chunk >> 3;
        bCc[k] = chunk & 7;
        bOff[k] = (uint32_t)(bRow[k] * 128 + ((bCc[k] ^ (bRow[k] & 7)) << 4));
    }

    const int row0 = wid * 16;
    const int quad = lane >> 3;
    const int rA = row0 + (lane & 7) + ((quad & 1) << 3);
    const int aChunkAdd = quad >> 1;
    const int rBbase = (lane & 7) + (((lane >> 3) & 1) << 3);
    const int bChunkAdd = lane >> 4;

    float acc[8][4] = {};

    {
        #pragma unroll
        for (int k = 0; k < 4; k++) {
            int j = j0 + aRow[k];
            bool ok = j < WW;
            size_t g = ok ? ((size_t)j * E + aCc[k] * 8) : 0;
            cp16(sb + OFF_PAH(0) + aOff[k], g_xhi + g, ok);
            cp16(sb + OFF_PAL(0) + aOff[k], g_xlo + g, ok);
        }
        size_t wb = ((size_t)i * E) * C;
        #pragma unroll
        for (int k = 0; k < 2; k++) {
            size_t g = wb + (size_t)bRow[k] * C + bCc[k] * 8;
            cp16(sb + OFF_PBH(0) + bOff[k], g_wxhi + g, true);
            cp16(sb + OFF_PBL(0) + bOff[k], g_wxlo + g, true);
        }
        CP_COMMIT();
        CP_WAIT0();
        __syncthreads();
    }

    #pragma unroll 1
    for (int ch = 0; ch < 4; ch++) {
        int buf = ch & 1;
        if (ch < 3) {
            int e0 = (ch + 1) * 64;
            int nb = buf ^ 1;
            #pragma unroll
            for (int k = 0; k < 4; k++) {
                int j = j0 + aRow[k];
                bool ok = j < WW;
                size_t g = ok ? ((size_t)j * E + e0 + aCc[k] * 8) : 0;
                cp16(sb + OFF_PAH(nb) + aOff[k], g_xhi + g, ok);
                cp16(sb + OFF_PAL(nb) + aOff[k], g_xlo + g, ok);
            }
            size_t wb = ((size_t)i * E + e0) * C;
            #pragma unroll
            for (int k = 0; k < 2; k++) {
                size_t g = wb + (size_t)bRow[k] * C + bCc[k] * 8;
                cp16(sb + OFF_PBH(nb) + bOff[k], g_wxhi + g, true);
                cp16(sb + OFF_PBL(nb) + bOff[k], g_wxlo + g, true);
            }
            CP_COMMIT();
        }

        const uint32_t pah = sb + OFF_PAH(buf);
        const uint32_t pal = sb + OFF_PAL(buf);
        const uint32_t pbh = sb + OFF_PBH(buf);
        const uint32_t pbl = sb + OFF_PBL(buf);
        #pragma unroll
        for (int ks = 0; ks < 4; ks++) {
            uint32_t ah[4], al[4];
            {
                int chunk = 2 * ks + aChunkAdd;
                uint32_t ao = (uint32_t)(rA * 128 + ((chunk ^ (rA & 7)) << 4));
                LDSM_X4(ah[0], ah[1], ah[2], ah[3], pah + ao);
                LDSM_X4(al[0], al[1], al[2], al[3], pal + ao);
            }
            int rB = rBbase + 16 * ks;
            #pragma unroll
            for (int p = 0; p < 4; p++) {
                int chunkB = 2 * p + bChunkAdd;
                uint32_t bo = (uint32_t)(rB * 128 + ((chunkB ^ (rB & 7)) << 4));
                uint32_t b0, b1, b2, b3;
                LDSM_X4_T(b0, b1, b2, b3, pbh + bo);
                mma16816(acc[2 * p],     ah, b0, b1);
                mma16816(acc[2 * p + 1], ah, b2, b3);
                mma16816(acc[2 * p],     al, b0, b1);
                mma16816(acc[2 * p + 1], al, b2, b3);
                LDSM_X4_T(b0, b1, b2, b3, pbl + bo);
                mma16816(acc[2 * p],     ah, b0, b1);
                mma16816(acc[2 * p + 1], ah, b2, b3);
            }
        }
        if (ch < 3) {
            CP_WAIT0();
            __syncthreads();
        }
    }

    int rtop = row0 + (lane >> 2);
    int cpair = (lane & 3) * 2;
    #pragma unroll
    for (int half = 0; half < 2; half++) {
        int j = j0 + rtop + half * 8;
        if (j < WW) {
            int pos = (i > j) ? (i - j) : (j - i);
            if (pos > MAXBIN) pos = MAXBIN;
            size_t prow = ((size_t)i * WW + j) * C;
            #pragma unroll
            for (int nt = 0; nt < 8; nt++) {
                int col = nt * 8 + cpair;
                float v0 = acc[nt][half * 2]     + 0.5f * (g_u[i * C + col]     + g_u[j * C + col])     + g_dproj[pos * C + col];
                float v1 = acc[nt][half * 2 + 1] + 0.5f * (g_u[i * C + col + 1] + g_u[j * C + col + 1]) + g_dproj[pos * C + col + 1];
                unsigned short h0 = f2bfu(v0), h1 = f2bfu(v1);
                unsigned short l0 = f2bfu(v0 - bf2f(h0)), l1 = f2bfu(v1 - bf2f(h1));
                *(uint32_t*)(g_Ahi + prow + col) = (uint32_t)h0 | ((uint32_t)h1 << 16);
                *(uint32_t*)(g_Alo + prow + col) = (uint32_t)l0 | ((uint32_t)l1 << 16);
            }
        }
    }
}

// ---------------- dilated conv (small dil): y-pair strip, DB W ----------------
#define OFF_BIAS 0
#define OFF_WB(b)  (256 + (b) * 16384)
#define OFF_S2     (256 + 32768)

template<int DIL>
__global__ __launch_bounds__(256, 2) void conv_strip2(int l) {
    constexpr int NR = ((128 + 6 * DIL) + 31) & ~31;

    extern __shared__ char smem[];
    const uint32_t sb = smem_to_u32(smem);
    const int tid = threadIdx.x;
    const int wid = tid >> 5, lane = tid & 31;
    const int y0 = blockIdx.y * 2;
    const int x0 = blockIdx.x * 128;

    const __nv_bfloat16* __restrict__ shi = (l & 1) ? g_Bhi : g_Ahi;
    const __nv_bfloat16* __restrict__ slo = (l & 1) ? g_Blo : g_Alo;
    __nv_bfloat16* __restrict__ dhi = (l & 1) ? g_Ahi : g_Bhi;
    __nv_bfloat16* __restrict__ dlo = (l & 1) ? g_Alo : g_Blo;
    const __nv_bfloat16* __restrict__ wh = g_whi + l * 49 * 4096;
    const __nv_bfloat16* __restrict__ wl = g_wlo + l * 49 * 4096;

    if (tid < C) ((float*)(smem + OFF_BIAS))[tid] = g_bf[l * C + tid];

    int wCi[2]; uint32_t wSo[2], wGo[2];
    #pragma unroll
    for (int k = 0; k < 2; k++) {
        int chunk = tid + k * 256;
        wCi[k] = chunk >> 3;
        int cc = chunk & 7;
        wGo[k] = (uint32_t)(wCi[k] * 64 + cc * 8);
        wSo[k] = (uint32_t)(wCi[k] * 128 + ((cc ^ (wCi[k] & 7)) << 4));
    }

    const int row0 = wid * 16;
    const int quad = lane >> 3;
    const int rA = row0 + (lane & 7) + ((quad & 1) << 3);
    const int aChunkAdd = quad >> 1;
    const int rBbase = (lane & 7) + (((lane >> 3) & 1) << 3);
    const int bChunkAdd = lane >> 4;

    float acc[2][8][4] = {};

    #pragma unroll 1
    for (int ky = 0; ky < 7; ky++) {
        #pragma unroll
        for (int s = 0; s < 2; s++) {
            int yy = y0 + s + (ky - 3) * DIL;
            bool yok = (yy >= 0) && (yy < HH);
            size_t rowbase = (size_t)yy * WW;
            uint32_t sbase = sb + OFF_S2 + s * (NR * 256);
            #pragma unroll 1
            for (int chunk = tid; chunk < NR * 8; chunk += 256) {
                int r = chunk >> 3;
                int cc = chunk & 7;
                int xg = x0 - 3 * DIL + r;
                bool ok = yok && (xg >= 0) && (xg < WW);
                size_t g = ok ? ((rowbase + xg) * C + cc * 8) : 0;
                uint32_t so = (uint32_t)(r * 128 + ((cc ^ (r & 7)) << 4));
                cp16(sbase + so, shi + g, ok);
                cp16(sbase + NR * 128 + so, slo + g, ok);
            }
        }
        {
            const __nv_bfloat16* wph = wh + (ky * 7) * 4096;
            const __nv_bfloat16* wpl = wl + (ky * 7) * 4096;
            #pragma unroll
            for (int k = 0; k < 2; k++) {
                cp16(sb + OFF_WB(0) + wSo[k],        wph + wGo[k], true);
                cp16(sb + OFF_WB(0) + 8192 + wSo[k], wpl + wGo[k], true);
            }
        }
        CP_COMMIT();
        CP_WAIT0();
        __syncthreads();

        #pragma unroll 1
        for (int kx = 0; kx < 7; kx++) {
            int buf = kx & 1;
            if (kx < 6) {
                const __nv_bfloat16* wph = wh + (ky * 7 + kx + 1) * 4096;
                const __nv_bfloat16* wpl = wl + (ky * 7 + kx + 1) * 4096;
                int nb = (kx + 1) & 1;
                #pragma unroll
                for (int k = 0; k < 2; k++) {
                    cp16(sb + OFF_WB(nb) + wSo[k],        wph + wGo[k], true);
                    cp16(sb + OFF_WB(nb) + 8192 + wSo[k], wpl + wGo[k], true);
                }
                CP_COMMIT();
            }
            const uint32_t wbh = sb + OFF_WB(buf);
            const uint32_t wbl = wbh + 8192;
            const int rowL = kx * DIL + rA;
            const uint32_t aoBase = (uint32_t)(rowL * 128);
            const int rpar = rowL & 7;
            const uint32_t s0h = sb + OFF_S2;
            const uint32_t s0l = s0h + NR * 128;
            const uint32_t s1h = s0h + NR * 256;
            const uint32_t s1l = s1h + NR * 128;

            #pragma unroll
            for (int ks = 0; ks < 4; ks++) {
                uint32_t ah0[4], al0[4], ah1[4], al1[4];
                {
                    int chunk = 2 * ks + aChunkAdd;
                    uint32_t ao = aoBase + ((uint32_t)(chunk ^ rpar) << 4);
                    LDSM_X4(ah0[0], ah0[1], ah0[2], ah0[3], s0h + ao);
                    LDSM_X4(al0[0], al0[1], al0[2], al0[3], s0l + ao);
                    LDSM_X4(ah1[0], ah1[1], ah1[2], ah1[3], s1h + ao);
                    LDSM_X4(al1[0], al1[1], al1[2], al1[3], s1l + ao);
                }
                int rB = rBbase + 16 * ks;
                #pragma unroll
                for (int p = 0; p < 4; p++) {
                    int chunkB = 2 * p + bChunkAdd;
                    uint32_t bo = (uint32_t)(rB * 128 + ((chunkB ^ (rB & 7)) << 4));
                    uint32_t b0, b1, b2, b3;
                    LDSM_X4_T(b0, b1, b2, b3, wbh + bo);
                    mma16816(acc[0][2 * p],     ah0, b0, b1);
                    mma16816(acc[0][2 * p + 1], ah0, b2, b3);
                    mma16816(acc[1][2 * p],     ah1, b0, b1);
                    mma16816(acc[1][2 * p + 1], ah1, b2, b3);
                    mma16816(acc[0][2 * p],     al0, b0, b1);
                    mma16816(acc[0][2 * p + 1], al0, b2, b3);
                    mma16816(acc[1][2 * p],     al1, b0, b1);
                    mma16816(acc[1][2 * p + 1], al1, b2, b3);
                    LDSM_X4_T(b0, b1, b2, b3, wbl + bo);
                    mma16816(acc[0][2 * p],     ah0, b0, b1);
                    mma16816(acc[0][2 * p + 1], ah0, b2, b3);
                    mma16816(acc[1][2 * p],     ah1, b0, b1);
                    mma16816(acc[1][2 * p + 1], ah1, b2, b3);
                }
            }
            if (kx < 6) {
                CP_WAIT0();
                __syncthreads();
            }
        }
        __syncthreads();
    }

    const float* sbias = (const float*)(smem + OFF_BIAS);
    int rtop = row0 + (lane >> 2);
    int cpair = (lane & 3) * 2;
    #pragma unroll
    for (int s = 0; s < 2; s++) {
        int y = y0 + s;
        #pragma unroll
        for (int half = 0; half < 2; half++) {
            int xg = x0 + rtop + half * 8;
            if (xg < WW) {
                size_t prow = ((size_t)y * WW + xg) * C;
                #pragma unroll
                for (int nt = 0; nt < 8; nt++) {
                    int col = nt * 8 + cpair;
                    size_t p = prow + col;
                    uint32_t rh = *(const uint32_t*)(shi + p);
                    uint32_t rl = *(const uint32_t*)(slo + p);
                    float v0 = acc[s][nt][half * 2]     + sbias[col]     + bf2f(rh & 0xffffu) + bf2f(rl & 0xffffu);
                    float v1 = acc[s][nt][half * 2 + 1] + sbias[col + 1] + bf2f(rh >> 16)     + bf2f(rl >> 16);
                    v0 = fmaxf(v0, 0.f); v1 = fmaxf(v1, 0.f);
                    unsigned short h0 = f2bfu(v0), h1 = f2bfu(v1);
                    unsigned short l0 = f2bfu(v0 - bf2f(h0)), l1 = f2bfu(v1 - bf2f(h1));
                    *(uint32_t*)(dhi + p) = (uint32_t)h0 | ((uint32_t)h1 << 16);
                    *(uint32_t*)(dlo + p) = (uint32_t)l0 | ((uint32_t)l1 << 16);
                }
            }
        }
    }
}

// ---------------- dilated conv (mid dil incl. 32): single-row strip, DB W ----------------
#define OFF_STRIP  (256 + 32768)

template<int DIL>
__global__ __launch_bounds__(256, 2) void conv_strip(int l) {
    constexpr int NR = ((128 + 6 * DIL) + 31) & ~31;
    constexpr int OFF_SH = OFF_STRIP;
    constexpr int OFF_SL = OFF_STRIP + NR * 128;

    extern __shared__ char smem[];
    const uint32_t sb = smem_to_u32(smem);
    const int tid = threadIdx.x;
    const int wid = tid >> 5, lane = tid & 31;
    const int y = blockIdx.y;
    const int x0 = blockIdx.x * 128;

    const __nv_bfloat16* __restrict__ shi = (l & 1) ? g_Bhi : g_Ahi;
    const __nv_bfloat16* __restrict__ slo = (l & 1) ? g_Blo : g_Alo;
    __nv_bfloat16* __restrict__ dhi = (l & 1) ? g_Ahi : g_Bhi;
    __nv_bfloat16* __restrict__ dlo = (l & 1) ? g_Alo : g_Blo;
    const __nv_bfloat16* __restrict__ wh = g_whi + l * 49 * 4096;
    const __nv_bfloat16* __restrict__ wl = g_wlo + l * 49 * 4096;

    if (tid < C) ((float*)(smem + OFF_BIAS))[tid] = g_bf[l * C + tid];

    int wCi[2]; uint32_t wSo[2], wGo[2];
    #pragma unroll
    for (int k = 0; k < 2; k++) {
        int chunk = tid + k * 256;
        wCi[k] = chunk >> 3;
        int cc = chunk & 7;
        wGo[k] = (uint32_t)(wCi[k] * 64 + cc * 8);
        wSo[k] = (uint32_t)(wCi[k] * 128 + ((cc ^ (wCi[k] & 7)) << 4));
    }

    const int row0 = wid * 16;
    const int quad = lane >> 3;
    const int rA = row0 + (lane & 7) + ((quad & 1) << 3);
    const int aChunkAdd = quad >> 1;
    const int rBbase = (lane & 7) + (((lane >> 3) & 1) << 3);
    const int bChunkAdd = lane >> 4;

    float acc[8][4] = {};

    #pragma unroll 1
    for (int ky = 0; ky < 7; ky++) {
        int yy = y + (ky - 3) * DIL;
        bool yok = (yy >= 0) && (yy < HH);
        size_t rowbase = (size_t)yy * WW;

        #pragma unroll 1
        for (int chunk = tid; chunk < NR * 8; chunk += 256) {
            int r = chunk >> 3;
            int cc = chunk & 7;
            int xg = x0 - 3 * DIL + r;
            bool ok = yok && (xg >= 0) && (xg < WW);
            size_t g = ok ? ((rowbase + xg) * C + cc * 8) : 0;
            uint32_t so = (uint32_t)(r * 128 + ((cc ^ (r & 7)) << 4));
            cp16(sb + OFF_SH + so, shi + g, ok);
            cp16(sb + OFF_SL + so, slo + g, ok);
        }
        {
            const __nv_bfloat16* wph = wh + (ky * 7) * 4096;
            const __nv_bfloat16* wpl = wl + (ky * 7) * 4096;
            #pragma unroll
            for (int k = 0; k < 2; k++) {
                cp16(sb + OFF_WB(0) + wSo[k],        wph + wGo[k], true);
                cp16(sb + OFF_WB(0) + 8192 + wSo[k], wpl + wGo[k], true);
            }
        }
        CP_COMMIT();
        CP_WAIT0();
        __syncthreads();

        #pragma unroll 1
        for (int kx = 0; kx < 7; kx++) {
            int buf = kx & 1;
            if (kx < 6) {
                const __nv_bfloat16* wph = wh + (ky * 7 + kx + 1) * 4096;
                const __nv_bfloat16* wpl = wl + (ky * 7 + kx + 1) * 4096;
                int nb = (kx + 1) & 1;
                #pragma unroll
                for (int k = 0; k < 2; k++) {
                    cp16(sb + OFF_WB(nb) + wSo[k],        wph + wGo[k], true);
                    cp16(sb + OFF_WB(nb) + 8192 + wSo[k], wpl + wGo[k], true);
                }
                CP_COMMIT();
            }
            const uint32_t wbh = sb + OFF_WB(buf);
            const uint32_t wbl = wbh + 8192;
            const int rowL = kx * DIL + rA;
            const uint32_t aoBase = (uint32_t)(rowL * 128);
            const int rpar = rowL & 7;

            #pragma unroll
            for (int ks = 0; ks < 4; ks++) {
                uint32_t ah[4], al[4];
                {
                    int chunk = 2 * ks + aChunkAdd;
                    uint32_t ao = aoBase + ((uint32_t)(chunk ^ rpar) << 4);
                    LDSM_X4(ah[0], ah[1], ah[2], ah[3], sb + OFF_SH + ao);
                    LDSM_X4(al[0], al[1], al[2], al[3], sb + OFF_SL + ao);
                }
                int rB = rBbase + 16 * ks;
                #pragma unroll
                for (int p = 0; p < 4; p++) {
                    int chunkB = 2 * p + bChunkAdd;
                    uint32_t bo = (uint32_t)(rB * 128 + ((chunkB ^ (rB & 7)) << 4));
                    uint32_t b0, b1, b2, b3;
                    LDSM_X4_T(b0, b1, b2, b3, wbh + bo);
                    mma16816(acc[2 * p],     ah, b0, b1);
                    mma16816(acc[2 * p + 1], ah, b2, b3);
                    mma16816(acc[2 * p],     al, b0, b1);
                    mma16816(acc[2 * p + 1], al, b2, b3);
                    LDSM_X4_T(b0, b1, b2, b3, wbl + bo);
                    mma16816(acc[2 * p],     ah, b0, b1);
                    mma16816(acc[2 * p + 1], ah, b2, b3);
                }
            }
            if (kx < 6) {
                CP_WAIT0();
                __syncthreads();
            }
        }
        __syncthreads();
    }

    const float* sbias = (const float*)(smem + OFF_BIAS);
    int rtop = row0 + (lane >> 2);
    int cpair = (lane & 3) * 2;
    #pragma unroll
    for (int half = 0; half < 2; half++) {
        int xg = x0 + rtop + half * 8;
        if (xg < WW) {
            size_t prow = ((size_t)y * WW + xg) * C;
            #pragma unroll
            for (int nt = 0; nt < 8; nt++) {
                int col = nt * 8 + cpair;
                size_t p = prow + col;
                uint32_t rh = *(const uint32_t*)(shi + p);
                uint32_t rl = *(const uint32_t*)(slo + p);
                float v0 = acc[nt][half * 2]     + sbias[col]     + bf2f(rh & 0xffffu) + bf2f(rl & 0xffffu);
                float v1 = acc[nt][half * 2 + 1] + sbias[col + 1] + bf2f(rh >> 16)     + bf2f(rl >> 16);
                v0 = fmaxf(v0, 0.f); v1 = fmaxf(v1, 0.f);
                unsigned short h0 = f2bfu(v0), h1 = f2bfu(v1);
                unsigned short l0 = f2bfu(v0 - bf2f(h0)), l1 = f2bfu(v1 - bf2f(h1));
                *(uint32_t*)(dhi + p) = (uint32_t)h0 | ((uint32_t)h1 << 16);
                *(uint32_t*)(dlo + p) = (uint32_t)l0 | ((uint32_t)l1 << 16);
            }
        }
    }
}

// ---------------- dilated conv (dil 64): per-tap double-buffered A+W ----------------
#define OT_BUF(b)  (256 + (b) * 49152)
#define SMEM_TAP   98560

template<int DIL>
__global__ __launch_bounds__(256, 2) void conv_tap(int l) {
    extern __shared__ char smem[];
    const uint32_t sb = smem_to_u32(smem);
    const int tid = threadIdx.x;
    const int wid = tid >> 5, lane = tid & 31;
    const int y = blockIdx.y;
    const int x0 = blockIdx.x * 128;

    const __nv_bfloat16* __restrict__ shi = (l & 1) ? g_Bhi : g_Ahi;
    const __nv_bfloat16* __restrict__ slo = (l & 1) ? g_Blo : g_Alo;
    __nv_bfloat16* __restrict__ dhi = (l & 1) ? g_Ahi : g_Bhi;
    __nv_bfloat16* __restrict__ dlo = (l & 1) ? g_Alo : g_Blo;
    const __nv_bfloat16* __restrict__ wh = g_whi + l * 49 * 4096;
    const __nv_bfloat16* __restrict__ wl = g_wlo + l * 49 * 4096;

    if (tid < C) ((float*)(smem))[tid] = g_bf[l * C + tid];

    int aRow[4], aCc[4]; uint32_t aOff[4];
    #pragma unroll
    for (int k = 0; k < 4; k++) {
        int chunk = tid + k * 256;
        aRow[k] = chunk >> 3;
        aCc[k] = chunk & 7;
        aOff[k] = (uint32_t)(aRow[k] * 128 + ((aCc[k] ^ (aRow[k] & 7)) << 4));
    }
    int wCi[2]; uint32_t wSo[2], wGo[2];
    #pragma unroll
    for (int k = 0; k < 2; k++) {
        int chunk = tid + k * 256;
        wCi[k] = chunk >> 3;
        int cc = chunk & 7;
        wGo[k] = (uint32_t)(wCi[k] * 64 + cc * 8);
        wSo[k] = (uint32_t)(wCi[k] * 128 + ((cc ^ (wCi[k] & 7)) << 4));
    }

    const int row0 = wid * 16;
    const int quad = lane >> 3;
    const int rA = row0 + (lane & 7) + ((quad & 1) << 3);
    const int aChunkAdd = quad >> 1;
    const int rBbase = (lane & 7) + (((lane >> 3) & 1) << 3);
    const int bChunkAdd = lane >> 4;
    const int rpar = rA & 7;
    const uint32_t aoBase = (uint32_t)(rA * 128);

    #define STAGE_TAP(TAP, BUF) do { \
        int _t = (TAP); \
        int _ky = _t / 7, _kx = _t - _ky * 7; \
        int _yy = y + (_ky - 3) * DIL; \
        bool _yok = (_yy >= 0) && (_yy < HH); \
        size_t _rb = (size_t)_yy * WW; \
        int _xs = x0 + (_kx - 3) * DIL; \
        uint32_t _ba = sb + OT_BUF(BUF); \
        _Pragma("unroll") \
        for (int _k = 0; _k < 4; _k++) { \
            int _xg = _xs + aRow[_k]; \
            bool _ok = _yok && (_xg >= 0) && (_xg < WW); \
            size_t _g = _ok ? ((_rb + _xg) * C + aCc[_k] * 8) : 0; \
            cp16(_ba + aOff[_k],         shi + _g, _ok); \
            cp16(_ba + 16384 + aOff[_k], slo + _g, _ok); \
        } \
        const __nv_bfloat16* _wph = wh + _t * 4096; \
        const __nv_bfloat16* _wpl = wl + _t * 4096; \
        _Pragma("unroll") \
        for (int _k = 0; _k < 2; _k++) { \
            cp16(_ba + 32768 + wSo[_k], _wph + wGo[_k], true); \
            cp16(_ba + 40960 + wSo[_k], _wpl + wGo[_k], true); \
        } \
    } while (0)

    float acc[8][4] = {};

    STAGE_TAP(0, 0);
    CP_COMMIT();
    CP_WAIT0();
    __syncthreads();

    #pragma unroll 1
    for (int tap = 0; tap < 49; ++tap) {
        int buf = tap & 1;
        if (tap < 48) {
            STAGE_TAP(tap + 1, buf ^ 1);
            CP_COMMIT();
        }
        const uint32_t pah = sb + OT_BUF(buf);
        const uint32_t pal = pah + 16384;
        const uint32_t wbh = pah + 32768;
        const uint32_t wbl = pah + 40960;

        #pragma unroll
        for (int ks = 0; ks < 4; ks++) {
            uint32_t ah[4], al[4];
            {
                int chunk = 2 * ks + aChunkAdd;
                uint32_t ao = aoBase + ((uint32_t)(chunk ^ rpar) << 4);
                LDSM_X4(ah[0], ah[1], ah[2], ah[3], pah + ao);
                LDSM_X4(al[0], al[1], al[2], al[3], pal + ao);
            }
            int rB = rBbase + 16 * ks;
            #pragma unroll
            for (int p = 0; p < 4; p++) {
                int chunkB = 2 * p + bChunkAdd;
                uint32_t bo = (uint32_t)(rB * 128 + ((chunkB ^ (rB & 7)) << 4));
                uint32_t b0, b1, b2, b3;
                LDSM_X4_T(b0, b1, b2, b3, wbh + bo);
                mma16816(acc[2 * p],     ah, b0, b1);
                mma16816(acc[2 * p + 1], ah, b2, b3);
                mma16816(acc[2 * p],     al, b0, b1);
                mma16816(acc[2 * p + 1], al, b2, b3);
                LDSM_X4_T(b0, b1, b2, b3, wbl + bo);
                mma16816(acc[2 * p],     ah, b0, b1);
                mma16816(acc[2 * p + 1], ah, b2, b3);
            }
        }
        if (tap < 48) {
            CP_WAIT0();
            __syncthreads();
        }
    }
    #undef STAGE_TAP

    const float* sbias = (const float*)(smem);
    int rtop = row0 + (lane >> 2);
    int cpair = (lane & 3) * 2;
    #pragma unroll
    for (int half = 0; half < 2; half++) {
        int xg = x0 + rtop + half * 8;
        if (xg < WW) {
            size_t prow = ((size_t)y * WW + xg) * C;
            #pragma unroll
            for (int nt = 0; nt < 8; nt++) {
                int col = nt * 8 + cpair;
                size_t p = prow + col;
                uint32_t rh = *(const uint32_t*)(shi + p);
                uint32_t rl = *(const uint32_t*)(slo + p);
                float v0 = acc[nt][half * 2]     + sbias[col]     + bf2f(rh & 0xffffu) + bf2f(rl & 0xffffu);
                float v1 = acc[nt][half * 2 + 1] + sbias[col + 1] + bf2f(rh >> 16)     + bf2f(rl >> 16);
                v0 = fmaxf(v0, 0.f); v1 = fmaxf(v1, 0.f);
                unsigned short h0 = f2bfu(v0), h1 = f2bfu(v1);
                unsigned short l0 = f2bfu(v0 - bf2f(h0)), l1 = f2bfu(v1 - bf2f(h1));
                *(uint32_t*)(dhi + p) = (uint32_t)h0 | ((uint32_t)h1 << 16);
                *(uint32_t*)(dlo + p) = (uint32_t)l0 | ((uint32_t)l1 << 16);
            }
        }
    }
}

// ---------------- head ----------------
__device__ __forceinline__ int tri_offs(int r) { return r * NOUT - (r * (r - 1)) / 2; }

__global__ void head_k(float* __restrict__ out) {
    int k = blockIdx.x * blockDim.x + threadIdx.x;
    if (k >= NTRI) return;
    float disc = (2.f * NOUT + 1.f) * (2.f * NOUT + 1.f) - 8.f * (float)k;
    int r = (int)(((2.f * NOUT + 1.f) - sqrtf(disc)) * 0.5f);
    if (r < 0) r = 0;
    if (r > NOUT - 1) r = NOUT - 1;
    while (r > 0 && tri_offs(r) > k) r--;
    while (r < NOUT - 1 && tri_offs(r + 1) <= k) r++;
    int c = r + (k - tri_offs(r));
    int yy = CROPV + r, xx = CROPV + c;
    size_t p = ((size_t)yy * WW + xx) * C;

    float s = g_weff[C];
    const uint4* rh = (const uint4*)(g_Bhi + p);
    const uint4* rl = (const uint4*)(g_Blo + p);
    #pragma unroll
    for (int q = 0; q < 8; q++) {
        uint4 vh = rh[q], vl = rl[q];
        uint32_t vhw[4] = {vh.x, vh.y, vh.z, vh.w};
        uint32_t vlw[4] = {vl.x, vl.y, vl.z, vl.w};
        #pragma unroll
        for (int e = 0; e < 4; e++) {
            int ci = q * 8 + e * 2;
            float h0 = bf2f(vhw[e] & 0xffffu) + bf2f(vlw[e] & 0xffffu);
            float h1 = bf2f(vhw[e] >> 16) + bf2f(vlw[e] >> 16);
            s = fmaf(h0, __ldg(&g_weff[ci]), s);
            s = fmaf(h1, __ldg(&g_weff[ci + 1]), s);
        }
    }
    out[k] = s;
}

// ------------------------------------------------------------------
template<int DIL>
static void launch_conv2(int l) {
    constexpr int NR = ((128 + 6 * DIL) + 31) & ~31;
    constexpr int SMEM = 256 + 32768 + 2 * NR * 256;
    static bool done = false;
    if (!done) {
        cudaFuncSetAttribute(conv_strip2<DIL>, cudaFuncAttributeMaxDynamicSharedMemorySize, SMEM);
        done = true;
    }
    conv_strip2<DIL><<<dim3((WW + 127) / 128, HH / 2), 256, SMEM>>>(l);
}

template<int DIL>
static void launch_conv(int l) {
    constexpr int NR = ((128 + 6 * DIL) + 31) & ~31;
    constexpr int SMEM = 256 + 32768 + NR * 256;
    static bool done = false;
    if (!done) {
        cudaFuncSetAttribute(conv_strip<DIL>, cudaFuncAttributeMaxDynamicSharedMemorySize, SMEM);
        done = true;
    }
    conv_strip<DIL><<<dim3((WW + 127) / 128, HH), 256, SMEM>>>(l);
}

template<int DIL>
static void launch_tap(int l) {
    static bool done = false;
    if (!done) {
        cudaFuncSetAttribute(conv_tap<DIL>, cudaFuncAttributeMaxDynamicSharedMemorySize, SMEM_TAP);
        done = true;
    }
    conv_tap<DIL><<<dim3((WW + 127) / 128, HH), 256, SMEM_TAP>>>(l);
}

extern "C" void kernel_launch(void* const* d_in, const int* in_sizes, int n_in,
                              void* d_out, int out_size) {
    const float* x      = (const float*)d_in[0];
    const float* dist   = (const float*)d_in[1];
    const float* w_in   = (const float*)d_in[2];
    const float* b_in   = (const float*)d_in[3];
    const float* w_dil  = (const float*)d_in[4];
    const float* b_dil  = (const float*)d_in[5];
    const float* gamma  = (const float*)d_in[6];
    const float* beta   = (const float*)d_in[7];
    const float* mean   = (const float*)d_in[8];
    const float* var    = (const float*)d_in[9];
    const float* w_out  = (const float*)d_in[10];
    const float* b_out  = (const float*)d_in[11];
    const float* w_head = (const float*)d_in[12];
    const float* b_head = (const float*)d_in[13];
    float* out = (float*)d_out;

    cudaFuncSetAttribute(pair_mma, cudaFuncAttributeMaxDynamicSharedMemorySize, SMEM_PAIR);

    prep_u<<<HH, C>>>(x, w_in);
    prep_dproj<<<MAXBIN + 1, C>>>(dist, w_in, b_in);
    prep_wx<<<HH, 256>>>(x, w_in);
    prep_fold<<<NL * 49, 256>>>(w_dil, gamma, var);
    prep_bias<<<NL, C>>>(b_dil, gamma, beta, mean, var);
    prep_weff<<<1, C>>>(w_out, b_out, w_head, b_head);

    pair_mma<<<dim3((WW + 127) / 128, HH), 256, SMEM_PAIR>>>();

    launch_conv2<1>(0);
    launch_conv2<2>(1);
    launch_conv2<4>(2);
    launch_conv<8>(3);
    launch_conv<16>(4);
    launch_conv<32>(5);
    launch_tap<64>(6);

    head_k<<<(NTRI + 255) / 256, 256>>>(out);
}

// round 15
// speedup vs baseline: 1.0374x; 1.0041x over previous
#include <cuda_runtime.h>
#include <cuda_bf16.h>
#include <cstdint>
#include <cstddef>

#define HH 600
#define WW 600
#define HWX (HH*WW)
#define C 64
#define E 256
#define NL 7
#define CROPV 50
#define NOUT 500
#define NTRI ((NOUT*(NOUT+1))/2)   // 125250
#define MAXBIN 100

__device__ __forceinline__ uint32_t smem_to_u32(const void* p) {
    uint32_t a;
    asm("{ .reg .u64 t; cvta.to.shared.u64 t, %1; cvt.u32.u64 %0, t; }" : "=r"(a) : "l"(p));
    return a;
}
__device__ __forceinline__ float bf2f(uint32_t u) {
    return __bfloat162float(__ushort_as_bfloat16((unsigned short)u));
}
__device__ __forceinline__ unsigned short f2bfu(float v) {
    return __bfloat16_as_ushort(__float2bfloat16_rn(v));
}

#define LDSM_X4(r0, r1, r2, r3, a) \
    asm volatile("ldmatrix.sync.aligned.m8n8.x4.shared.b16 {%0,%1,%2,%3}, [%4];" \
        : "=r"(r0), "=r"(r1), "=r"(r2), "=r"(r3) : "r"(a))
#define LDSM_X4_T(r0, r1, r2, r3, a) \
    asm volatile("ldmatrix.sync.aligned.m8n8.x4.trans.shared.b16 {%0,%1,%2,%3}, [%4];" \
        : "=r"(r0), "=r"(r1), "=r"(r2), "=r"(r3) : "r"(a))

__device__ __forceinline__ void mma16816(float* d, const uint32_t* a, uint32_t b0, uint32_t b1) {
    asm volatile("mma.sync.aligned.m16n8k16.row.col.f32.bf16.bf16.f32 "
        "{%0,%1,%2,%3}, {%4,%5,%6,%7}, {%8,%9}, {%0,%1,%2,%3};"
        : "+f"(d[0]), "+f"(d[1]), "+f"(d[2]), "+f"(d[3])
        : "r"(a[0]), "r"(a[1]), "r"(a[2]), "r"(a[3]), "r"(b0), "r"(b1));
}

__device__ __forceinline__ void cp16(uint32_t dst, const void* src, bool ok) {
    asm volatile("cp.async.cg.shared.global [%0], [%1], 16, %2;"
        :: "r"(dst), "l"(src), "r"(ok ? 16 : 0) : "memory");
}
#define CP_COMMIT() asm volatile("cp.async.commit_group;" ::: "memory")
#define CP_WAIT0()  asm volatile("cp.async.wait_group 0;" ::: "memory")

// ---------------- device buffers ----------------
__device__ __nv_bfloat16 g_Ahi[(size_t)HWX * C];
__device__ __nv_bfloat16 g_Alo[(size_t)HWX * C];
__device__ __nv_bfloat16 g_Bhi[(size_t)HWX * C];
__device__ __nv_bfloat16 g_Blo[(size_t)HWX * C];
__device__ __nv_bfloat16 g_whi[NL * 49 * C * C];   // [l][tap][ci][co]
__device__ __nv_bfloat16 g_wlo[NL * 49 * C * C];
__device__ __nv_bfloat16 g_xhi[HH * E];
__device__ __nv_bfloat16 g_xlo[HH * E];
__device__ __nv_bfloat16 g_wxhi[(size_t)HH * E * C];
__device__ __nv_bfloat16 g_wxlo[(size_t)HH * E * C];
__device__ float g_bf[NL * C];
__device__ float g_u[HH * C];
__device__ float g_dproj[(MAXBIN + 1) * C];
__device__ float g_weff[C + 1];

// ---------------- prep kernels ----------------
__global__ void prep_u(const float* __restrict__ x, const float* __restrict__ w_in) {
    int i = blockIdx.x, c = threadIdx.x;
    const float* xr = x + i * E;
    const float* wr = w_in + c * E;
    float s = 0.f;
    #pragma unroll 8
    for (int e = 0; e < E; e++) s += wr[e] * xr[e];
    g_u[i * C + c] = s;
}

__global__ void prep_dproj(const float* __restrict__ dist, const float* __restrict__ w_in,
                           const float* __restrict__ b_in) {
    int p = blockIdx.x, c = threadIdx.x;
    const float* dr = dist + p * E;
    const float* wr = w_in + c * E;
    float s = b_in[c];
    #pragma unroll 8
    for (int e = 0; e < E; e++) s += wr[e] * dr[e];
    g_dproj[p * C + c] = s;
}

// coalesced wx prep (fuses x hi/lo split): thread -> (e group, 8 consecutive c)
__global__ void prep_wx(const float* __restrict__ x, const float* __restrict__ w_in) {
    int i = blockIdx.x;
    int tid = threadIdx.x;
    int eg = tid >> 3;          // 0..31
    int c0 = (tid & 7) * 8;     // 0,8,..,56
    #pragma unroll
    for (int ee = 0; ee < 8; ee++) {
        int e = eg + ee * 32;
        float xie = x[i * E + e];
        if ((tid & 7) == 0) {
            unsigned short h = f2bfu(xie);
            g_xhi[i * E + e] = __ushort_as_bfloat16(h);
            g_xlo[i * E + e] = __float2bfloat16_rn(xie - bf2f(h));
        }
        size_t base = ((size_t)i * E + e) * C + c0;
        uint32_t hw[4], lw[4];
        #pragma unroll
        for (int k = 0; k < 4; k++) {
            float v0 = w_in[(c0 + 2 * k) * E + e] * xie;
            float v1 = w_in[(c0 + 2 * k + 1) * E + e] * xie;
            unsigned short h0 = f2bfu(v0), h1 = f2bfu(v1);
            unsigned short l0 = f2bfu(v0 - bf2f(h0)), l1 = f2bfu(v1 - bf2f(h1));
            hw[k] = (uint32_t)h0 | ((uint32_t)h1 << 16);
            lw[k] = (uint32_t)l0 | ((uint32_t)l1 << 16);
        }
        *(uint4*)(g_wxhi + base) = make_uint4(hw[0], hw[1], hw[2], hw[3]);
        *(uint4*)(g_wxlo + base) = make_uint4(lw[0], lw[1], lw[2], lw[3]);
    }
}

// smem-transposed fold: block = (l, ci); coalesced reads (tap runs) + coalesced writes (co runs)
__global__ void prep_fold(const float* __restrict__ w_dil, const float* __restrict__ gamma,
                          const float* __restrict__ var) {
    __shared__ float tile[64 * 49];
    __shared__ float sscale[64];
    int l = blockIdx.x >> 6;
    int ci = blockIdx.x & 63;
    int tid = threadIdx.x;
    const float* wsrc = w_dil + l * C * C * 49;

    // load: tile[co*49 + tap] = wsrc[(co*64+ci)*49 + tap]; contiguous 49-float runs
    #pragma unroll 1
    for (int idx = tid; idx < 64 * 49; idx += 256) {
        int co = idx / 49;
        int tap = idx - co * 49;
        tile[idx] = wsrc[(co * C + ci) * 49 + tap];
    }
    if (tid < 64)
        sscale[tid] = gamma[l * C + tid] * rsqrtf(var[l * C + tid] + 1e-5f);
    __syncthreads();

    // write: per (tap, co-pair); consecutive threads -> consecutive co pairs -> coalesced
    #pragma unroll 1
    for (int t = tid; t < 49 * 32; t += 256) {
        int tap = t >> 5;
        int co0 = (t & 31) * 2;
        float v0 = tile[co0 * 49 + tap] * sscale[co0];
        float v1 = tile[(co0 + 1) * 49 + tap] * sscale[co0 + 1];
        unsigned short h0 = f2bfu(v0), h1 = f2bfu(v1);
        unsigned short l0 = f2bfu(v0 - bf2f(h0)), l1 = f2bfu(v1 - bf2f(h1));
        size_t o = (size_t)(l * 49 + tap) * 4096 + ci * 64 + co0;
        *(uint32_t*)(g_whi + o) = (uint32_t)h0 | ((uint32_t)h1 << 16);
        *(uint32_t*)(g_wlo + o) = (uint32_t)l0 | ((uint32_t)l1 << 16);
    }
}

__global__ void prep_bias(const float* __restrict__ b_dil, const float* __restrict__ gamma,
                          const float* __restrict__ beta, const float* __restrict__ mean,
                          const float* __restrict__ var) {
    int l = blockIdx.x, c = threadIdx.x;
    float s = gamma[l * C + c] * rsqrtf(var[l * C + c] + 1e-5f);
    g_bf[l * C + c] = (b_dil[l * C + c] - mean[l * C + c]) * s + beta[l * C + c];
}

__global__ void prep_weff(const float* __restrict__ w_out, const float* __restrict__ b_out,
                          const float* __restrict__ w_head, const float* __restrict__ b_head) {
    int ci = threadIdx.x;
    float s = 0.f;
    for (int co = 0; co < C; co++) s += w_head[co] * w_out[co * C + ci];
    g_weff[ci] = s;
    if (ci == 0) {
        float b = b_head[0];
        for (int co = 0; co < C; co++) b += w_head[co] * b_out[co];
        g_weff[C] = b;
    }
}

// ---------------- pair via mma.sync ----------------
#define OFF_PAH(b) ((b) * 49152)
#define OFF_PAL(b) ((b) * 49152 + 16384)
#define OFF_PBH(b) ((b) * 49152 + 32768)
#define OFF_PBL(b) ((b) * 49152 + 40960)
#define SMEM_PAIR 98304

__global__ __launch_bounds__(256, 2) void pair_mma() {
    extern __shared__ char smem[];
    const uint32_t sb = smem_to_u32(smem);
    const int tid = threadIdx.x;
    const int wid = tid >> 5, lane = tid & 31;
    const int i = blockIdx.y;
    const int j0 = blockIdx.x * 128;

    int aRow[4], aCc[4]; uint32_t aOff[4];
    #pragma unroll
    for (int k = 0; k < 4; k++) {
        int chunk = tid + k * 256;
        aRow[k] = chunk >> 3;
        aCc[k] = chunk & 7;
        aOff[k] = (uint32_t)(aRow[k] * 128 + ((aCc[k] ^ (aRow[k] & 7)) << 4));
    }
    int bRow[2], bCc[2]; uint32_t bOff[2];
    #pragma unroll
    for (int k = 0; k < 2; k++) {
        int chunk = tid + k * 256;
        bRow[k] = chunk >> 3;
        bCc[k] = chunk & 7;
        bOff[k] = (uint32_t)(bRow[k] * 128 + ((bCc[k] ^ (bRow[k] & 7)) << 4));
    }

    const int row0 = wid * 16;
    const int quad = lane >> 3;
    const int rA = row0 + (lane & 7) + ((quad & 1) << 3);
    const int aChunkAdd = quad >> 1;
    const int rBbase = (lane & 7) + (((lane >> 3) & 1) << 3);
    const int bChunkAdd = lane >> 4;

    float acc[8][4] = {};

    {
        #pragma unroll
        for (int k = 0; k < 4; k++) {
            int j = j0 + aRow[k];
            bool ok = j < WW;
            size_t g = ok ? ((size_t)j * E + aCc[k] * 8) : 0;
            cp16(sb + OFF_PAH(0) + aOff[k], g_xhi + g, ok);
            cp16(sb + OFF_PAL(0) + aOff[k], g_xlo + g, ok);
        }
        size_t wb = ((size_t)i * E) * C;
        #pragma unroll
        for (int k = 0; k < 2; k++) {
            size_t g = wb + (size_t)bRow[k] * C + bCc[k] * 8;
            cp16(sb + OFF_PBH(0) + bOff[k], g_wxhi + g, true);
            cp16(sb + OFF_PBL(0) + bOff[k], g_wxlo + g, true);
        }
        CP_COMMIT();
        CP_WAIT0();
        __syncthreads();
    }

    #pragma unroll 1
    for (int ch = 0; ch < 4; ch++) {
        int buf = ch & 1;
        if (ch < 3) {
            int e0 = (ch + 1) * 64;
            int nb = buf ^ 1;
            #pragma unroll
            for (int k = 0; k < 4; k++) {
                int j = j0 + aRow[k];
                bool ok = j < WW;
                size_t g = ok ? ((size_t)j * E + e0 + aCc[k] * 8) : 0;
                cp16(sb + OFF_PAH(nb) + aOff[k], g_xhi + g, ok);
                cp16(sb + OFF_PAL(nb) + aOff[k], g_xlo + g, ok);
            }
            size_t wb = ((size_t)i * E + e0) * C;
            #pragma unroll
            for (int k = 0; k < 2; k++) {
                size_t g = wb + (size_t)bRow[k] * C + bCc[k] * 8;
                cp16(sb + OFF_PBH(nb) + bOff[k], g_wxhi + g, true);
                cp16(sb + OFF_PBL(nb) + bOff[k], g_wxlo + g, true);
            }
            CP_COMMIT();
        }

        const uint32_t pah = sb + OFF_PAH(buf);
        const uint32_t pal = sb + OFF_PAL(buf);
        const uint32_t pbh = sb + OFF_PBH(buf);
        const uint32_t pbl = sb + OFF_PBL(buf);
        #pragma unroll
        for (int ks = 0; ks < 4; ks++) {
            uint32_t ah[4], al[4];
            {
                int chunk = 2 * ks + aChunkAdd;
                uint32_t ao = (uint32_t)(rA * 128 + ((chunk ^ (rA & 7)) << 4));
                LDSM_X4(ah[0], ah[1], ah[2], ah[3], pah + ao);
                LDSM_X4(al[0], al[1], al[2], al[3], pal + ao);
            }
            int rB = rBbase + 16 * ks;
            #pragma unroll
            for (int p = 0; p < 4; p++) {
                int chunkB = 2 * p + bChunkAdd;
                uint32_t bo = (uint32_t)(rB * 128 + ((chunkB ^ (rB & 7)) << 4));
                uint32_t b0, b1, b2, b3;
                LDSM_X4_T(b0, b1, b2, b3, pbh + bo);
                mma16816(acc[2 * p],     ah, b0, b1);
                mma16816(acc[2 * p + 1], ah, b2, b3);
                mma16816(acc[2 * p],     al, b0, b1);
                mma16816(acc[2 * p + 1], al, b2, b3);
                LDSM_X4_T(b0, b1, b2, b3, pbl + bo);
                mma16816(acc[2 * p],     ah, b0, b1);
                mma16816(acc[2 * p + 1], ah, b2, b3);
            }
        }
        if (ch < 3) {
            CP_WAIT0();
            __syncthreads();
        }
    }

    int rtop = row0 + (lane >> 2);
    int cpair = (lane & 3) * 2;
    #pragma unroll
    for (int half = 0; half < 2; half++) {
        int j = j0 + rtop + half * 8;
        if (j < WW) {
            int pos = (i > j) ? (i - j) : (j - i);
            if (pos > MAXBIN) pos = MAXBIN;
            size_t prow = ((size_t)i * WW + j) * C;
            #pragma unroll
            for (int nt = 0; nt < 8; nt++) {
                int col = nt * 8 + cpair;
                float v0 = acc[nt][half * 2]     + 0.5f * (g_u[i * C + col]     + g_u[j * C + col])     + g_dproj[pos * C + col];
                float v1 = acc[nt][half * 2 + 1] + 0.5f * (g_u[i * C + col + 1] + g_u[j * C + col + 1]) + g_dproj[pos * C + col + 1];
                unsigned short h0 = f2bfu(v0), h1 = f2bfu(v1);
                unsigned short l0 = f2bfu(v0 - bf2f(h0)), l1 = f2bfu(v1 - bf2f(h1));
                *(uint32_t*)(g_Ahi + prow + col) = (uint32_t)h0 | ((uint32_t)h1 << 16);
                *(uint32_t*)(g_Alo + prow + col) = (uint32_t)l0 | ((uint32_t)l1 << 16);
            }
        }
    }
}

// ---------------- dilated conv (small dil): y-pair strip, DB W ----------------
#define OFF_BIAS 0
#define OFF_WB(b)  (256 + (b) * 16384)
#define OFF_S2     (256 + 32768)

template<int DIL>
__global__ __launch_bounds__(256, 2) void conv_strip2(int l) {
    constexpr int NR = ((128 + 6 * DIL) + 31) & ~31;

    extern __shared__ char smem[];
    const uint32_t sb = smem_to_u32(smem);
    const int tid = threadIdx.x;
    const int wid = tid >> 5, lane = tid & 31;
    const int y0 = blockIdx.y * 2;
    const int x0 = blockIdx.x * 128;

    const __nv_bfloat16* __restrict__ shi = (l & 1) ? g_Bhi : g_Ahi;
    const __nv_bfloat16* __restrict__ slo = (l & 1) ? g_Blo : g_Alo;
    __nv_bfloat16* __restrict__ dhi = (l & 1) ? g_Ahi : g_Bhi;
    __nv_bfloat16* __restrict__ dlo = (l & 1) ? g_Alo : g_Blo;
    const __nv_bfloat16* __restrict__ wh = g_whi + l * 49 * 4096;
    const __nv_bfloat16* __restrict__ wl = g_wlo + l * 49 * 4096;

    if (tid < C) ((float*)(smem + OFF_BIAS))[tid] = g_bf[l * C + tid];

    int wCi[2]; uint32_t wSo[2], wGo[2];
    #pragma unroll
    for (int k = 0; k < 2; k++) {
        int chunk = tid + k * 256;
        wCi[k] = chunk >> 3;
        int cc = chunk & 7;
        wGo[k] = (uint32_t)(wCi[k] * 64 + cc * 8);
        wSo[k] = (uint32_t)(wCi[k] * 128 + ((cc ^ (wCi[k] & 7)) << 4));
    }

    const int row0 = wid * 16;
    const int quad = lane >> 3;
    const int rA = row0 + (lane & 7) + ((quad & 1) << 3);
    const int aChunkAdd = quad >> 1;
    const int rBbase = (lane & 7) + (((lane >> 3) & 1) << 3);
    const int bChunkAdd = lane >> 4;

    float acc[2][8][4] = {};

    #pragma unroll 1
    for (int ky = 0; ky < 7; ky++) {
        #pragma unroll
        for (int s = 0; s < 2; s++) {
            int yy = y0 + s + (ky - 3) * DIL;
            bool yok = (yy >= 0) && (yy < HH);
            size_t rowbase = (size_t)yy * WW;
            uint32_t sbase = sb + OFF_S2 + s * (NR * 256);
            #pragma unroll 1
            for (int chunk = tid; chunk < NR * 8; chunk += 256) {
                int r = chunk >> 3;
                int cc = chunk & 7;
                int xg = x0 - 3 * DIL + r;
                bool ok = yok && (xg >= 0) && (xg < WW);
                size_t g = ok ? ((rowbase + xg) * C + cc * 8) : 0;
                uint32_t so = (uint32_t)(r * 128 + ((cc ^ (r & 7)) << 4));
                cp16(sbase + so, shi + g, ok);
                cp16(sbase + NR * 128 + so, slo + g, ok);
            }
        }
        {
            const __nv_bfloat16* wph = wh + (ky * 7) * 4096;
            const __nv_bfloat16* wpl = wl + (ky * 7) * 4096;
            #pragma unroll
            for (int k = 0; k < 2; k++) {
                cp16(sb + OFF_WB(0) + wSo[k],        wph + wGo[k], true);
                cp16(sb + OFF_WB(0) + 8192 + wSo[k], wpl + wGo[k], true);
            }
        }
        CP_COMMIT();
        CP_WAIT0();
        __syncthreads();

        #pragma unroll 1
        for (int kx = 0; kx < 7; kx++) {
            int buf = kx & 1;
            if (kx < 6) {
                const __nv_bfloat16* wph = wh + (ky * 7 + kx + 1) * 4096;
                const __nv_bfloat16* wpl = wl + (ky * 7 + kx + 1) * 4096;
                int nb = (kx + 1) & 1;
                #pragma unroll
                for (int k = 0; k < 2; k++) {
                    cp16(sb + OFF_WB(nb) + wSo[k],        wph + wGo[k], true);
                    cp16(sb + OFF_WB(nb) + 8192 + wSo[k], wpl + wGo[k], true);
                }
                CP_COMMIT();
            }
            const uint32_t wbh = sb + OFF_WB(buf);
            const uint32_t wbl = wbh + 8192;
            const int rowL = kx * DIL + rA;
            const uint32_t aoBase = (uint32_t)(rowL * 128);
            const int rpar = rowL & 7;
            const uint32_t s0h = sb + OFF_S2;
            const uint32_t s0l = s0h + NR * 128;
            const uint32_t s1h = s0h + NR * 256;
            const uint32_t s1l = s1h + NR * 128;

            #pragma unroll
            for (int ks = 0; ks < 4; ks++) {
                uint32_t ah0[4], al0[4], ah1[4], al1[4];
                {
                    int chunk = 2 * ks + aChunkAdd;
                    uint32_t ao = aoBase + ((uint32_t)(chunk ^ rpar) << 4);
                    LDSM_X4(ah0[0], ah0[1], ah0[2], ah0[3], s0h + ao);
                    LDSM_X4(al0[0], al0[1], al0[2], al0[3], s0l + ao);
                    LDSM_X4(ah1[0], ah1[1], ah1[2], ah1[3], s1h + ao);
                    LDSM_X4(al1[0], al1[1], al1[2], al1[3], s1l + ao);
                }
                int rB = rBbase + 16 * ks;
                #pragma unroll
                for (int p = 0; p < 4; p++) {
                    int chunkB = 2 * p + bChunkAdd;
                    uint32_t bo = (uint32_t)(rB * 128 + ((chunkB ^ (rB & 7)) << 4));
                    uint32_t b0, b1, b2, b3;
                    LDSM_X4_T(b0, b1, b2, b3, wbh + bo);
                    mma16816(acc[0][2 * p],     ah0, b0, b1);
                    mma16816(acc[0][2 * p + 1], ah0, b2, b3);
                    mma16816(acc[1][2 * p],     ah1, b0, b1);
                    mma16816(acc[1][2 * p + 1], ah1, b2, b3);
                    mma16816(acc[0][2 * p],     al0, b0, b1);
                    mma16816(acc[0][2 * p + 1], al0, b2, b3);
                    mma16816(acc[1][2 * p],     al1, b0, b1);
                    mma16816(acc[1][2 * p + 1], al1, b2, b3);
                    LDSM_X4_T(b0, b1, b2, b3, wbl + bo);
                    mma16816(acc[0][2 * p],     ah0, b0, b1);
                    mma16816(acc[0][2 * p + 1], ah0, b2, b3);
                    mma16816(acc[1][2 * p],     ah1, b0, b1);
                    mma16816(acc[1][2 * p + 1], ah1, b2, b3);
                }
            }
            if (kx < 6) {
                CP_WAIT0();
                __syncthreads();
            }
        }
        __syncthreads();
    }

    const float* sbias = (const float*)(smem + OFF_BIAS);
    int rtop = row0 + (lane >> 2);
    int cpair = (lane & 3) * 2;
    #pragma unroll
    for (int s = 0; s < 2; s++) {
        int y = y0 + s;
        #pragma unroll
        for (int half = 0; half < 2; half++) {
            int xg = x0 + rtop + half * 8;
            if (xg < WW) {
                size_t prow = ((size_t)y * WW + xg) * C;
                #pragma unroll
                for (int nt = 0; nt < 8; nt++) {
                    int col = nt * 8 + cpair;
                    size_t p = prow + col;
                    uint32_t rh = *(const uint32_t*)(shi + p);
                    uint32_t rl = *(const uint32_t*)(slo + p);
                    float v0 = acc[s][nt][half * 2]     + sbias[col]     + bf2f(rh & 0xffffu) + bf2f(rl & 0xffffu);
                    float v1 = acc[s][nt][half * 2 + 1] + sbias[col + 1] + bf2f(rh >> 16)     + bf2f(rl >> 16);
                    v0 = fmaxf(v0, 0.f); v1 = fmaxf(v1, 0.f);
                    unsigned short h0 = f2bfu(v0), h1 = f2bfu(v1);
                    unsigned short l0 = f2bfu(v0 - bf2f(h0)), l1 = f2bfu(v1 - bf2f(h1));
                    *(uint32_t*)(dhi + p) = (uint32_t)h0 | ((uint32_t)h1 << 16);
                    *(uint32_t*)(dlo + p) = (uint32_t)l0 | ((uint32_t)l1 << 16);
                }
            }
        }
    }
}

// ---------------- dilated conv (mid dil incl. 32): single-row strip, DB W ----------------
#define OFF_STRIP  (256 + 32768)

template<int DIL>
__global__ __launch_bounds__(256, 2) void conv_strip(int l) {
    constexpr int NR = ((128 + 6 * DIL) + 31) & ~31;
    constexpr int OFF_SH = OFF_STRIP;
    constexpr int OFF_SL = OFF_STRIP + NR * 128;

    extern __shared__ char smem[];
    const uint32_t sb = smem_to_u32(smem);
    const int tid = threadIdx.x;
    const int wid = tid >> 5, lane = tid & 31;
    const int y = blockIdx.y;
    const int x0 = blockIdx.x * 128;

    const __nv_bfloat16* __restrict__ shi = (l & 1) ? g_Bhi : g_Ahi;
    const __nv_bfloat16* __restrict__ slo = (l & 1) ? g_Blo : g_Alo;
    __nv_bfloat16* __restrict__ dhi = (l & 1) ? g_Ahi : g_Bhi;
    __nv_bfloat16* __restrict__ dlo = (l & 1) ? g_Alo : g_Blo;
    const __nv_bfloat16* __restrict__ wh = g_whi + l * 49 * 4096;
    const __nv_bfloat16* __restrict__ wl = g_wlo + l * 49 * 4096;

    if (tid < C) ((float*)(smem + OFF_BIAS))[tid] = g_bf[l * C + tid];

    int wCi[2]; uint32_t wSo[2], wGo[2];
    #pragma unroll
    for (int k = 0; k < 2; k++) {
        int chunk = tid + k * 256;
        wCi[k] = chunk >> 3;
        int cc = chunk & 7;
        wGo[k] = (uint32_t)(wCi[k] * 64 + cc * 8);
        wSo[k] = (uint32_t)(wCi[k] * 128 + ((cc ^ (wCi[k] & 7)) << 4));
    }

    const int row0 = wid * 16;
    const int quad = lane >> 3;
    const int rA = row0 + (lane & 7) + ((quad & 1) << 3);
    const int aChunkAdd = quad >> 1;
    const int rBbase = (lane & 7) + (((lane >> 3) & 1) << 3);
    const int bChunkAdd = lane >> 4;

    float acc[8][4] = {};

    #pragma unroll 1
    for (int ky = 0; ky < 7; ky++) {
        int yy = y + (ky - 3) * DIL;
        bool yok = (yy >= 0) && (yy < HH);
        size_t rowbase = (size_t)yy * WW;

        #pragma unroll 1
        for (int chunk = tid; chunk < NR * 8; chunk += 256) {
            int r = chunk >> 3;
            int cc = chunk & 7;
            int xg = x0 - 3 * DIL + r;
            bool ok = yok && (xg >= 0) && (xg < WW);
            size_t g = ok ? ((rowbase + xg) * C + cc * 8) : 0;
            uint32_t so = (uint32_t)(r * 128 + ((cc ^ (r & 7)) << 4));
            cp16(sb + OFF_SH + so, shi + g, ok);
            cp16(sb + OFF_SL + so, slo + g, ok);
        }
        {
            const __nv_bfloat16* wph = wh + (ky * 7) * 4096;
            const __nv_bfloat16* wpl = wl + (ky * 7) * 4096;
            #pragma unroll
            for (int k = 0; k < 2; k++) {
                cp16(sb + OFF_WB(0) + wSo[k],        wph + wGo[k], true);
                cp16(sb + OFF_WB(0) + 8192 + wSo[k], wpl + wGo[k], true);
            }
        }
        CP_COMMIT();
        CP_WAIT0();
        __syncthreads();

        #pragma unroll 1
        for (int kx = 0; kx < 7; kx++) {
            int buf = kx & 1;
            if (kx < 6) {
                const __nv_bfloat16* wph = wh + (ky * 7 + kx + 1) * 4096;
                const __nv_bfloat16* wpl = wl + (ky * 7 + kx + 1) * 4096;
                int nb = (kx + 1) & 1;
                #pragma unroll
                for (int k = 0; k < 2; k++) {
                    cp16(sb + OFF_WB(nb) + wSo[k],        wph + wGo[k], true);
                    cp16(sb + OFF_WB(nb) + 8192 + wSo[k], wpl + wGo[k], true);
                }
                CP_COMMIT();
            }
            const uint32_t wbh = sb + OFF_WB(buf);
            const uint32_t wbl = wbh + 8192;
            const int rowL = kx * DIL + rA;
            const uint32_t aoBase = (uint32_t)(rowL * 128);
            const int rpar = rowL & 7;

            #pragma unroll
            for (int ks = 0; ks < 4; ks++) {
                uint32_t ah[4], al[4];
                {
                    int chunk = 2 * ks + aChunkAdd;
                    uint32_t ao = aoBase + ((uint32_t)(chunk ^ rpar) << 4);
                    LDSM_X4(ah[0], ah[1], ah[2], ah[3], sb + OFF_SH + ao);
                    LDSM_X4(al[0], al[1], al[2], al[3], sb + OFF_SL + ao);
                }
                int rB = rBbase + 16 * ks;
                #pragma unroll
                for (int p = 0; p < 4; p++) {
                    int chunkB = 2 * p + bChunkAdd;
                    uint32_t bo = (uint32_t)(rB * 128 + ((chunkB ^ (rB & 7)) << 4));
                    uint32_t b0, b1, b2, b3;
                    LDSM_X4_T(b0, b1, b2, b3, wbh + bo);
                    mma16816(acc[2 * p],     ah, b0, b1);
                    mma16816(acc[2 * p + 1], ah, b2, b3);
                    mma16816(acc[2 * p],     al, b0, b1);
                    mma16816(acc[2 * p + 1], al, b2, b3);
                    LDSM_X4_T(b0, b1, b2, b3, wbl + bo);
                    mma16816(acc[2 * p],     ah, b0, b1);
                    mma16816(acc[2 * p + 1], ah, b2, b3);
                }
            }
            if (kx < 6) {
                CP_WAIT0();
                __syncthreads();
            }
        }
        __syncthreads();
    }

    const float* sbias = (const float*)(smem + OFF_BIAS);
    int rtop = row0 + (lane >> 2);
    int cpair = (lane & 3) * 2;
    #pragma unroll
    for (int half = 0; half < 2; half++) {
        int xg = x0 + rtop + half * 8;
        if (xg < WW) {
            size_t prow = ((size_t)y * WW + xg) * C;
            #pragma unroll
            for (int nt = 0; nt < 8; nt++) {
                int col = nt * 8 + cpair;
                size_t p = prow + col;
                uint32_t rh = *(const uint32_t*)(shi + p);
                uint32_t rl = *(const uint32_t*)(slo + p);
                float v0 = acc[nt][half * 2]     + sbias[col]     + bf2f(rh & 0xffffu) + bf2f(rl & 0xffffu);
                float v1 = acc[nt][half * 2 + 1] + sbias[col + 1] + bf2f(rh >> 16)     + bf2f(rl >> 16);
                v0 = fmaxf(v0, 0.f); v1 = fmaxf(v1, 0.f);
                unsigned short h0 = f2bfu(v0), h1 = f2bfu(v1);
                unsigned short l0 = f2bfu(v0 - bf2f(h0)), l1 = f2bfu(v1 - bf2f(h1));
                *(uint32_t*)(dhi + p) = (uint32_t)h0 | ((uint32_t)h1 << 16);
                *(uint32_t*)(dlo + p) = (uint32_t)l0 | ((uint32_t)l1 << 16);
            }
        }
    }
}

// ---------------- dilated conv (dil 64): per-tap double-buffered A+W ----------------
#define OT_BUF(b)  (256 + (b) * 49152)
#define SMEM_TAP   98560

template<int DIL>
__global__ __launch_bounds__(256, 2) void conv_tap(int l) {
    extern __shared__ char smem[];
    const uint32_t sb = smem_to_u32(smem);
    const int tid = threadIdx.x;
    const int wid = tid >> 5, lane = tid & 31;
    const int y = blockIdx.y;
    const int x0 = blockIdx.x * 128;

    const __nv_bfloat16* __restrict__ shi = (l & 1) ? g_Bhi : g_Ahi;
    const __nv_bfloat16* __restrict__ slo = (l & 1) ? g_Blo : g_Alo;
    __nv_bfloat16* __restrict__ dhi = (l & 1) ? g_Ahi : g_Bhi;
    __nv_bfloat16* __restrict__ dlo = (l & 1) ? g_Alo : g_Blo;
    const __nv_bfloat16* __restrict__ wh = g_whi + l * 49 * 4096;
    const __nv_bfloat16* __restrict__ wl = g_wlo + l * 49 * 4096;

    if (tid < C) ((float*)(smem))[tid] = g_bf[l * C + tid];

    int aRow[4], aCc[4]; uint32_t aOff[4];
    #pragma unroll
    for (int k = 0; k < 4; k++) {
        int chunk = tid + k * 256;
        aRow[k] = chunk >> 3;
        aCc[k] = chunk & 7;
        aOff[k] = (uint32_t)(aRow[k] * 128 + ((aCc[k] ^ (aRow[k] & 7)) << 4));
    }
    int wCi[2]; uint32_t wSo[2], wGo[2];
    #pragma unroll
    for (int k = 0; k < 2; k++) {
        int chunk = tid + k * 256;
        wCi[k] = chunk >> 3;
        int cc = chunk & 7;
        wGo[k] = (uint32_t)(wCi[k] * 64 + cc * 8);
        wSo[k] = (uint32_t)(wCi[k] * 128 + ((cc ^ (wCi[k] & 7)) << 4));
    }

    const int row0 = wid * 16;
    const int quad = lane >> 3;
    const int rA = row0 + (lane & 7) + ((quad & 1) << 3);
    const int aChunkAdd = quad >> 1;
    const int rBbase = (lane & 7) + (((lane >> 3) & 1) << 3);
    const int bChunkAdd = lane >> 4;
    const int rpar = rA & 7;
    const uint32_t aoBase = (uint32_t)(rA * 128);

    #define STAGE_TAP(TAP, BUF) do { \
        int _t = (TAP); \
        int _ky = _t / 7, _kx = _t - _ky * 7; \
        int _yy = y + (_ky - 3) * DIL; \
        bool _yok = (_yy >= 0) && (_yy < HH); \
        size_t _rb = (size_t)_yy * WW; \
        int _xs = x0 + (_kx - 3) * DIL; \
        uint32_t _ba = sb + OT_BUF(BUF); \
        _Pragma("unroll") \
        for (int _k = 0; _k < 4; _k++) { \
            int _xg = _xs + aRow[_k]; \
            bool _ok = _yok && (_xg >= 0) && (_xg < WW); \
            size_t _g = _ok ? ((_rb + _xg) * C + aCc[_k] * 8) : 0; \
            cp16(_ba + aOff[_k],         shi + _g, _ok); \
            cp16(_ba + 16384 + aOff[_k], slo + _g, _ok); \
        } \
        const __nv_bfloat16* _wph = wh + _t * 4096; \
        const __nv_bfloat16* _wpl = wl + _t * 4096; \
        _Pragma("unroll") \
        for (int _k = 0; _k < 2; _k++) { \
            cp16(_ba + 32768 + wSo[_k], _wph + wGo[_k], true); \
            cp16(_ba + 40960 + wSo[_k], _wpl + wGo[_k], true); \
        } \
    } while (0)

    float acc[8][4] = {};

    STAGE_TAP(0, 0);
    CP_COMMIT();
    CP_WAIT0();
    __syncthreads();

    #pragma unroll 1
    for (int tap = 0; tap < 49; ++tap) {
        int buf = tap & 1;
        if (tap < 48) {
            STAGE_TAP(tap + 1, buf ^ 1);
            CP_COMMIT();
        }
        const uint32_t pah = sb + OT_BUF(buf);
        const uint32_t pal = pah + 16384;
        const uint32_t wbh = pah + 32768;
        const uint32_t wbl = pah + 40960;

        #pragma unroll
        for (int ks = 0; ks < 4; ks++) {
            uint32_t ah[4], al[4];
            {
                int chunk = 2 * ks + aChunkAdd;
                uint32_t ao = aoBase + ((uint32_t)(chunk ^ rpar) << 4);
                LDSM_X4(ah[0], ah[1], ah[2], ah[3], pah + ao);
                LDSM_X4(al[0], al[1], al[2], al[3], pal + ao);
            }
            int rB = rBbase + 16 * ks;
            #pragma unroll
            for (int p = 0; p < 4; p++) {
                int chunkB = 2 * p + bChunkAdd;
                uint32_t bo = (uint32_t)(rB * 128 + ((chunkB ^ (rB & 7)) << 4));
                uint32_t b0, b1, b2, b3;
                LDSM_X4_T(b0, b1, b2, b3, wbh + bo);
                mma16816(acc[2 * p],     ah, b0, b1);
                mma16816(acc[2 * p + 1], ah, b2, b3);
                mma16816(acc[2 * p],     al, b0, b1);
                mma16816(acc[2 * p + 1], al, b2, b3);
                LDSM_X4_T(b0, b1, b2, b3, wbl + bo);
                mma16816(acc[2 * p],     ah, b0, b1);
                mma16816(acc[2 * p + 1], ah, b2, b3);
            }
        }
        if (tap < 48) {
            CP_WAIT0();
            __syncthreads();
        }
    }
    #undef STAGE_TAP

    const float* sbias = (const float*)(smem);
    int rtop = row0 + (lane >> 2);
    int cpair = (lane & 3) * 2;
    #pragma unroll
    for (int half = 0; half < 2; half++) {
        int xg = x0 + rtop + half * 8;
        if (xg < WW) {
            size_t prow = ((size_t)y * WW + xg) * C;
            #pragma unroll
            for (int nt = 0; nt < 8; nt++) {
                int col = nt * 8 + cpair;
                size_t p = prow + col;
                uint32_t rh = *(const uint32_t*)(shi + p);
                uint32_t rl = *(const uint32_t*)(slo + p);
                float v0 = acc[nt][half * 2]     + sbias[col]     + bf2f(rh & 0xffffu) + bf2f(rl & 0xffffu);
                float v1 = acc[nt][half * 2 + 1] + sbias[col + 1] + bf2f(rh >> 16)     + bf2f(rl >> 16);
                v0 = fmaxf(v0, 0.f); v1 = fmaxf(v1, 0.f);
                unsigned short h0 = f2bfu(v0), h1 = f2bfu(v1);
                unsigned short l0 = f2bfu(v0 - bf2f(h0)), l1 = f2bfu(v1 - bf2f(h1));
                *(uint32_t*)(dhi + p) = (uint32_t)h0 | ((uint32_t)h1 << 16);
                *(uint32_t*)(dlo + p) = (uint32_t)l0 | ((uint32_t)l1 << 16);
            }
        }
    }
}

// ---------------- head ----------------
__device__ __forceinline__ int tri_offs(int r) { return r * NOUT - (r * (r - 1)) / 2; }

__global__ void head_k(float* __restrict__ out) {
    int k = blockIdx.x * blockDim.x + threadIdx.x;
    if (k >= NTRI) return;
    float disc = (2.f * NOUT + 1.f) * (2.f * NOUT + 1.f) - 8.f * (float)k;
    int r = (int)(((2.f * NOUT + 1.f) - sqrtf(disc)) * 0.5f);
    if (r < 0) r = 0;
    if (r > NOUT - 1) r = NOUT - 1;
    while (r > 0 && tri_offs(r) > k) r--;
    while (r < NOUT - 1 && tri_offs(r + 1) <= k) r++;
    int c = r + (k - tri_offs(r));
    int yy = CROPV + r, xx = CROPV + c;
    size_t p = ((size_t)yy * WW + xx) * C;

    float s = g_weff[C];
    const uint4* rh = (const uint4*)(g_Bhi + p);
    const uint4* rl = (const uint4*)(g_Blo + p);
    #pragma unroll
    for (int q = 0; q < 8; q++) {
        uint4 vh = rh[q], vl = rl[q];
        uint32_t vhw[4] = {vh.x, vh.y, vh.z, vh.w};
        uint32_t vlw[4] = {vl.x, vl.y, vl.z, vl.w};
        #pragma unroll
        for (int e = 0; e < 4; e++) {
            int ci = q * 8 + e * 2;
            float h0 = bf2f(vhw[e] & 0xffffu) + bf2f(vlw[e] & 0xffffu);
            float h1 = bf2f(vhw[e] >> 16) + bf2f(vlw[e] >> 16);
            s = fmaf(h0, __ldg(&g_weff[ci]), s);
            s = fmaf(h1, __ldg(&g_weff[ci + 1]), s);
        }
    }
    out[k] = s;
}

// ------------------------------------------------------------------
template<int DIL>
static void launch_conv2(int l) {
    constexpr int NR = ((128 + 6 * DIL) + 31) & ~31;
    constexpr int SMEM = 256 + 32768 + 2 * NR * 256;
    static bool done = false;
    if (!done) {
        cudaFuncSetAttribute(conv_strip2<DIL>, cudaFuncAttributeMaxDynamicSharedMemorySize, SMEM);
        done = true;
    }
    conv_strip2<DIL><<<dim3((WW + 127) / 128, HH / 2), 256, SMEM>>>(l);
}

template<int DIL>
static void launch_conv(int l) {
    constexpr int NR = ((128 + 6 * DIL) + 31) & ~31;
    constexpr int SMEM = 256 + 32768 + NR * 256;
    static bool done = false;
    if (!done) {
        cudaFuncSetAttribute(conv_strip<DIL>, cudaFuncAttributeMaxDynamicSharedMemorySize, SMEM);
        done = true;
    }
    conv_strip<DIL><<<dim3((WW + 127) / 128, HH), 256, SMEM>>>(l);
}

template<int DIL>
static void launch_tap(int l) {
    static bool done = false;
    if (!done) {
        cudaFuncSetAttribute(conv_tap<DIL>, cudaFuncAttributeMaxDynamicSharedMemorySize, SMEM_TAP);
        done = true;
    }
    conv_tap<DIL><<<dim3((WW + 127) / 128, HH), 256, SMEM_TAP>>>(l);
}

extern "C" void kernel_launch(void* const* d_in, const int* in_sizes, int n_in,
                              void* d_out, int out_size) {
    const float* x      = (const float*)d_in[0];
    const float* dist   = (const float*)d_in[1];
    const float* w_in   = (const float*)d_in[2];
    const float* b_in   = (const float*)d_in[3];
    const float* w_dil  = (const float*)d_in[4];
    const float* b_dil  = (const float*)d_in[5];
    const float* gamma  = (const float*)d_in[6];
    const float* beta   = (const float*)d_in[7];
    const float* mean   = (const float*)d_in[8];
    const float* var    = (const float*)d_in[9];
    const float* w_out  = (const float*)d_in[10];
    const float* b_out  = (const float*)d_in[11];
    const float* w_head = (const float*)d_in[12];
    const float* b_head = (const float*)d_in[13];
    float* out = (float*)d_out;

    cudaFuncSetAttribute(pair_mma, cudaFuncAttributeMaxDynamicSharedMemorySize, SMEM_PAIR);

    prep_u<<<HH, C>>>(x, w_in);
    prep_dproj<<<MAXBIN + 1, C>>>(dist, w_in, b_in);
    prep_wx<<<HH, 256>>>(x, w_in);
    prep_fold<<<NL * 64, 256>>>(w_dil, gamma, var);
    prep_bias<<<NL, C>>>(b_dil, gamma, beta, mean, var);
    prep_weff<<<1, C>>>(w_out, b_out, w_head, b_head);

    pair_mma<<<dim3((WW + 127) / 128, HH), 256, SMEM_PAIR>>>();

    launch_conv2<1>(0);
    launch_conv2<2>(1);
    launch_conv2<4>(2);
    launch_conv<8>(3);
    launch_conv<16>(4);
    launch_conv<32>(5);
    launch_tap<64>(6);

    head_k<<<(NTRI + 255) / 256, 256>>>(out);
}

// round 16
// speedup vs baseline: 1.0403x; 1.0028x over previous
#include <cuda_runtime.h>
#include <cuda_bf16.h>
#include <cstdint>
#include <cstddef>

#define HH 600
#define WW 600
#define HWX (HH*WW)
#define C 64
#define E 256
#define NL 7
#define CROPV 50
#define NOUT 500
#define NTRI ((NOUT*(NOUT+1))/2)   // 125250
#define MAXBIN 100

__device__ __forceinline__ uint32_t smem_to_u32(const void* p) {
    uint32_t a;
    asm("{ .reg .u64 t; cvta.to.shared.u64 t, %1; cvt.u32.u64 %0, t; }" : "=r"(a) : "l"(p));
    return a;
}
__device__ __forceinline__ float bf2f(uint32_t u) {
    return __bfloat162float(__ushort_as_bfloat16((unsigned short)u));
}
__device__ __forceinline__ unsigned short f2bfu(float v) {
    return __bfloat16_as_ushort(__float2bfloat16_rn(v));
}

#define LDSM_X4(r0, r1, r2, r3, a) \
    asm volatile("ldmatrix.sync.aligned.m8n8.x4.shared.b16 {%0,%1,%2,%3}, [%4];" \
        : "=r"(r0), "=r"(r1), "=r"(r2), "=r"(r3) : "r"(a))
#define LDSM_X4_T(r0, r1, r2, r3, a) \
    asm volatile("ldmatrix.sync.aligned.m8n8.x4.trans.shared.b16 {%0,%1,%2,%3}, [%4];" \
        : "=r"(r0), "=r"(r1), "=r"(r2), "=r"(r3) : "r"(a))

__device__ __forceinline__ void mma16816(float* d, const uint32_t* a, uint32_t b0, uint32_t b1) {
    asm volatile("mma.sync.aligned.m16n8k16.row.col.f32.bf16.bf16.f32 "
        "{%0,%1,%2,%3}, {%4,%5,%6,%7}, {%8,%9}, {%0,%1,%2,%3};"
        : "+f"(d[0]), "+f"(d[1]), "+f"(d[2]), "+f"(d[3])
        : "r"(a[0]), "r"(a[1]), "r"(a[2]), "r"(a[3]), "r"(b0), "r"(b1));
}

__device__ __forceinline__ void cp16(uint32_t dst, const void* src, bool ok) {
    asm volatile("cp.async.cg.shared.global [%0], [%1], 16, %2;"
        :: "r"(dst), "l"(src), "r"(ok ? 16 : 0) : "memory");
}
#define CP_COMMIT() asm volatile("cp.async.commit_group;" ::: "memory")
#define CP_WAIT0()  asm volatile("cp.async.wait_group 0;" ::: "memory")

// ---------------- device buffers ----------------
__device__ __nv_bfloat16 g_Ahi[(size_t)HWX * C];
__device__ __nv_bfloat16 g_Alo[(size_t)HWX * C];
__device__ __nv_bfloat16 g_Bhi[(size_t)HWX * C];
__device__ __nv_bfloat16 g_Blo[(size_t)HWX * C];
__device__ __nv_bfloat16 g_whi[NL * 49 * C * C];   // [l][tap][ci][co]
__device__ __nv_bfloat16 g_wlo[NL * 49 * C * C];
__device__ __nv_bfloat16 g_xhi[HH * E];
__device__ __nv_bfloat16 g_xlo[HH * E];
__device__ __nv_bfloat16 g_wxhi[(size_t)HH * E * C];
__device__ __nv_bfloat16 g_wxlo[(size_t)HH * E * C];
__device__ float g_bf[NL * C];
__device__ float g_u[HH * C];
__device__ float g_dproj[(MAXBIN + 1) * C];
__device__ float g_weff[C + 1];

// ---------------- fused small prep: u / dproj / bias / weff ----------------
__global__ void prep_small(const float* __restrict__ x, const float* __restrict__ w_in,
                           const float* __restrict__ dist, const float* __restrict__ b_in,
                           const float* __restrict__ b_dil, const float* __restrict__ gamma,
                           const float* __restrict__ beta, const float* __restrict__ mean,
                           const float* __restrict__ var,
                           const float* __restrict__ w_out, const float* __restrict__ b_out,
                           const float* __restrict__ w_head, const float* __restrict__ b_head) {
    int b = blockIdx.x;
    int c = threadIdx.x;
    if (b < HH) {
        const float* xr = x + b * E;
        const float* wr = w_in + c * E;
        float s = 0.f;
        #pragma unroll 8
        for (int e = 0; e < E; e++) s += wr[e] * xr[e];
        g_u[b * C + c] = s;
    } else if (b < HH + MAXBIN + 1) {
        int p = b - HH;
        const float* dr = dist + p * E;
        const float* wr = w_in + c * E;
        float s = b_in[c];
        #pragma unroll 8
        for (int e = 0; e < E; e++) s += wr[e] * dr[e];
        g_dproj[p * C + c] = s;
    } else if (b < HH + MAXBIN + 1 + NL) {
        int l = b - (HH + MAXBIN + 1);
        float s = gamma[l * C + c] * rsqrtf(var[l * C + c] + 1e-5f);
        g_bf[l * C + c] = (b_dil[l * C + c] - mean[l * C + c]) * s + beta[l * C + c];
    } else {
        float s = 0.f;
        for (int co = 0; co < C; co++) s += w_head[co] * w_out[co * C + c];
        g_weff[c] = s;
        if (c == 0) {
            float bb = b_head[0];
            for (int co = 0; co < C; co++) bb += w_head[co] * b_out[co];
            g_weff[C] = bb;
        }
    }
}

// coalesced wx prep (fuses x hi/lo split): thread -> (e group, 8 consecutive c)
__global__ void prep_wx(const float* __restrict__ x, const float* __restrict__ w_in) {
    int i = blockIdx.x;
    int tid = threadIdx.x;
    int eg = tid >> 3;          // 0..31
    int c0 = (tid & 7) * 8;     // 0,8,..,56
    #pragma unroll
    for (int ee = 0; ee < 8; ee++) {
        int e = eg + ee * 32;
        float xie = x[i * E + e];
        if ((tid & 7) == 0) {
            unsigned short h = f2bfu(xie);
            g_xhi[i * E + e] = __ushort_as_bfloat16(h);
            g_xlo[i * E + e] = __float2bfloat16_rn(xie - bf2f(h));
        }
        size_t base = ((size_t)i * E + e) * C + c0;
        uint32_t hw[4], lw[4];
        #pragma unroll
        for (int k = 0; k < 4; k++) {
            float v0 = w_in[(c0 + 2 * k) * E + e] * xie;
            float v1 = w_in[(c0 + 2 * k + 1) * E + e] * xie;
            unsigned short h0 = f2bfu(v0), h1 = f2bfu(v1);
            unsigned short l0 = f2bfu(v0 - bf2f(h0)), l1 = f2bfu(v1 - bf2f(h1));
            hw[k] = (uint32_t)h0 | ((uint32_t)h1 << 16);
            lw[k] = (uint32_t)l0 | ((uint32_t)l1 << 16);
        }
        *(uint4*)(g_wxhi + base) = make_uint4(hw[0], hw[1], hw[2], hw[3]);
        *(uint4*)(g_wxlo + base) = make_uint4(lw[0], lw[1], lw[2], lw[3]);
    }
}

// smem-transposed fold
__global__ void prep_fold(const float* __restrict__ w_dil, const float* __restrict__ gamma,
                          const float* __restrict__ var) {
    __shared__ float tile[64 * 49];
    __shared__ float sscale[64];
    int l = blockIdx.x >> 6;
    int ci = blockIdx.x & 63;
    int tid = threadIdx.x;
    const float* wsrc = w_dil + l * C * C * 49;

    #pragma unroll 1
    for (int idx = tid; idx < 64 * 49; idx += 256) {
        int co = idx / 49;
        int tap = idx - co * 49;
        tile[idx] = wsrc[(co * C + ci) * 49 + tap];
    }
    if (tid < 64)
        sscale[tid] = gamma[l * C + tid] * rsqrtf(var[l * C + tid] + 1e-5f);
    __syncthreads();

    #pragma unroll 1
    for (int t = tid; t < 49 * 32; t += 256) {
        int tap = t >> 5;
        int co0 = (t & 31) * 2;
        float v0 = tile[co0 * 49 + tap] * sscale[co0];
        float v1 = tile[(co0 + 1) * 49 + tap] * sscale[co0 + 1];
        unsigned short h0 = f2bfu(v0), h1 = f2bfu(v1);
        unsigned short l0 = f2bfu(v0 - bf2f(h0)), l1 = f2bfu(v1 - bf2f(h1));
        size_t o = (size_t)(l * 49 + tap) * 4096 + ci * 64 + co0;
        *(uint32_t*)(g_whi + o) = (uint32_t)h0 | ((uint32_t)h1 << 16);
        *(uint32_t*)(g_wlo + o) = (uint32_t)l0 | ((uint32_t)l1 << 16);
    }
}

// ---------------- pair via mma.sync ----------------
#define OFF_PAH(b) ((b) * 49152)
#define OFF_PAL(b) ((b) * 49152 + 16384)
#define OFF_PBH(b) ((b) * 49152 + 32768)
#define OFF_PBL(b) ((b) * 49152 + 40960)
#define SMEM_PAIR 98304

__global__ __launch_bounds__(256, 2) void pair_mma() {
    extern __shared__ char smem[];
    const uint32_t sb = smem_to_u32(smem);
    const int tid = threadIdx.x;
    const int wid = tid >> 5, lane = tid & 31;
    const int i = blockIdx.y;
    const int j0 = blockIdx.x * 128;

    int aRow[4], aCc[4]; uint32_t aOff[4];
    #pragma unroll
    for (int k = 0; k < 4; k++) {
        int chunk = tid + k * 256;
        aRow[k] = chunk >> 3;
        aCc[k] = chunk & 7;
        aOff[k] = (uint32_t)(aRow[k] * 128 + ((aCc[k] ^ (aRow[k] & 7)) << 4));
    }
    int bRow[2], bCc[2]; uint32_t bOff[2];
    #pragma unroll
    for (int k = 0; k < 2; k++) {
        int chunk = tid + k * 256;
        bRow[k] = chunk >> 3;
        bCc[k] = chunk & 7;
        bOff[k] = (uint32_t)(bRow[k] * 128 + ((bCc[k] ^ (bRow[k] & 7)) << 4));
    }

    const int row0 = wid * 16;
    const int quad = lane >> 3;
    const int rA = row0 + (lane & 7) + ((quad & 1) << 3);
    const int aChunkAdd = quad >> 1;
    const int rBbase = (lane & 7) + (((lane >> 3) & 1) << 3);
    const int bChunkAdd = lane >> 4;

    float acc[8][4] = {};

    {
        #pragma unroll
        for (int k = 0; k < 4; k++) {
            int j = j0 + aRow[k];
            bool ok = j < WW;
            size_t g = ok ? ((size_t)j * E + aCc[k] * 8) : 0;
            cp16(sb + OFF_PAH(0) + aOff[k], g_xhi + g, ok);
            cp16(sb + OFF_PAL(0) + aOff[k], g_xlo + g, ok);
        }
        size_t wb = ((size_t)i * E) * C;
        #pragma unroll
        for (int k = 0; k < 2; k++) {
            size_t g = wb + (size_t)bRow[k] * C + bCc[k] * 8;
            cp16(sb + OFF_PBH(0) + bOff[k], g_wxhi + g, true);
            cp16(sb + OFF_PBL(0) + bOff[k], g_wxlo + g, true);
        }
        CP_COMMIT();
        CP_WAIT0();
        __syncthreads();
    }

    #pragma unroll 1
    for (int ch = 0; ch < 4; ch++) {
        int buf = ch & 1;
        if (ch < 3) {
            int e0 = (ch + 1) * 64;
            int nb = buf ^ 1;
            #pragma unroll
            for (int k = 0; k < 4; k++) {
                int j = j0 + aRow[k];
                bool ok = j < WW;
                size_t g = ok ? ((size_t)j * E + e0 + aCc[k] * 8) : 0;
                cp16(sb + OFF_PAH(nb) + aOff[k], g_xhi + g, ok);
                cp16(sb + OFF_PAL(nb) + aOff[k], g_xlo + g, ok);
            }
            size_t wb = ((size_t)i * E + e0) * C;
            #pragma unroll
            for (int k = 0; k < 2; k++) {
                size_t g = wb + (size_t)bRow[k] * C + bCc[k] * 8;
                cp16(sb + OFF_PBH(nb) + bOff[k], g_wxhi + g, true);
                cp16(sb + OFF_PBL(nb) + bOff[k], g_wxlo + g, true);
            }
            CP_COMMIT();
        }

        const uint32_t pah = sb + OFF_PAH(buf);
        const uint32_t pal = sb + OFF_PAL(buf);
        const uint32_t pbh = sb + OFF_PBH(buf);
        const uint32_t pbl = sb + OFF_PBL(buf);
        #pragma unroll
        for (int ks = 0; ks < 4; ks++) {
            uint32_t ah[4], al[4];
            {
                int chunk = 2 * ks + aChunkAdd;
                uint32_t ao = (uint32_t)(rA * 128 + ((chunk ^ (rA & 7)) << 4));
                LDSM_X4(ah[0], ah[1], ah[2], ah[3], pah + ao);
                LDSM_X4(al[0], al[1], al[2], al[3], pal + ao);
            }
            int rB = rBbase + 16 * ks;
            #pragma unroll
            for (int p = 0; p < 4; p++) {
                int chunkB = 2 * p + bChunkAdd;
                uint32_t bo = (uint32_t)(rB * 128 + ((chunkB ^ (rB & 7)) << 4));
                uint32_t b0, b1, b2, b3;
                LDSM_X4_T(b0, b1, b2, b3, pbh + bo);
                mma16816(acc[2 * p],     ah, b0, b1);
                mma16816(acc[2 * p + 1], ah, b2, b3);
                mma16816(acc[2 * p],     al, b0, b1);
                mma16816(acc[2 * p + 1], al, b2, b3);
                LDSM_X4_T(b0, b1, b2, b3, pbl + bo);
                mma16816(acc[2 * p],     ah, b0, b1);
                mma16816(acc[2 * p + 1], ah, b2, b3);
            }
        }
        if (ch < 3) {
            CP_WAIT0();
            __syncthreads();
        }
    }

    int rtop = row0 + (lane >> 2);
    int cpair = (lane & 3) * 2;
    #pragma unroll
    for (int half = 0; half < 2; half++) {
        int j = j0 + rtop + half * 8;
        if (j < WW) {
            int pos = (i > j) ? (i - j) : (j - i);
            if (pos > MAXBIN) pos = MAXBIN;
            size_t prow = ((size_t)i * WW + j) * C;
            #pragma unroll
            for (int nt = 0; nt < 8; nt++) {
                int col = nt * 8 + cpair;
                float v0 = acc[nt][half * 2]     + 0.5f * (g_u[i * C + col]     + g_u[j * C + col])     + g_dproj[pos * C + col];
                float v1 = acc[nt][half * 2 + 1] + 0.5f * (g_u[i * C + col + 1] + g_u[j * C + col + 1]) + g_dproj[pos * C + col + 1];
                unsigned short h0 = f2bfu(v0), h1 = f2bfu(v1);
                unsigned short l0 = f2bfu(v0 - bf2f(h0)), l1 = f2bfu(v1 - bf2f(h1));
                *(uint32_t*)(g_Ahi + prow + col) = (uint32_t)h0 | ((uint32_t)h1 << 16);
                *(uint32_t*)(g_Alo + prow + col) = (uint32_t)l0 | ((uint32_t)l1 << 16);
            }
        }
    }
}

// ---------------- dilated conv (small dil): y-pair strip, DB W ----------------
#define OFF_BIAS 0
#define OFF_WB(b)  (256 + (b) * 16384)
#define OFF_S2     (256 + 32768)

template<int DIL>
__global__ __launch_bounds__(256, 2) void conv_strip2(int l) {
    constexpr int NR = ((128 + 6 * DIL) + 31) & ~31;

    extern __shared__ char smem[];
    const uint32_t sb = smem_to_u32(smem);
    const int tid = threadIdx.x;
    const int wid = tid >> 5, lane = tid & 31;
    const int y0 = blockIdx.y * 2;
    const int x0 = blockIdx.x * 128;

    const __nv_bfloat16* __restrict__ shi = (l & 1) ? g_Bhi : g_Ahi;
    const __nv_bfloat16* __restrict__ slo = (l & 1) ? g_Blo : g_Alo;
    __nv_bfloat16* __restrict__ dhi = (l & 1) ? g_Ahi : g_Bhi;
    __nv_bfloat16* __restrict__ dlo = (l & 1) ? g_Alo : g_Blo;
    const __nv_bfloat16* __restrict__ wh = g_whi + l * 49 * 4096;
    const __nv_bfloat16* __restrict__ wl = g_wlo + l * 49 * 4096;

    if (tid < C) ((float*)(smem + OFF_BIAS))[tid] = g_bf[l * C + tid];

    int wCi[2]; uint32_t wSo[2], wGo[2];
    #pragma unroll
    for (int k = 0; k < 2; k++) {
        int chunk = tid + k * 256;
        wCi[k] = chunk >> 3;
        int cc = chunk & 7;
        wGo[k] = (uint32_t)(wCi[k] * 64 + cc * 8);
        wSo[k] = (uint32_t)(wCi[k] * 128 + ((cc ^ (wCi[k] & 7)) << 4));
    }

    const int row0 = wid * 16;
    const int quad = lane >> 3;
    const int rA = row0 + (lane & 7) + ((quad & 1) << 3);
    const int aChunkAdd = quad >> 1;
    const int rBbase = (lane & 7) + (((lane >> 3) & 1) << 3);
    const int bChunkAdd = lane >> 4;

    float acc[2][8][4] = {};

    #pragma unroll 1
    for (int ky = 0; ky < 7; ky++) {
        #pragma unroll
        for (int s = 0; s < 2; s++) {
            int yy = y0 + s + (ky - 3) * DIL;
            bool yok = (yy >= 0) && (yy < HH);
            size_t rowbase = (size_t)yy * WW;
            uint32_t sbase = sb + OFF_S2 + s * (NR * 256);
            #pragma unroll 1
            for (int chunk = tid; chunk < NR * 8; chunk += 256) {
                int r = chunk >> 3;
                int cc = chunk & 7;
                int xg = x0 - 3 * DIL + r;
                bool ok = yok && (xg >= 0) && (xg < WW);
                size_t g = ok ? ((rowbase + xg) * C + cc * 8) : 0;
                uint32_t so = (uint32_t)(r * 128 + ((cc ^ (r & 7)) << 4));
                cp16(sbase + so, shi + g, ok);
                cp16(sbase + NR * 128 + so, slo + g, ok);
            }
        }
        {
            const __nv_bfloat16* wph = wh + (ky * 7) * 4096;
            const __nv_bfloat16* wpl = wl + (ky * 7) * 4096;
            #pragma unroll
            for (int k = 0; k < 2; k++) {
                cp16(sb + OFF_WB(0) + wSo[k],        wph + wGo[k], true);
                cp16(sb + OFF_WB(0) + 8192 + wSo[k], wpl + wGo[k], true);
            }
        }
        CP_COMMIT();
        CP_WAIT0();
        __syncthreads();

        #pragma unroll 1
        for (int kx = 0; kx < 7; kx++) {
            int buf = kx & 1;
            if (kx < 6) {
                const __nv_bfloat16* wph = wh + (ky * 7 + kx + 1) * 4096;
                const __nv_bfloat16* wpl = wl + (ky * 7 + kx + 1) * 4096;
                int nb = (kx + 1) & 1;
                #pragma unroll
                for (int k = 0; k < 2; k++) {
                    cp16(sb + OFF_WB(nb) + wSo[k],        wph + wGo[k], true);
                    cp16(sb + OFF_WB(nb) + 8192 + wSo[k], wpl + wGo[k], true);
                }
                CP_COMMIT();
            }
            const uint32_t wbh = sb + OFF_WB(buf);
            const uint32_t wbl = wbh + 8192;
            const int rowL = kx * DIL + rA;
            const uint32_t aoBase = (uint32_t)(rowL * 128);
            const int rpar = rowL & 7;
            const uint32_t s0h = sb + OFF_S2;
            const uint32_t s0l = s0h + NR * 128;
            const uint32_t s1h = s0h + NR * 256;
            const uint32_t s1l = s1h + NR * 128;

            #pragma unroll
            for (int ks = 0; ks < 4; ks++) {
                uint32_t ah0[4], al0[4], ah1[4], al1[4];
                {
                    int chunk = 2 * ks + aChunkAdd;
                    uint32_t ao = aoBase + ((uint32_t)(chunk ^ rpar) << 4);
                    LDSM_X4(ah0[0], ah0[1], ah0[2], ah0[3], s0h + ao);
                    LDSM_X4(al0[0], al0[1], al0[2], al0[3], s0l + ao);
                    LDSM_X4(ah1[0], ah1[1], ah1[2], ah1[3], s1h + ao);
                    LDSM_X4(al1[0], al1[1], al1[2], al1[3], s1l + ao);
                }
                int rB = rBbase + 16 * ks;
                #pragma unroll
                for (int p = 0; p < 4; p++) {
                    int chunkB = 2 * p + bChunkAdd;
                    uint32_t bo = (uint32_t)(rB * 128 + ((chunkB ^ (rB & 7)) << 4));
                    uint32_t b0, b1, b2, b3;
                    LDSM_X4_T(b0, b1, b2, b3, wbh + bo);
                    mma16816(acc[0][2 * p],     ah0, b0, b1);
                    mma16816(acc[0][2 * p + 1], ah0, b2, b3);
                    mma16816(acc[1][2 * p],     ah1, b0, b1);
                    mma16816(acc[1][2 * p + 1], ah1, b2, b3);
                    mma16816(acc[0][2 * p],     al0, b0, b1);
                    mma16816(acc[0][2 * p + 1], al0, b2, b3);
                    mma16816(acc[1][2 * p],     al1, b0, b1);
                    mma16816(acc[1][2 * p + 1], al1, b2, b3);
                    LDSM_X4_T(b0, b1, b2, b3, wbl + bo);
                    mma16816(acc[0][2 * p],     ah0, b0, b1);
                    mma16816(acc[0][2 * p + 1], ah0, b2, b3);
                    mma16816(acc[1][2 * p],     ah1, b0, b1);
                    mma16816(acc[1][2 * p + 1], ah1, b2, b3);
                }
            }
            if (kx < 6) {
                CP_WAIT0();
                __syncthreads();
            }
        }
        __syncthreads();
    }

    const float* sbias = (const float*)(smem + OFF_BIAS);
    int rtop = row0 + (lane >> 2);
    int cpair = (lane & 3) * 2;
    #pragma unroll
    for (int s = 0; s < 2; s++) {
        int y = y0 + s;
        #pragma unroll
        for (int half = 0; half < 2; half++) {
            int xg = x0 + rtop + half * 8;
            if (xg < WW) {
                size_t prow = ((size_t)y * WW + xg) * C;
                #pragma unroll
                for (int nt = 0; nt < 8; nt++) {
                    int col = nt * 8 + cpair;
                    size_t p = prow + col;
                    uint32_t rh = *(const uint32_t*)(shi + p);
                    uint32_t rl = *(const uint32_t*)(slo + p);
                    float v0 = acc[s][nt][half * 2]     + sbias[col]     + bf2f(rh & 0xffffu) + bf2f(rl & 0xffffu);
                    float v1 = acc[s][nt][half * 2 + 1] + sbias[col + 1] + bf2f(rh >> 16)     + bf2f(rl >> 16);
                    v0 = fmaxf(v0, 0.f); v1 = fmaxf(v1, 0.f);
                    unsigned short h0 = f2bfu(v0), h1 = f2bfu(v1);
                    unsigned short l0 = f2bfu(v0 - bf2f(h0)), l1 = f2bfu(v1 - bf2f(h1));
                    *(uint32_t*)(dhi + p) = (uint32_t)h0 | ((uint32_t)h1 << 16);
                    *(uint32_t*)(dlo + p) = (uint32_t)l0 | ((uint32_t)l1 << 16);
                }
            }
        }
    }
}

// ---------------- dilated conv (mid dil incl. 32): single-row strip, DB W ----------------
#define OFF_STRIP  (256 + 32768)

template<int DIL>
__global__ __launch_bounds__(256, 2) void conv_strip(int l) {
    constexpr int NR = ((128 + 6 * DIL) + 31) & ~31;
    constexpr int OFF_SH = OFF_STRIP;
    constexpr int OFF_SL = OFF_STRIP + NR * 128;

    extern __shared__ char smem[];
    const uint32_t sb = smem_to_u32(smem);
    const int tid = threadIdx.x;
    const int wid = tid >> 5, lane = tid & 31;
    const int y = blockIdx.y;
    const int x0 = blockIdx.x * 128;

    const __nv_bfloat16* __restrict__ shi = (l & 1) ? g_Bhi : g_Ahi;
    const __nv_bfloat16* __restrict__ slo = (l & 1) ? g_Blo : g_Alo;
    __nv_bfloat16* __restrict__ dhi = (l & 1) ? g_Ahi : g_Bhi;
    __nv_bfloat16* __restrict__ dlo = (l & 1) ? g_Alo : g_Blo;
    const __nv_bfloat16* __restrict__ wh = g_whi + l * 49 * 4096;
    const __nv_bfloat16* __restrict__ wl = g_wlo + l * 49 * 4096;

    if (tid < C) ((float*)(smem + OFF_BIAS))[tid] = g_bf[l * C + tid];

    int wCi[2]; uint32_t wSo[2], wGo[2];
    #pragma unroll
    for (int k = 0; k < 2; k++) {
        int chunk = tid + k * 256;
        wCi[k] = chunk >> 3;
        int cc = chunk & 7;
        wGo[k] = (uint32_t)(wCi[k] * 64 + cc * 8);
        wSo[k] = (uint32_t)(wCi[k] * 128 + ((cc ^ (wCi[k] & 7)) << 4));
    }

    const int row0 = wid * 16;
    const int quad = lane >> 3;
    const int rA = row0 + (lane & 7) + ((quad & 1) << 3);
    const int aChunkAdd = quad >> 1;
    const int rBbase = (lane & 7) + (((lane >> 3) & 1) << 3);
    const int bChunkAdd = lane >> 4;

    float acc[8][4] = {};

    #pragma unroll 1
    for (int ky = 0; ky < 7; ky++) {
        int yy = y + (ky - 3) * DIL;
        bool yok = (yy >= 0) && (yy < HH);
        size_t rowbase = (size_t)yy * WW;

        #pragma unroll 1
        for (int chunk = tid; chunk < NR * 8; chunk += 256) {
            int r = chunk >> 3;
            int cc = chunk & 7;
            int xg = x0 - 3 * DIL + r;
            bool ok = yok && (xg >= 0) && (xg < WW);
            size_t g = ok ? ((rowbase + xg) * C + cc * 8) : 0;
            uint32_t so = (uint32_t)(r * 128 + ((cc ^ (r & 7)) << 4));
            cp16(sb + OFF_SH + so, shi + g, ok);
            cp16(sb + OFF_SL + so, slo + g, ok);
        }
        {
            const __nv_bfloat16* wph = wh + (ky * 7) * 4096;
            const __nv_bfloat16* wpl = wl + (ky * 7) * 4096;
            #pragma unroll
            for (int k = 0; k < 2; k++) {
                cp16(sb + OFF_WB(0) + wSo[k],        wph + wGo[k], true);
                cp16(sb + OFF_WB(0) + 8192 + wSo[k], wpl + wGo[k], true);
            }
        }
        CP_COMMIT();
        CP_WAIT0();
        __syncthreads();

        #pragma unroll 1
        for (int kx = 0; kx < 7; kx++) {
            int buf = kx & 1;
            if (kx < 6) {
                const __nv_bfloat16* wph = wh + (ky * 7 + kx + 1) * 4096;
                const __nv_bfloat16* wpl = wl + (ky * 7 + kx + 1) * 4096;
                int nb = (kx + 1) & 1;
                #pragma unroll
                for (int k = 0; k < 2; k++) {
                    cp16(sb + OFF_WB(nb) + wSo[k],        wph + wGo[k], true);
                    cp16(sb + OFF_WB(nb) + 8192 + wSo[k], wpl + wGo[k], true);
                }
                CP_COMMIT();
            }
            const uint32_t wbh = sb + OFF_WB(buf);
            const uint32_t wbl = wbh + 8192;
            const int rowL = kx * DIL + rA;
            const uint32_t aoBase = (uint32_t)(rowL * 128);
            const int rpar = rowL & 7;

            #pragma unroll
            for (int ks = 0; ks < 4; ks++) {
                uint32_t ah[4], al[4];
                {
                    int chunk = 2 * ks + aChunkAdd;
                    uint32_t ao = aoBase + ((uint32_t)(chunk ^ rpar) << 4);
                    LDSM_X4(ah[0], ah[1], ah[2], ah[3], sb + OFF_SH + ao);
                    LDSM_X4(al[0], al[1], al[2], al[3], sb + OFF_SL + ao);
                }
                int rB = rBbase + 16 * ks;
                #pragma unroll
                for (int p = 0; p < 4; p++) {
                    int chunkB = 2 * p + bChunkAdd;
                    uint32_t bo = (uint32_t)(rB * 128 + ((chunkB ^ (rB & 7)) << 4));
                    uint32_t b0, b1, b2, b3;
                    LDSM_X4_T(b0, b1, b2, b3, wbh + bo);
                    mma16816(acc[2 * p],     ah, b0, b1);
                    mma16816(acc[2 * p + 1], ah, b2, b3);
                    mma16816(acc[2 * p],     al, b0, b1);
                    mma16816(acc[2 * p + 1], al, b2, b3);
                    LDSM_X4_T(b0, b1, b2, b3, wbl + bo);
                    mma16816(acc[2 * p],     ah, b0, b1);
                    mma16816(acc[2 * p + 1], ah, b2, b3);
                }
            }
            if (kx < 6) {
                CP_WAIT0();
                __syncthreads();
            }
        }
        __syncthreads();
    }

    const float* sbias = (const float*)(smem + OFF_BIAS);
    int rtop = row0 + (lane >> 2);
    int cpair = (lane & 3) * 2;
    #pragma unroll
    for (int half = 0; half < 2; half++) {
        int xg = x0 + rtop + half * 8;
        if (xg < WW) {
            size_t prow = ((size_t)y * WW + xg) * C;
            #pragma unroll
            for (int nt = 0; nt < 8; nt++) {
                int col = nt * 8 + cpair;
                size_t p = prow + col;
                uint32_t rh = *(const uint32_t*)(shi + p);
                uint32_t rl = *(const uint32_t*)(slo + p);
                float v0 = acc[nt][half * 2]     + sbias[col]     + bf2f(rh & 0xffffu) + bf2f(rl & 0xffffu);
                float v1 = acc[nt][half * 2 + 1] + sbias[col + 1] + bf2f(rh >> 16)     + bf2f(rl >> 16);
                v0 = fmaxf(v0, 0.f); v1 = fmaxf(v1, 0.f);
                unsigned short h0 = f2bfu(v0), h1 = f2bfu(v1);
                unsigned short l0 = f2bfu(v0 - bf2f(h0)), l1 = f2bfu(v1 - bf2f(h1));
                *(uint32_t*)(dhi + p) = (uint32_t)h0 | ((uint32_t)h1 << 16);
                *(uint32_t*)(dlo + p) = (uint32_t)l0 | ((uint32_t)l1 << 16);
            }
        }
    }
}

// ---------------- dilated conv (dil 64): per-tap double-buffered A+W ----------------
#define OT_BUF(b)  (256 + (b) * 49152)
#define SMEM_TAP   98560

template<int DIL>
__global__ __launch_bounds__(256, 2) void conv_tap(int l) {
    extern __shared__ char smem[];
    const uint32_t sb = smem_to_u32(smem);
    const int tid = threadIdx.x;
    const int wid = tid >> 5, lane = tid & 31;
    const int y = blockIdx.y;
    const int x0 = blockIdx.x * 128;

    const __nv_bfloat16* __restrict__ shi = (l & 1) ? g_Bhi : g_Ahi;
    const __nv_bfloat16* __restrict__ slo = (l & 1) ? g_Blo : g_Alo;
    __nv_bfloat16* __restrict__ dhi = (l & 1) ? g_Ahi : g_Bhi;
    __nv_bfloat16* __restrict__ dlo = (l & 1) ? g_Alo : g_Blo;
    const __nv_bfloat16* __restrict__ wh = g_whi + l * 49 * 4096;
    const __nv_bfloat16* __restrict__ wl = g_wlo + l * 49 * 4096;

    if (tid < C) ((float*)(smem))[tid] = g_bf[l * C + tid];

    int aRow[4], aCc[4]; uint32_t aOff[4];
    #pragma unroll
    for (int k = 0; k < 4; k++) {
        int chunk = tid + k * 256;
        aRow[k] = chunk >> 3;
        aCc[k] = chunk & 7;
        aOff[k] = (uint32_t)(aRow[k] * 128 + ((aCc[k] ^ (aRow[k] & 7)) << 4));
    }
    int wCi[2]; uint32_t wSo[2], wGo[2];
    #pragma unroll
    for (int k = 0; k < 2; k++) {
        int chunk = tid + k * 256;
        wCi[k] = chunk >> 3;
        int cc = chunk & 7;
        wGo[k] = (uint32_t)(wCi[k] * 64 + cc * 8);
        wSo[k] = (uint32_t)(wCi[k] * 128 + ((cc ^ (wCi[k] & 7)) << 4));
    }

    const int row0 = wid * 16;
    const int quad = lane >> 3;
    const int rA = row0 + (lane & 7) + ((quad & 1) << 3);
    const int aChunkAdd = quad >> 1;
    const int rBbase = (lane & 7) + (((lane >> 3) & 1) << 3);
    const int bChunkAdd = lane >> 4;
    const int rpar = rA & 7;
    const uint32_t aoBase = (uint32_t)(rA * 128);

    #define STAGE_TAP(TAP, BUF) do { \
        int _t = (TAP); \
        int _ky = _t / 7, _kx = _t - _ky * 7; \
        int _yy = y + (_ky - 3) * DIL; \
        bool _yok = (_yy >= 0) && (_yy < HH); \
        size_t _rb = (size_t)_yy * WW; \
        int _xs = x0 + (_kx - 3) * DIL; \
        uint32_t _ba = sb + OT_BUF(BUF); \
        _Pragma("unroll") \
        for (int _k = 0; _k < 4; _k++) { \
            int _xg = _xs + aRow[_k]; \
            bool _ok = _yok && (_xg >= 0) && (_xg < WW); \
            size_t _g = _ok ? ((_rb + _xg) * C + aCc[_k] * 8) : 0; \
            cp16(_ba + aOff[_k],         shi + _g, _ok); \
            cp16(_ba + 16384 + aOff[_k], slo + _g, _ok); \
        } \
        const __nv_bfloat16* _wph = wh + _t * 4096; \
        const __nv_bfloat16* _wpl = wl + _t * 4096; \
        _Pragma("unroll") \
        for (int _k = 0; _k < 2; _k++) { \
            cp16(_ba + 32768 + wSo[_k], _wph + wGo[_k], true); \
            cp16(_ba + 40960 + wSo[_k], _wpl + wGo[_k], true); \
        } \
    } while (0)

    float acc[8][4] = {};

    STAGE_TAP(0, 0);
    CP_COMMIT();
    CP_WAIT0();
    __syncthreads();

    #pragma unroll 1
    for (int tap = 0; tap < 49; ++tap) {
        int buf = tap & 1;
        if (tap < 48) {
            STAGE_TAP(tap + 1, buf ^ 1);
            CP_COMMIT();
        }
        const uint32_t pah = sb + OT_BUF(buf);
        const uint32_t pal = pah + 16384;
        const uint32_t wbh = pah + 32768;
        const uint32_t wbl = pah + 40960;

        #pragma unroll
        for (int ks = 0; ks < 4; ks++) {
            uint32_t ah[4], al[4];
            {
                int chunk = 2 * ks + aChunkAdd;
                uint32_t ao = aoBase + ((uint32_t)(chunk ^ rpar) << 4);
                LDSM_X4(ah[0], ah[1], ah[2], ah[3], pah + ao);
                LDSM_X4(al[0], al[1], al[2], al[3], pal + ao);
            }
            int rB = rBbase + 16 * ks;
            #pragma unroll
            for (int p = 0; p < 4; p++) {
                int chunkB = 2 * p + bChunkAdd;
                uint32_t bo = (uint32_t)(rB * 128 + ((chunkB ^ (rB & 7)) << 4));
                uint32_t b0, b1, b2, b3;
                LDSM_X4_T(b0, b1, b2, b3, wbh + bo);
                mma16816(acc[2 * p],     ah, b0, b1);
                mma16816(acc[2 * p + 1], ah, b2, b3);
                mma16816(acc[2 * p],     al, b0, b1);
                mma16816(acc[2 * p + 1], al, b2, b3);
                LDSM_X4_T(b0, b1, b2, b3, wbl + bo);
                mma16816(acc[2 * p],     ah, b0, b1);
                mma16816(acc[2 * p + 1], ah, b2, b3);
            }
        }
        if (tap < 48) {
            CP_WAIT0();
            __syncthreads();
        }
    }
    #undef STAGE_TAP

    const float* sbias = (const float*)(smem);
    int rtop = row0 + (lane >> 2);
    int cpair = (lane & 3) * 2;
    #pragma unroll
    for (int half = 0; half < 2; half++) {
        int xg = x0 + rtop + half * 8;
        if (xg < WW) {
            size_t prow = ((size_t)y * WW + xg) * C;
            #pragma unroll
            for (int nt = 0; nt < 8; nt++) {
                int col = nt * 8 + cpair;
                size_t p = prow + col;
                uint32_t rh = *(const uint32_t*)(shi + p);
                uint32_t rl = *(const uint32_t*)(slo + p);
                float v0 = acc[nt][half * 2]     + sbias[col]     + bf2f(rh & 0xffffu) + bf2f(rl & 0xffffu);
                float v1 = acc[nt][half * 2 + 1] + sbias[col + 1] + bf2f(rh >> 16)     + bf2f(rl >> 16);
                v0 = fmaxf(v0, 0.f); v1 = fmaxf(v1, 0.f);
                unsigned short h0 = f2bfu(v0), h1 = f2bfu(v1);
                unsigned short l0 = f2bfu(v0 - bf2f(h0)), l1 = f2bfu(v1 - bf2f(h1));
                *(uint32_t*)(dhi + p) = (uint32_t)h0 | ((uint32_t)h1 << 16);
                *(uint32_t*)(dlo + p) = (uint32_t)l0 | ((uint32_t)l1 << 16);
            }
        }
    }
}

// ---------------- head ----------------
__device__ __forceinline__ int tri_offs(int r) { return r * NOUT - (r * (r - 1)) / 2; }

__global__ void head_k(float* __restrict__ out) {
    int k = blockIdx.x * blockDim.x + threadIdx.x;
    if (k >= NTRI) return;
    float disc = (2.f * NOUT + 1.f) * (2.f * NOUT + 1.f) - 8.f * (float)k;
    int r = (int)(((2.f * NOUT + 1.f) - sqrtf(disc)) * 0.5f);
    if (r < 0) r = 0;
    if (r > NOUT - 1) r = NOUT - 1;
    while (r > 0 && tri_offs(r) > k) r--;
    while (r < NOUT - 1 && tri_offs(r + 1) <= k) r++;
    int c = r + (k - tri_offs(r));
    int yy = CROPV + r, xx = CROPV + c;
    size_t p = ((size_t)yy * WW + xx) * C;

    float s = g_weff[C];
    const uint4* rh = (const uint4*)(g_Bhi + p);
    const uint4* rl = (const uint4*)(g_Blo + p);
    #pragma unroll
    for (int q = 0; q < 8; q++) {
        uint4 vh = rh[q], vl = rl[q];
        uint32_t vhw[4] = {vh.x, vh.y, vh.z, vh.w};
        uint32_t vlw[4] = {vl.x, vl.y, vl.z, vl.w};
        #pragma unroll
        for (int e = 0; e < 4; e++) {
            int ci = q * 8 + e * 2;
            float h0 = bf2f(vhw[e] & 0xffffu) + bf2f(vlw[e] & 0xffffu);
            float h1 = bf2f(vhw[e] >> 16) + bf2f(vlw[e] >> 16);
            s = fmaf(h0, __ldg(&g_weff[ci]), s);
            s = fmaf(h1, __ldg(&g_weff[ci + 1]), s);
        }
    }
    out[k] = s;
}

// ------------------------------------------------------------------
template<int DIL>
static void launch_conv2(int l) {
    constexpr int NR = ((128 + 6 * DIL) + 31) & ~31;
    constexpr int SMEM = 256 + 32768 + 2 * NR * 256;
    static bool done = false;
    if (!done) {
        cudaFuncSetAttribute(conv_strip2<DIL>, cudaFuncAttributeMaxDynamicSharedMemorySize, SMEM);
        done = true;
    }
    conv_strip2<DIL><<<dim3((WW + 127) / 128, HH / 2), 256, SMEM>>>(l);
}

template<int DIL>
static void launch_conv(int l) {
    constexpr int NR = ((128 + 6 * DIL) + 31) & ~31;
    constexpr int SMEM = 256 + 32768 + NR * 256;
    static bool done = false;
    if (!done) {
        cudaFuncSetAttribute(conv_strip<DIL>, cudaFuncAttributeMaxDynamicSharedMemorySize, SMEM);
        done = true;
    }
    conv_strip<DIL><<<dim3((WW + 127) / 128, HH), 256, SMEM>>>(l);
}

template<int DIL>
static void launch_tap(int l) {
    static bool done = false;
    if (!done) {
        cudaFuncSetAttribute(conv_tap<DIL>, cudaFuncAttributeMaxDynamicSharedMemorySize, SMEM_TAP);
        done = true;
    }
    conv_tap<DIL><<<dim3((WW + 127) / 128, HH), 256, SMEM_TAP>>>(l);
}

extern "C" void kernel_launch(void* const* d_in, const int* in_sizes, int n_in,
                              void* d_out, int out_size) {
    const float* x      = (const float*)d_in[0];
    const float* dist   = (const float*)d_in[1];
    const float* w_in   = (const float*)d_in[2];
    const float* b_in   = (const float*)d_in[3];
    const float* w_dil  = (const float*)d_in[4];
    const float* b_dil  = (const float*)d_in[5];
    const float* gamma  = (const float*)d_in[6];
    const float* beta   = (const float*)d_in[7];
    const float* mean   = (const float*)d_in[8];
    const float* var    = (const float*)d_in[9];
    const float* w_out  = (const float*)d_in[10];
    const float* b_out  = (const float*)d_in[11];
    const float* w_head = (const float*)d_in[12];
    const float* b_head = (const float*)d_in[13];
    float* out = (float*)d_out;

    cudaFuncSetAttribute(pair_mma, cudaFuncAttributeMaxDynamicSharedMemorySize, SMEM_PAIR);

    prep_small<<<HH + MAXBIN + 1 + NL + 1, C>>>(x, w_in, dist, b_in, b_dil, gamma, beta,
                                                mean, var, w_out, b_out, w_head, b_head);
    prep_wx<<<HH, 256>>>(x, w_in);
    prep_fold<<<NL * 64, 256>>>(w_dil, gamma, var);

    pair_mma<<<dim3((WW + 127) / 128, HH), 256, SMEM_PAIR>>>();

    launch_conv2<1>(0);
    launch_conv2<2>(1);
    launch_conv2<4>(2);
    launch_conv<8>(3);
    launch_conv<16>(4);
    launch_conv<32>(5);
    launch_tap<64>(6);

    head_k<<<(NTRI + 255) / 256, 256>>>(out);
}

// round 17
// speedup vs baseline: 1.0458x; 1.0052x over previous
#include <cuda_runtime.h>
#include <cuda_bf16.h>
#include <cstdint>
#include <cstddef>

#define HH 600
#define WW 600
#define HWX (HH*WW)
#define C 64
#define E 256
#define NL 7
#define CROPV 50
#define NOUT 500
#define NTRI ((NOUT*(NOUT+1))/2)   // 125250
#define MAXBIN 100

__device__ __forceinline__ uint32_t smem_to_u32(const void* p) {
    uint32_t a;
    asm("{ .reg .u64 t; cvta.to.shared.u64 t, %1; cvt.u32.u64 %0, t; }" : "=r"(a) : "l"(p));
    return a;
}
__device__ __forceinline__ float bf2f(uint32_t u) {
    return __bfloat162float(__ushort_as_bfloat16((unsigned short)u));
}
__device__ __forceinline__ unsigned short f2bfu(float v) {
    return __bfloat16_as_ushort(__float2bfloat16_rn(v));
}

#define LDSM_X4(r0, r1, r2, r3, a) \
    asm volatile("ldmatrix.sync.aligned.m8n8.x4.shared.b16 {%0,%1,%2,%3}, [%4];" \
        : "=r"(r0), "=r"(r1), "=r"(r2), "=r"(r3) : "r"(a))
#define LDSM_X4_T(r0, r1, r2, r3, a) \
    asm volatile("ldmatrix.sync.aligned.m8n8.x4.trans.shared.b16 {%0,%1,%2,%3}, [%4];" \
        : "=r"(r0), "=r"(r1), "=r"(r2), "=r"(r3) : "r"(a))

__device__ __forceinline__ void mma16816(float* d, const uint32_t* a, uint32_t b0, uint32_t b1) {
    asm volatile("mma.sync.aligned.m16n8k16.row.col.f32.bf16.bf16.f32 "
        "{%0,%1,%2,%3}, {%4,%5,%6,%7}, {%8,%9}, {%0,%1,%2,%3};"
        : "+f"(d[0]), "+f"(d[1]), "+f"(d[2]), "+f"(d[3])
        : "r"(a[0]), "r"(a[1]), "r"(a[2]), "r"(a[3]), "r"(b0), "r"(b1));
}

__device__ __forceinline__ void cp16(uint32_t dst, const void* src, bool ok) {
    asm volatile("cp.async.cg.shared.global [%0], [%1], 16, %2;"
        :: "r"(dst), "l"(src), "r"(ok ? 16 : 0) : "memory");
}
#define CP_COMMIT() asm volatile("cp.async.commit_group;" ::: "memory")
#define CP_WAIT0()  asm volatile("cp.async.wait_group 0;" ::: "memory")

// ---------------- device buffers ----------------
__device__ __nv_bfloat16 g_Ahi[(size_t)HWX * C];
__device__ __nv_bfloat16 g_Alo[(size_t)HWX * C];
__device__ __nv_bfloat16 g_Bhi[(size_t)HWX * C];
__device__ __nv_bfloat16 g_Blo[(size_t)HWX * C];
__device__ __nv_bfloat16 g_whi[NL * 49 * C * C];   // [l][tap][ci][co]
__device__ __nv_bfloat16 g_wlo[NL * 49 * C * C];
__device__ __nv_bfloat16 g_xhi[HH * E];
__device__ __nv_bfloat16 g_xlo[HH * E];
__device__ __nv_bfloat16 g_wxhi[(size_t)HH * E * C];
__device__ __nv_bfloat16 g_wxlo[(size_t)HH * E * C];
__device__ float g_bf[NL * C];
__device__ float g_u[HH * C];
__device__ float g_dproj[(MAXBIN + 1) * C];
__device__ float g_weff[C + 1];

// ---------------- fused small prep: u / dproj / bias / weff ----------------
__global__ void prep_small(const float* __restrict__ x, const float* __restrict__ w_in,
                           const float* __restrict__ dist, const float* __restrict__ b_in,
                           const float* __restrict__ b_dil, const float* __restrict__ gamma,
                           const float* __restrict__ beta, const float* __restrict__ mean,
                           const float* __restrict__ var,
                           const float* __restrict__ w_out, const float* __restrict__ b_out,
                           const float* __restrict__ w_head, const float* __restrict__ b_head) {
    int b = blockIdx.x;
    int c = threadIdx.x;
    if (b < HH) {
        const float* xr = x + b * E;
        const float* wr = w_in + c * E;
        float s = 0.f;
        #pragma unroll 8
        for (int e = 0; e < E; e++) s += wr[e] * xr[e];
        g_u[b * C + c] = s;
    } else if (b < HH + MAXBIN + 1) {
        int p = b - HH;
        const float* dr = dist + p * E;
        const float* wr = w_in + c * E;
        float s = b_in[c];
        #pragma unroll 8
        for (int e = 0; e < E; e++) s += wr[e] * dr[e];
        g_dproj[p * C + c] = s;
    } else if (b < HH + MAXBIN + 1 + NL) {
        int l = b - (HH + MAXBIN + 1);
        float s = gamma[l * C + c] * rsqrtf(var[l * C + c] + 1e-5f);
        g_bf[l * C + c] = (b_dil[l * C + c] - mean[l * C + c]) * s + beta[l * C + c];
    } else {
        float s = 0.f;
        for (int co = 0; co < C; co++) s += w_head[co] * w_out[co * C + c];
        g_weff[c] = s;
        if (c == 0) {
            float bb = b_head[0];
            for (int co = 0; co < C; co++) bb += w_head[co] * b_out[co];
            g_weff[C] = bb;
        }
    }
}

// coalesced wx prep (fuses x hi/lo split)
__global__ void prep_wx(const float* __restrict__ x, const float* __restrict__ w_in) {
    int i = blockIdx.x;
    int tid = threadIdx.x;
    int eg = tid >> 3;
    int c0 = (tid & 7) * 8;
    #pragma unroll
    for (int ee = 0; ee < 8; ee++) {
        int e = eg + ee * 32;
        float xie = x[i * E + e];
        if ((tid & 7) == 0) {
            unsigned short h = f2bfu(xie);
            g_xhi[i * E + e] = __ushort_as_bfloat16(h);
            g_xlo[i * E + e] = __float2bfloat16_rn(xie - bf2f(h));
        }
        size_t base = ((size_t)i * E + e) * C + c0;
        uint32_t hw[4], lw[4];
        #pragma unroll
        for (int k = 0; k < 4; k++) {
            float v0 = w_in[(c0 + 2 * k) * E + e] * xie;
            float v1 = w_in[(c0 + 2 * k + 1) * E + e] * xie;
            unsigned short h0 = f2bfu(v0), h1 = f2bfu(v1);
            unsigned short l0 = f2bfu(v0 - bf2f(h0)), l1 = f2bfu(v1 - bf2f(h1));
            hw[k] = (uint32_t)h0 | ((uint32_t)h1 << 16);
            lw[k] = (uint32_t)l0 | ((uint32_t)l1 << 16);
        }
        *(uint4*)(g_wxhi + base) = make_uint4(hw[0], hw[1], hw[2], hw[3]);
        *(uint4*)(g_wxlo + base) = make_uint4(lw[0], lw[1], lw[2], lw[3]);
    }
}

// smem-transposed fold
__global__ void prep_fold(const float* __restrict__ w_dil, const float* __restrict__ gamma,
                          const float* __restrict__ var) {
    __shared__ float tile[64 * 49];
    __shared__ float sscale[64];
    int l = blockIdx.x >> 6;
    int ci = blockIdx.x & 63;
    int tid = threadIdx.x;
    const float* wsrc = w_dil + l * C * C * 49;

    #pragma unroll 1
    for (int idx = tid; idx < 64 * 49; idx += 256) {
        int co = idx / 49;
        int tap = idx - co * 49;
        tile[idx] = wsrc[(co * C + ci) * 49 + tap];
    }
    if (tid < 64)
        sscale[tid] = gamma[l * C + tid] * rsqrtf(var[l * C + tid] + 1e-5f);
    __syncthreads();

    #pragma unroll 1
    for (int t = tid; t < 49 * 32; t += 256) {
        int tap = t >> 5;
        int co0 = (t & 31) * 2;
        float v0 = tile[co0 * 49 + tap] * sscale[co0];
        float v1 = tile[(co0 + 1) * 49 + tap] * sscale[co0 + 1];
        unsigned short h0 = f2bfu(v0), h1 = f2bfu(v1);
        unsigned short l0 = f2bfu(v0 - bf2f(h0)), l1 = f2bfu(v1 - bf2f(h1));
        size_t o = (size_t)(l * 49 + tap) * 4096 + ci * 64 + co0;
        *(uint32_t*)(g_whi + o) = (uint32_t)h0 | ((uint32_t)h1 << 16);
        *(uint32_t*)(g_wlo + o) = (uint32_t)l0 | ((uint32_t)l1 << 16);
    }
}

// ---------------- pair via mma.sync (symmetric: only j >= i tiles, mirror store) ----------------
#define OFF_PAH(b) ((b) * 49152)
#define OFF_PAL(b) ((b) * 49152 + 16384)
#define OFF_PBH(b) ((b) * 49152 + 32768)
#define OFF_PBL(b) ((b) * 49152 + 40960)
#define SMEM_PAIR 98304

__global__ __launch_bounds__(256, 2) void pair_mma() {
    const int i = blockIdx.y;
    const int j0 = blockIdx.x * 128;
    if (j0 + 127 < i) return;   // tile entirely below diagonal: mirrored by other CTAs

    extern __shared__ char smem[];
    const uint32_t sb = smem_to_u32(smem);
    const int tid = threadIdx.x;
    const int wid = tid >> 5, lane = tid & 31;

    int aRow[4], aCc[4]; uint32_t aOff[4];
    #pragma unroll
    for (int k = 0; k < 4; k++) {
        int chunk = tid + k * 256;
        aRow[k] = chunk >> 3;
        aCc[k] = chunk & 7;
        aOff[k] = (uint32_t)(aRow[k] * 128 + ((aCc[k] ^ (aRow[k] & 7)) << 4));
    }
    int bRow[2], bCc[2]; uint32_t bOff[2];
    #pragma unroll
    for (int k = 0; k < 2; k++) {
        int chunk = tid + k * 256;
        bRow[k] = chunk >> 3;
        bCc[k] = chunk & 7;
        bOff[k] = (uint32_t)(bRow[k] * 128 + ((bCc[k] ^ (bRow[k] & 7)) << 4));
    }

    const int row0 = wid * 16;
    const int quad = lane >> 3;
    const int rA = row0 + (lane & 7) + ((quad & 1) << 3);
    const int aChunkAdd = quad >> 1;
    const int rBbase = (lane & 7) + (((lane >> 3) & 1) << 3);
    const int bChunkAdd = lane >> 4;

    float acc[8][4] = {};

    {
        #pragma unroll
        for (int k = 0; k < 4; k++) {
            int j = j0 + aRow[k];
            bool ok = j < WW;
            size_t g = ok ? ((size_t)j * E + aCc[k] * 8) : 0;
            cp16(sb + OFF_PAH(0) + aOff[k], g_xhi + g, ok);
            cp16(sb + OFF_PAL(0) + aOff[k], g_xlo + g, ok);
        }
        size_t wb = ((size_t)i * E) * C;
        #pragma unroll
        for (int k = 0; k < 2; k++) {
            size_t g = wb + (size_t)bRow[k] * C + bCc[k] * 8;
            cp16(sb + OFF_PBH(0) + bOff[k], g_wxhi + g, true);
            cp16(sb + OFF_PBL(0) + bOff[k], g_wxlo + g, true);
        }
        CP_COMMIT();
        CP_WAIT0();
        __syncthreads();
    }

    #pragma unroll 1
    for (int ch = 0; ch < 4; ch++) {
        int buf = ch & 1;
        if (ch < 3) {
            int e0 = (ch + 1) * 64;
            int nb = buf ^ 1;
            #pragma unroll
            for (int k = 0; k < 4; k++) {
                int j = j0 + aRow[k];
                bool ok = j < WW;
                size_t g = ok ? ((size_t)j * E + e0 + aCc[k] * 8) : 0;
                cp16(sb + OFF_PAH(nb) + aOff[k], g_xhi + g, ok);
                cp16(sb + OFF_PAL(nb) + aOff[k], g_xlo + g, ok);
            }
            size_t wb = ((size_t)i * E + e0) * C;
            #pragma unroll
            for (int k = 0; k < 2; k++) {
                size_t g = wb + (size_t)bRow[k] * C + bCc[k] * 8;
                cp16(sb + OFF_PBH(nb) + bOff[k], g_wxhi + g, true);
                cp16(sb + OFF_PBL(nb) + bOff[k], g_wxlo + g, true);
            }
            CP_COMMIT();
        }

        const uint32_t pah = sb + OFF_PAH(buf);
        const uint32_t pal = sb + OFF_PAL(buf);
        const uint32_t pbh = sb + OFF_PBH(buf);
        const uint32_t pbl = sb + OFF_PBL(buf);
        #pragma unroll
        for (int ks = 0; ks < 4; ks++) {
            uint32_t ah[4], al[4];
            {
                int chunk = 2 * ks + aChunkAdd;
                uint32_t ao = (uint32_t)(rA * 128 + ((chunk ^ (rA & 7)) << 4));
                LDSM_X4(ah[0], ah[1], ah[2], ah[3], pah + ao);
                LDSM_X4(al[0], al[1], al[2], al[3], pal + ao);
            }
            int rB = rBbase + 16 * ks;
            #pragma unroll
            for (int p = 0; p < 4; p++) {
                int chunkB = 2 * p + bChunkAdd;
                uint32_t bo = (uint32_t)(rB * 128 + ((chunkB ^ (rB & 7)) << 4));
                uint32_t b0, b1, b2, b3;
                LDSM_X4_T(b0, b1, b2, b3, pbh + bo);
                mma16816(acc[2 * p],     ah, b0, b1);
                mma16816(acc[2 * p + 1], ah, b2, b3);
                mma16816(acc[2 * p],     al, b0, b1);
                mma16816(acc[2 * p + 1], al, b2, b3);
                LDSM_X4_T(b0, b1, b2, b3, pbl + bo);
                mma16816(acc[2 * p],     ah, b0, b1);
                mma16816(acc[2 * p + 1], ah, b2, b3);
            }
        }
        if (ch < 3) {
            CP_WAIT0();
            __syncthreads();
        }
    }

    int rtop = row0 + (lane >> 2);
    int cpair = (lane & 3) * 2;
    #pragma unroll
    for (int half = 0; half < 2; half++) {
        int j = j0 + rtop + half * 8;
        if (j < WW && j >= i) {
            int pos = j - i;
            if (pos > MAXBIN) pos = MAXBIN;
            size_t prow = ((size_t)i * WW + j) * C;
            size_t mrow = ((size_t)j * WW + i) * C;
            bool mirror = (j > i);
            #pragma unroll
            for (int nt = 0; nt < 8; nt++) {
                int col = nt * 8 + cpair;
                float v0 = acc[nt][half * 2]     + 0.5f * (g_u[i * C + col]     + g_u[j * C + col])     + g_dproj[pos * C + col];
                float v1 = acc[nt][half * 2 + 1] + 0.5f * (g_u[i * C + col + 1] + g_u[j * C + col + 1]) + g_dproj[pos * C + col + 1];
                unsigned short h0 = f2bfu(v0), h1 = f2bfu(v1);
                unsigned short l0 = f2bfu(v0 - bf2f(h0)), l1 = f2bfu(v1 - bf2f(h1));
                uint32_t hp = (uint32_t)h0 | ((uint32_t)h1 << 16);
                uint32_t lp = (uint32_t)l0 | ((uint32_t)l1 << 16);
                *(uint32_t*)(g_Ahi + prow + col) = hp;
                *(uint32_t*)(g_Alo + prow + col) = lp;
                if (mirror) {
                    *(uint32_t*)(g_Ahi + mrow + col) = hp;
                    *(uint32_t*)(g_Alo + mrow + col) = lp;
                }
            }
        }
    }
}

// ---------------- dilated conv (small dil): y-pair strip, DB W ----------------
#define OFF_BIAS 0
#define OFF_WB(b)  (256 + (b) * 16384)
#define OFF_S2     (256 + 32768)

template<int DIL>
__global__ __launch_bounds__(256, 2) void conv_strip2(int l) {
    constexpr int NR = ((128 + 6 * DIL) + 31) & ~31;

    extern __shared__ char smem[];
    const uint32_t sb = smem_to_u32(smem);
    const int tid = threadIdx.x;
    const int wid = tid >> 5, lane = tid & 31;
    const int y0 = blockIdx.y * 2;
    const int x0 = blockIdx.x * 128;

    const __nv_bfloat16* __restrict__ shi = (l & 1) ? g_Bhi : g_Ahi;
    const __nv_bfloat16* __restrict__ slo = (l & 1) ? g_Blo : g_Alo;
    __nv_bfloat16* __restrict__ dhi = (l & 1) ? g_Ahi : g_Bhi;
    __nv_bfloat16* __restrict__ dlo = (l & 1) ? g_Alo : g_Blo;
    const __nv_bfloat16* __restrict__ wh = g_whi + l * 49 * 4096;
    const __nv_bfloat16* __restrict__ wl = g_wlo + l * 49 * 4096;

    if (tid < C) ((float*)(smem + OFF_BIAS))[tid] = g_bf[l * C + tid];

    int wCi[2]; uint32_t wSo[2], wGo[2];
    #pragma unroll
    for (int k = 0; k < 2; k++) {
        int chunk = tid + k * 256;
        wCi[k] = chunk >> 3;
        int cc = chunk & 7;
        wGo[k] = (uint32_t)(wCi[k] * 64 + cc * 8);
        wSo[k] = (uint32_t)(wCi[k] * 128 + ((cc ^ (wCi[k] & 7)) << 4));
    }

    const int row0 = wid * 16;
    const int quad = lane >> 3;
    const int rA = row0 + (lane & 7) + ((quad & 1) << 3);
    const int aChunkAdd = quad >> 1;
    const int rBbase = (lane & 7) + (((lane >> 3) & 1) << 3);
    const int bChunkAdd = lane >> 4;

    float acc[2][8][4] = {};

    #pragma unroll 1
    for (int ky = 0; ky < 7; ky++) {
        #pragma unroll
        for (int s = 0; s < 2; s++) {
            int yy = y0 + s + (ky - 3) * DIL;
            bool yok = (yy >= 0) && (yy < HH);
            size_t rowbase = (size_t)yy * WW;
            uint32_t sbase = sb + OFF_S2 + s * (NR * 256);
            #pragma unroll 1
            for (int chunk = tid; chunk < NR * 8; chunk += 256) {
                int r = chunk >> 3;
                int cc = chunk & 7;
                int xg = x0 - 3 * DIL + r;
                bool ok = yok && (xg >= 0) && (xg < WW);
                size_t g = ok ? ((rowbase + xg) * C + cc * 8) : 0;
                uint32_t so = (uint32_t)(r * 128 + ((cc ^ (r & 7)) << 4));
                cp16(sbase + so, shi + g, ok);
                cp16(sbase + NR * 128 + so, slo + g, ok);
            }
        }
        {
            const __nv_bfloat16* wph = wh + (ky * 7) * 4096;
            const __nv_bfloat16* wpl = wl + (ky * 7) * 4096;
            #pragma unroll
            for (int k = 0; k < 2; k++) {
                cp16(sb + OFF_WB(0) + wSo[k],        wph + wGo[k], true);
                cp16(sb + OFF_WB(0) + 8192 + wSo[k], wpl + wGo[k], true);
            }
        }
        CP_COMMIT();
        CP_WAIT0();
        __syncthreads();

        #pragma unroll 1
        for (int kx = 0; kx < 7; kx++) {
            int buf = kx & 1;
            if (kx < 6) {
                const __nv_bfloat16* wph = wh + (ky * 7 + kx + 1) * 4096;
                const __nv_bfloat16* wpl = wl + (ky * 7 + kx + 1) * 4096;
                int nb = (kx + 1) & 1;
                #pragma unroll
                for (int k = 0; k < 2; k++) {
                    cp16(sb + OFF_WB(nb) + wSo[k],        wph + wGo[k], true);
                    cp16(sb + OFF_WB(nb) + 8192 + wSo[k], wpl + wGo[k], true);
                }
                CP_COMMIT();
            }
            const uint32_t wbh = sb + OFF_WB(buf);
            const uint32_t wbl = wbh + 8192;
            const int rowL = kx * DIL + rA;
            const uint32_t aoBase = (uint32_t)(rowL * 128);
            const int rpar = rowL & 7;
            const uint32_t s0h = sb + OFF_S2;
            const uint32_t s0l = s0h + NR * 128;
            const uint32_t s1h = s0h + NR * 256;
            const uint32_t s1l = s1h + NR * 128;

            #pragma unroll
            for (int ks = 0; ks < 4; ks++) {
                uint32_t ah0[4], al0[4], ah1[4], al1[4];
                {
                    int chunk = 2 * ks + aChunkAdd;
                    uint32_t ao = aoBase + ((uint32_t)(chunk ^ rpar) << 4);
                    LDSM_X4(ah0[0], ah0[1], ah0[2], ah0[3], s0h + ao);
                    LDSM_X4(al0[0], al0[1], al0[2], al0[3], s0l + ao);
                    LDSM_X4(ah1[0], ah1[1], ah1[2], ah1[3], s1h + ao);
                    LDSM_X4(al1[0], al1[1], al1[2], al1[3], s1l + ao);
                }
                int rB = rBbase + 16 * ks;
                #pragma unroll
                for (int p = 0; p < 4; p++) {
                    int chunkB = 2 * p + bChunkAdd;
                    uint32_t bo = (uint32_t)(rB * 128 + ((chunkB ^ (rB & 7)) << 4));
                    uint32_t b0, b1, b2, b3;
                    LDSM_X4_T(b0, b1, b2, b3, wbh + bo);
                    mma16816(acc[0][2 * p],     ah0, b0, b1);
                    mma16816(acc[0][2 * p + 1], ah0, b2, b3);
                    mma16816(acc[1][2 * p],     ah1, b0, b1);
                    mma16816(acc[1][2 * p + 1], ah1, b2, b3);
                    mma16816(acc[0][2 * p],     al0, b0, b1);
                    mma16816(acc[0][2 * p + 1], al0, b2, b3);
                    mma16816(acc[1][2 * p],     al1, b0, b1);
                    mma16816(acc[1][2 * p + 1], al1, b2, b3);
                    LDSM_X4_T(b0, b1, b2, b3, wbl + bo);
                    mma16816(acc[0][2 * p],     ah0, b0, b1);
                    mma16816(acc[0][2 * p + 1], ah0, b2, b3);
                    mma16816(acc[1][2 * p],     ah1, b0, b1);
                    mma16816(acc[1][2 * p + 1], ah1, b2, b3);
                }
            }
            if (kx < 6) {
                CP_WAIT0();
                __syncthreads();
            }
        }
        __syncthreads();
    }

    const float* sbias = (const float*)(smem + OFF_BIAS);
    int rtop = row0 + (lane >> 2);
    int cpair = (lane & 3) * 2;
    #pragma unroll
    for (int s = 0; s < 2; s++) {
        int y = y0 + s;
        #pragma unroll
        for (int half = 0; half < 2; half++) {
            int xg = x0 + rtop + half * 8;
            if (xg < WW) {
                size_t prow = ((size_t)y * WW + xg) * C;
                #pragma unroll
                for (int nt = 0; nt < 8; nt++) {
                    int col = nt * 8 + cpair;
                    size_t p = prow + col;
                    uint32_t rh = *(const uint32_t*)(shi + p);
                    uint32_t rl = *(const uint32_t*)(slo + p);
                    float v0 = acc[s][nt][half * 2]     + sbias[col]     + bf2f(rh & 0xffffu) + bf2f(rl & 0xffffu);
                    float v1 = acc[s][nt][half * 2 + 1] + sbias[col + 1] + bf2f(rh >> 16)     + bf2f(rl >> 16);
                    v0 = fmaxf(v0, 0.f); v1 = fmaxf(v1, 0.f);
                    unsigned short h0 = f2bfu(v0), h1 = f2bfu(v1);
                    unsigned short l0 = f2bfu(v0 - bf2f(h0)), l1 = f2bfu(v1 - bf2f(h1));
                    *(uint32_t*)(dhi + p) = (uint32_t)h0 | ((uint32_t)h1 << 16);
                    *(uint32_t*)(dlo + p) = (uint32_t)l0 | ((uint32_t)l1 << 16);
                }
            }
        }
    }
}

// ---------------- dilated conv (mid dil incl. 32): single-row strip, DB W ----------------
#define OFF_STRIP  (256 + 32768)

template<int DIL>
__global__ __launch_bounds__(256, 2) void conv_strip(int l) {
    constexpr int NR = ((128 + 6 * DIL) + 31) & ~31;
    constexpr int OFF_SH = OFF_STRIP;
    constexpr int OFF_SL = OFF_STRIP + NR * 128;

    extern __shared__ char smem[];
    const uint32_t sb = smem_to_u32(smem);
    const int tid = threadIdx.x;
    const int wid = tid >> 5, lane = tid & 31;
    const int y = blockIdx.y;
    const int x0 = blockIdx.x * 128;

    const __nv_bfloat16* __restrict__ shi = (l & 1) ? g_Bhi : g_Ahi;
    const __nv_bfloat16* __restrict__ slo = (l & 1) ? g_Blo : g_Alo;
    __nv_bfloat16* __restrict__ dhi = (l & 1) ? g_Ahi : g_Bhi;
    __nv_bfloat16* __restrict__ dlo = (l & 1) ? g_Alo : g_Blo;
    const __nv_bfloat16* __restrict__ wh = g_whi + l * 49 * 4096;
    const __nv_bfloat16* __restrict__ wl = g_wlo + l * 49 * 4096;

    if (tid < C) ((float*)(smem + OFF_BIAS))[tid] = g_bf[l * C + tid];

    int wCi[2]; uint32_t wSo[2], wGo[2];
    #pragma unroll
    for (int k = 0; k < 2; k++) {
        int chunk = tid + k * 256;
        wCi[k] = chunk >> 3;
        int cc = chunk & 7;
        wGo[k] = (uint32_t)(wCi[k] * 64 + cc * 8);
        wSo[k] = (uint32_t)(wCi[k] * 128 + ((cc ^ (wCi[k] & 7)) << 4));
    }

    const int row0 = wid * 16;
    const int quad = lane >> 3;
    const int rA = row0 + (lane & 7) + ((quad & 1) << 3);
    const int aChunkAdd = quad >> 1;
    const int rBbase = (lane & 7) + (((lane >> 3) & 1) << 3);
    const int bChunkAdd = lane >> 4;

    float acc[8][4] = {};

    #pragma unroll 1
    for (int ky = 0; ky < 7; ky++) {
        int yy = y + (ky - 3) * DIL;
        bool yok = (yy >= 0) && (yy < HH);
        size_t rowbase = (size_t)yy * WW;

        #pragma unroll 1
        for (int chunk = tid; chunk < NR * 8; chunk += 256) {
            int r = chunk >> 3;
            int cc = chunk & 7;
            int xg = x0 - 3 * DIL + r;
            bool ok = yok && (xg >= 0) && (xg < WW);
            size_t g = ok ? ((rowbase + xg) * C + cc * 8) : 0;
            uint32_t so = (uint32_t)(r * 128 + ((cc ^ (r & 7)) << 4));
            cp16(sb + OFF_SH + so, shi + g, ok);
            cp16(sb + OFF_SL + so, slo + g, ok);
        }
        {
            const __nv_bfloat16* wph = wh + (ky * 7) * 4096;
            const __nv_bfloat16* wpl = wl + (ky * 7) * 4096;
            #pragma unroll
            for (int k = 0; k < 2; k++) {
                cp16(sb + OFF_WB(0) + wSo[k],        wph + wGo[k], true);
                cp16(sb + OFF_WB(0) + 8192 + wSo[k], wpl + wGo[k], true);
            }
        }
        CP_COMMIT();
        CP_WAIT0();
        __syncthreads();

        #pragma unroll 1
        for (int kx = 0; kx < 7; kx++) {
            int buf = kx & 1;
            if (kx < 6) {
                const __nv_bfloat16* wph = wh + (ky * 7 + kx + 1) * 4096;
                const __nv_bfloat16* wpl = wl + (ky * 7 + kx + 1) * 4096;
                int nb = (kx + 1) & 1;
                #pragma unroll
                for (int k = 0; k < 2; k++) {
                    cp16(sb + OFF_WB(nb) + wSo[k],        wph + wGo[k], true);
                    cp16(sb + OFF_WB(nb) + 8192 + wSo[k], wpl + wGo[k], true);
                }
                CP_COMMIT();
            }
            const uint32_t wbh = sb + OFF_WB(buf);
            const uint32_t wbl = wbh + 8192;
            const int rowL = kx * DIL + rA;
            const uint32_t aoBase = (uint32_t)(rowL * 128);
            const int rpar = rowL & 7;

            #pragma unroll
            for (int ks = 0; ks < 4; ks++) {
                uint32_t ah[4], al[4];
                {
                    int chunk = 2 * ks + aChunkAdd;
                    uint32_t ao = aoBase + ((uint32_t)(chunk ^ rpar) << 4);
                    LDSM_X4(ah[0], ah[1], ah[2], ah[3], sb + OFF_SH + ao);
                    LDSM_X4(al[0], al[1], al[2], al[3], sb + OFF_SL + ao);
                }
                int rB = rBbase + 16 * ks;
                #pragma unroll
                for (int p = 0; p < 4; p++) {
                    int chunkB = 2 * p + bChunkAdd;
                    uint32_t bo = (uint32_t)(rB * 128 + ((chunkB ^ (rB & 7)) << 4));
                    uint32_t b0, b1, b2, b3;
                    LDSM_X4_T(b0, b1, b2, b3, wbh + bo);
                    mma16816(acc[2 * p],     ah, b0, b1);
                    mma16816(acc[2 * p + 1], ah, b2, b3);
                    mma16816(acc[2 * p],     al, b0, b1);
                    mma16816(acc[2 * p + 1], al, b2, b3);
                    LDSM_X4_T(b0, b1, b2, b3, wbl + bo);
                    mma16816(acc[2 * p],     ah, b0, b1);
                    mma16816(acc[2 * p + 1], ah, b2, b3);
                }
            }
            if (kx < 6) {
                CP_WAIT0();
                __syncthreads();
            }
        }
        __syncthreads();
    }

    const float* sbias = (const float*)(smem + OFF_BIAS);
    int rtop = row0 + (lane >> 2);
    int cpair = (lane & 3) * 2;
    #pragma unroll
    for (int half = 0; half < 2; half++) {
        int xg = x0 + rtop + half * 8;
        if (xg < WW) {
            size_t prow = ((size_t)y * WW + xg) * C;
            #pragma unroll
            for (int nt = 0; nt < 8; nt++) {
                int col = nt * 8 + cpair;
                size_t p = prow + col;
                uint32_t rh = *(const uint32_t*)(shi + p);
                uint32_t rl = *(const uint32_t*)(slo + p);
                float v0 = acc[nt][half * 2]     + sbias[col]     + bf2f(rh & 0xffffu) + bf2f(rl & 0xffffu);
                float v1 = acc[nt][half * 2 + 1] + sbias[col + 1] + bf2f(rh >> 16)     + bf2f(rl >> 16);
                v0 = fmaxf(v0, 0.f); v1 = fmaxf(v1, 0.f);
                unsigned short h0 = f2bfu(v0), h1 = f2bfu(v1);
                unsigned short l0 = f2bfu(v0 - bf2f(h0)), l1 = f2bfu(v1 - bf2f(h1));
                *(uint32_t*)(dhi + p) = (uint32_t)h0 | ((uint32_t)h1 << 16);
                *(uint32_t*)(dlo + p) = (uint32_t)l0 | ((uint32_t)l1 << 16);
            }
        }
    }
}

// ---------------- dilated conv (dil 64): per-tap double-buffered A+W ----------------
#define OT_BUF(b)  (256 + (b) * 49152)
#define SMEM_TAP   98560

template<int DIL>
__global__ __launch_bounds__(256, 2) void conv_tap(int l) {
    extern __shared__ char smem[];
    const uint32_t sb = smem_to_u32(smem);
    const int tid = threadIdx.x;
    const int wid = tid >> 5, lane = tid & 31;
    const int y = blockIdx.y;
    const int x0 = blockIdx.x * 128;

    const __nv_bfloat16* __restrict__ shi = (l & 1) ? g_Bhi : g_Ahi;
    const __nv_bfloat16* __restrict__ slo = (l & 1) ? g_Blo : g_Alo;
    __nv_bfloat16* __restrict__ dhi = (l & 1) ? g_Ahi : g_Bhi;
    __nv_bfloat16* __restrict__ dlo = (l & 1) ? g_Alo : g_Blo;
    const __nv_bfloat16* __restrict__ wh = g_whi + l * 49 * 4096;
    const __nv_bfloat16* __restrict__ wl = g_wlo + l * 49 * 4096;

    if (tid < C) ((float*)(smem))[tid] = g_bf[l * C + tid];

    int aRow[4], aCc[4]; uint32_t aOff[4];
    #pragma unroll
    for (int k = 0; k < 4; k++) {
        int chunk = tid + k * 256;
        aRow[k] = chunk >> 3;
        aCc[k] = chunk & 7;
        aOff[k] = (uint32_t)(aRow[k] * 128 + ((aCc[k] ^ (aRow[k] & 7)) << 4));
    }
    int wCi[2]; uint32_t wSo[2], wGo[2];
    #pragma unroll
    for (int k = 0; k < 2; k++) {
        int chunk = tid + k * 256;
        wCi[k] = chunk >> 3;
        int cc = chunk & 7;
        wGo[k] = (uint32_t)(wCi[k] * 64 + cc * 8);
        wSo[k] = (uint32_t)(wCi[k] * 128 + ((cc ^ (wCi[k] & 7)) << 4));
    }

    const int row0 = wid * 16;
    const int quad = lane >> 3;
    const int rA = row0 + (lane & 7) + ((quad & 1) << 3);
    const int aChunkAdd = quad >> 1;
    const int rBbase = (lane & 7) + (((lane >> 3) & 1) << 3);
    const int bChunkAdd = lane >> 4;
    const int rpar = rA & 7;
    const uint32_t aoBase = (uint32_t)(rA * 128);

    #define STAGE_TAP(TAP, BUF) do { \
        int _t = (TAP); \
        int _ky = _t / 7, _kx = _t - _ky * 7; \
        int _yy = y + (_ky - 3) * DIL; \
        bool _yok = (_yy >= 0) && (_yy < HH); \
        size_t _rb = (size_t)_yy * WW; \
        int _xs = x0 + (_kx - 3) * DIL; \
        uint32_t _ba = sb + OT_BUF(BUF); \
        _Pragma("unroll") \
        for (int _k = 0; _k < 4; _k++) { \
            int _xg = _xs + aRow[_k]; \
            bool _ok = _yok && (_xg >= 0) && (_xg < WW); \
            size_t _g = _ok ? ((_rb + _xg) * C + aCc[_k] * 8) : 0; \
            cp16(_ba + aOff[_k],         shi + _g, _ok); \
            cp16(_ba + 16384 + aOff[_k], slo + _g, _ok); \
        } \
        const __nv_bfloat16* _wph = wh + _t * 4096; \
        const __nv_bfloat16* _wpl = wl + _t * 4096; \
        _Pragma("unroll") \
        for (int _k = 0; _k < 2; _k++) { \
            cp16(_ba + 32768 + wSo[_k], _wph + wGo[_k], true); \
            cp16(_ba + 40960 + wSo[_k], _wpl + wGo[_k], true); \
        } \
    } while (0)

    float acc[8][4] = {};

    STAGE_TAP(0, 0);
    CP_COMMIT();
    CP_WAIT0();
    __syncthreads();

    #pragma unroll 1
    for (int tap = 0; tap < 49; ++tap) {
        int buf = tap & 1;
        if (tap < 48) {
            STAGE_TAP(tap + 1, buf ^ 1);
            CP_COMMIT();
        }
        const uint32_t pah = sb + OT_BUF(buf);
        const uint32_t pal = pah + 16384;
        const uint32_t wbh = pah + 32768;
        const uint32_t wbl = pah + 40960;

        #pragma unroll
        for (int ks = 0; ks < 4; ks++) {
            uint32_t ah[4], al[4];
            {
                int chunk = 2 * ks + aChunkAdd;
                uint32_t ao = aoBase + ((uint32_t)(chunk ^ rpar) << 4);
                LDSM_X4(ah[0], ah[1], ah[2], ah[3], pah + ao);
                LDSM_X4(al[0], al[1], al[2], al[3], pal + ao);
            }
            int rB = rBbase + 16 * ks;
            #pragma unroll
            for (int p = 0; p < 4; p++) {
                int chunkB = 2 * p + bChunkAdd;
                uint32_t bo = (uint32_t)(rB * 128 + ((chunkB ^ (rB & 7)) << 4));
                uint32_t b0, b1, b2, b3;
                LDSM_X4_T(b0, b1, b2, b3, wbh + bo);
                mma16816(acc[2 * p],     ah, b0, b1);
                mma16816(acc[2 * p + 1], ah, b2, b3);
                mma16816(acc[2 * p],     al, b0, b1);
                mma16816(acc[2 * p + 1], al, b2, b3);
                LDSM_X4_T(b0, b1, b2, b3, wbl + bo);
                mma16816(acc[2 * p],     ah, b0, b1);
                mma16816(acc[2 * p + 1], ah, b2, b3);
            }
        }
        if (tap < 48) {
            CP_WAIT0();
            __syncthreads();
        }
    }
    #undef STAGE_TAP

    const float* sbias = (const float*)(smem);
    int rtop = row0 + (lane >> 2);
    int cpair = (lane & 3) * 2;
    #pragma unroll
    for (int half = 0; half < 2; half++) {
        int xg = x0 + rtop + half * 8;
        if (xg < WW) {
            size_t prow = ((size_t)y * WW + xg) * C;
            #pragma unroll
            for (int nt = 0; nt < 8; nt++) {
                int col = nt * 8 + cpair;
                size_t p = prow + col;
                uint32_t rh = *(const uint32_t*)(shi + p);
                uint32_t rl = *(const uint32_t*)(slo + p);
                float v0 = acc[nt][half * 2]     + sbias[col]     + bf2f(rh & 0xffffu) + bf2f(rl & 0xffffu);
                float v1 = acc[nt][half * 2 + 1] + sbias[col + 1] + bf2f(rh >> 16)     + bf2f(rl >> 16);
                v0 = fmaxf(v0, 0.f); v1 = fmaxf(v1, 0.f);
                unsigned short h0 = f2bfu(v0), h1 = f2bfu(v1);
                unsigned short l0 = f2bfu(v0 - bf2f(h0)), l1 = f2bfu(v1 - bf2f(h1));
                *(uint32_t*)(dhi + p) = (uint32_t)h0 | ((uint32_t)h1 << 16);
                *(uint32_t*)(dlo + p) = (uint32_t)l0 | ((uint32_t)l1 << 16);
            }
        }
    }
}

// ---------------- head ----------------
__device__ __forceinline__ int tri_offs(int r) { return r * NOUT - (r * (r - 1)) / 2; }

__global__ void head_k(float* __restrict__ out) {
    int k = blockIdx.x * blockDim.x + threadIdx.x;
    if (k >= NTRI) return;
    float disc = (2.f * NOUT + 1.f) * (2.f * NOUT + 1.f) - 8.f * (float)k;
    int r = (int)(((2.f * NOUT + 1.f) - sqrtf(disc)) * 0.5f);
    if (r < 0) r = 0;
    if (r > NOUT - 1) r = NOUT - 1;
    while (r > 0 && tri_offs(r) > k) r--;
    while (r < NOUT - 1 && tri_offs(r + 1) <= k) r++;
    int c = r + (k - tri_offs(r));
    int yy = CROPV + r, xx = CROPV + c;
    size_t p = ((size_t)yy * WW + xx) * C;

    float s = g_weff[C];
    const uint4* rh = (const uint4*)(g_Bhi + p);
    const uint4* rl = (const uint4*)(g_Blo + p);
    #pragma unroll
    for (int q = 0; q < 8; q++) {
        uint4 vh = rh[q], vl = rl[q];
        uint32_t vhw[4] = {vh.x, vh.y, vh.z, vh.w};
        uint32_t vlw[4] = {vl.x, vl.y, vl.z, vl.w};
        #pragma unroll
        for (int e = 0; e < 4; e++) {
            int ci = q * 8 + e * 2;
            float h0 = bf2f(vhw[e] & 0xffffu) + bf2f(vlw[e] & 0xffffu);
            float h1 = bf2f(vhw[e] >> 16) + bf2f(vlw[e] >> 16);
            s = fmaf(h0, __ldg(&g_weff[ci]), s);
            s = fmaf(h1, __ldg(&g_weff[ci + 1]), s);
        }
    }
    out[k] = s;
}

// ------------------------------------------------------------------
template<int DIL>
static void launch_conv2(int l) {
    constexpr int NR = ((128 + 6 * DIL) + 31) & ~31;
    constexpr int SMEM = 256 + 32768 + 2 * NR * 256;
    static bool done = false;
    if (!done) {
        cudaFuncSetAttribute(conv_strip2<DIL>, cudaFuncAttributeMaxDynamicSharedMemorySize, SMEM);
        done = true;
    }
    conv_strip2<DIL><<<dim3((WW + 127) / 128, HH / 2), 256, SMEM>>>(l);
}

template<int DIL>
static void launch_conv(int l) {
    constexpr int NR = ((128 + 6 * DIL) + 31) & ~31;
    constexpr int SMEM = 256 + 32768 + NR * 256;
    static bool done = false;
    if (!done) {
        cudaFuncSetAttribute(conv_strip<DIL>, cudaFuncAttributeMaxDynamicSharedMemorySize, SMEM);
        done = true;
    }
    conv_strip<DIL><<<dim3((WW + 127) / 128, HH), 256, SMEM>>>(l);
}

template<int DIL>
static void launch_tap(int l) {
    static bool done = false;
    if (!done) {
        cudaFuncSetAttribute(conv_tap<DIL>, cudaFuncAttributeMaxDynamicSharedMemorySize, SMEM_TAP);
        done = true;
    }
    conv_tap<DIL><<<dim3((WW + 127) / 128, HH), 256, SMEM_TAP>>>(l);
}

extern "C" void kernel_launch(void* const* d_in, const int* in_sizes, int n_in,
                              void* d_out, int out_size) {
    const float* x      = (const float*)d_in[0];
    const float* dist   = (const float*)d_in[1];
    const float* w_in   = (const float*)d_in[2];
    const float* b_in   = (const float*)d_in[3];
    const float* w_dil  = (const float*)d_in[4];
    const float* b_dil  = (const float*)d_in[5];
    const float* gamma  = (const float*)d_in[6];
    const float* beta   = (const float*)d_in[7];
    const float* mean   = (const float*)d_in[8];
    const float* var    = (const float*)d_in[9];
    const float* w_out  = (const float*)d_in[10];
    const float* b_out  = (const float*)d_in[11];
    const float* w_head = (const float*)d_in[12];
    const float* b_head = (const float*)d_in[13];
    float* out = (float*)d_out;

    cudaFuncSetAttribute(pair_mma, cudaFuncAttributeMaxDynamicSharedMemorySize, SMEM_PAIR);

    prep_small<<<HH + MAXBIN + 1 + NL + 1, C>>>(x, w_in, dist, b_in, b_dil, gamma, beta,
                                                mean, var, w_out, b_out, w_head, b_head);
    prep_wx<<<HH, 256>>>(x, w_in);
    prep_fold<<<NL * 64, 256>>>(w_dil, gamma, var);

    pair_mma<<<dim3((WW + 127) / 128, HH), 256, SMEM_PAIR>>>();

    launch_conv2<1>(0);
    launch_conv2<2>(1);
    launch_conv2<4>(2);
    launch_conv<8>(3);
    launch_conv<16>(4);
    launch_conv<32>(5);
    launch_tap<64>(6);

    head_k<<<(NTRI + 255) / 256, 256>>>(out);
}